// round 1
// baseline (speedup 1.0000x reference)
#include <cuda_runtime.h>
#include <math.h>

#define Bb 32
#define Ss 512
#define NNODE 6
#define CIN 12
#define H1C 128
#define HHC 256
#define TCC 1536
#define LLEN 512
#define M1R (Bb*Ss*NNODE)   /* 98304 */
#define NBS (Bb*Ss)         /* 16384 */
#define RKK (5*TCC)         /* 7680  */
#define BNEPS 1e-5f

// ---------------- scratch (device globals; no runtime allocation) ----------
__device__ float g_xc1 [M1R*H1C];
__device__ float g_res1[M1R*H1C];
__device__ float g_h1  [M1R*H1C];
__device__ float g_y2  [M1R*HHC];
__device__ float g_res2[M1R*HHC];
__device__ float g_xc2 [M1R*HHC];
__device__ float g_ht  [Bb*TCC*LLEN];
__device__ float g_t1  [Bb*TCC*LLEN];
__device__ float g_t2  [Bb*TCC*LLEN];
__device__ float g_wt1 [RKK*TCC];
__device__ float g_wt2 [RKK*TCC];
__device__ float g_w2T [H1C*HHC];
__device__ float g_rw2T[H1C*HHC];
__device__ float g_owT [TCC*HHC];
__device__ float g_stats[4*TCC];

// ---------------- small utility kernels ------------------------------------
__global__ void zero_stats_k() {
    int i = blockIdx.x * blockDim.x + threadIdx.x;
    if (i < 4*TCC) g_stats[i] = 0.f;
}

// out[c*R + r] = in[r*C + c]
__global__ void transpose_small(const float* __restrict__ in, float* __restrict__ out,
                                int R, int C) {
    int idx = blockIdx.x * blockDim.x + threadIdx.x;
    if (idx >= R * C) return;
    int r = idx / C, c = idx % C;
    out[(size_t)c * R + r] = in[idx];
}

// wt[(k*TC+ci)*TC + co] = cw[(co*TC+ci)*5 + k]
__global__ void wtrans_conv(const float* __restrict__ cw, float* __restrict__ wt) {
    int idx = blockIdx.x * blockDim.x + threadIdx.x;
    if (idx >= TCC * TCC) return;
    int ci = idx / TCC;
    int co = idx % TCC;
    const float* src = cw + ((size_t)co * TCC + ci) * 5;
#pragma unroll
    for (int k = 0; k < 5; k++)
        wt[((size_t)k * TCC + ci) * TCC + co] = src[k];
}

// ---------------- GCN stage 1 (K=12, fused linear + node mix) --------------
__global__ void gcn1_kernel(const float* __restrict__ x, const float* __restrict__ adj,
                            const float* __restrict__ eimp,
                            const float* __restrict__ w1, const float* __restrict__ b1,
                            const float* __restrict__ rw1, const float* __restrict__ rb1) {
    __shared__ float xs[NNODE*CIN];
    __shared__ float Asm[NNODE*NNODE];
    __shared__ float xts[NNODE*H1C];
    int bs = blockIdx.x;
    int tid = threadIdx.x;
    if (tid < NNODE*CIN) xs[tid] = x[(size_t)bs*NNODE*CIN + tid];
    if (tid >= 128 && tid < 128 + NNODE*NNODE) Asm[tid-128] = adj[tid-128] * eimp[tid-128];
    __syncthreads();
    for (int e = tid; e < NNODE*H1C; e += blockDim.x) {
        int n = e / H1C, c = e % H1C;
        float ws = b1[c], rs = rb1[c];
#pragma unroll
        for (int i = 0; i < CIN; i++) {
            float xv = xs[n*CIN + i];
            ws += xv * w1[c*CIN + i];
            rs += xv * rw1[c*CIN + i];
        }
        xts[e] = ws;
        g_res1[(size_t)bs*(NNODE*H1C) + e] = rs;
    }
    __syncthreads();
    for (int e = tid; e < NNODE*H1C; e += blockDim.x) {
        int n = e / H1C, c = e % H1C;
        float acc = 0.f;
#pragma unroll
        for (int m = 0; m < NNODE; m++) acc += Asm[n*NNODE + m] * xts[m*H1C + c];
        g_xc1[(size_t)bs*(NNODE*H1C) + e] = acc;
    }
}

// per-channel sum/sumsq over rows for two row-major [M,C] tensors
__global__ void stats_rows(const float* __restrict__ a, const float* __restrict__ b,
                           int Mrows, int C) {
    int c = threadIdx.x;          // blockDim == C
    int rows_per = Mrows / gridDim.x;
    int r0 = blockIdx.x * rows_per;
    int r1 = r0 + rows_per;
    float sa = 0.f, qa = 0.f, sb = 0.f, qb = 0.f;
    for (int r = r0; r < r1; r++) {
        float v = a[(size_t)r*C + c]; sa += v; qa += v*v;
        float u = b[(size_t)r*C + c]; sb += u; qb += u*u;
    }
    atomicAdd(&g_stats[c],       sa);
    atomicAdd(&g_stats[C + c],   qa);
    atomicAdd(&g_stats[2*C + c], sb);
    atomicAdd(&g_stats[3*C + c], qb);
}

__global__ void bn_apply1(const float* __restrict__ g1, const float* __restrict__ beta1,
                          const float* __restrict__ rg1, const float* __restrict__ rbeta1) {
    size_t idx = (size_t)blockIdx.x * blockDim.x + threadIdx.x;
    if (idx >= (size_t)M1R*H1C) return;
    int c = (int)(idx % H1C);
    const float invM = 1.f / (float)M1R;
    float m1 = g_stats[c] * invM;
    float v1 = g_stats[H1C + c] * invM - m1*m1;
    float m2 = g_stats[2*H1C + c] * invM;
    float v2 = g_stats[3*H1C + c] * invM - m2*m2;
    float a = (g_xc1[idx]  - m1) * rsqrtf(v1 + BNEPS) * g1[c]  + beta1[c];
    float r = (g_res1[idx] - m2) * rsqrtf(v2 + BNEPS) * rg1[c] + rbeta1[c];
    float o = a + r;
    g_h1[idx] = o > 0.f ? o : 0.f;
}

// ---------------- generic SGEMM: A[M,K] row-major, B[K,N] row-major --------
__global__ __launch_bounds__(256) void sgemm_rowA(
        const float* __restrict__ A, const float* __restrict__ B,
        const float* __restrict__ bias, float* __restrict__ C,
        int M, int N, int K) {
    const int BK = 8;
    __shared__ float As[2][BK][128];
    __shared__ float Bs[2][BK][128];
    int tid = threadIdx.x;
    int bm = blockIdx.x * 128;
    int bn = blockIdx.y * 128;

    int arow = tid >> 1;
    int acol = (tid & 1) * 4;
    int brow = tid >> 5;
    int bcol = (tid & 31) * 4;
    int tx = tid & 15, ty = tid >> 4;

    float acc[8][8];
#pragma unroll
    for (int i = 0; i < 8; i++)
#pragma unroll
        for (int j = 0; j < 8; j++) acc[i][j] = 0.f;

    float4 aReg = *(const float4*)(A + (size_t)(bm + arow) * K + acol);
    float4 bReg = *(const float4*)(B + (size_t)brow * N + bn + bcol);
    As[0][acol+0][arow] = aReg.x; As[0][acol+1][arow] = aReg.y;
    As[0][acol+2][arow] = aReg.z; As[0][acol+3][arow] = aReg.w;
    *(float4*)&Bs[0][brow][bcol] = bReg;
    __syncthreads();

    int nt = K / BK, cur = 0;
    for (int t = 0; t < nt; ++t) {
        if (t + 1 < nt) {
            int k0 = (t + 1) * BK;
            aReg = *(const float4*)(A + (size_t)(bm + arow) * K + k0 + acol);
            bReg = *(const float4*)(B + (size_t)(k0 + brow) * N + bn + bcol);
        }
#pragma unroll
        for (int kk = 0; kk < BK; ++kk) {
            float4 a0 = *(const float4*)&As[cur][kk][ty*8];
            float4 a1 = *(const float4*)&As[cur][kk][ty*8+4];
            float4 b0 = *(const float4*)&Bs[cur][kk][tx*8];
            float4 b1 = *(const float4*)&Bs[cur][kk][tx*8+4];
            float av[8] = {a0.x,a0.y,a0.z,a0.w,a1.x,a1.y,a1.z,a1.w};
            float bv[8] = {b0.x,b0.y,b0.z,b0.w,b1.x,b1.y,b1.z,b1.w};
#pragma unroll
            for (int i = 0; i < 8; i++)
#pragma unroll
                for (int j = 0; j < 8; j++) acc[i][j] += av[i]*bv[j];
        }
        if (t + 1 < nt) {
            int nxt = cur ^ 1;
            As[nxt][acol+0][arow] = aReg.x; As[nxt][acol+1][arow] = aReg.y;
            As[nxt][acol+2][arow] = aReg.z; As[nxt][acol+3][arow] = aReg.w;
            *(float4*)&Bs[nxt][brow][bcol] = bReg;
        }
        __syncthreads();
        cur ^= 1;
    }
#pragma unroll
    for (int i = 0; i < 8; i++) {
        int m = bm + ty*8 + i;
        float* cp = C + (size_t)m * N + bn + tx*8;
#pragma unroll
        for (int j = 0; j < 8; j++) cp[j] = acc[i][j] + bias[bn + tx*8 + j];
    }
}

// ---------------- node mix for stage 2 --------------------------------------
__global__ void nodemix2(const float* __restrict__ adj, const float* __restrict__ eimp) {
    __shared__ float ys[NNODE*HHC];
    __shared__ float Asm[NNODE*NNODE];
    int bs = blockIdx.x, tid = threadIdx.x;
    if (tid < NNODE*NNODE) Asm[tid] = adj[tid] * eimp[tid];
    for (int e = tid; e < NNODE*HHC; e += blockDim.x)
        ys[e] = g_y2[(size_t)bs*NNODE*HHC + e];
    __syncthreads();
    for (int e = tid; e < NNODE*HHC; e += blockDim.x) {
        int n = e / HHC, c = e % HHC;
        float acc = 0.f;
#pragma unroll
        for (int m = 0; m < NNODE; m++) acc += Asm[n*NNODE + m] * ys[m*HHC + c];
        g_xc2[(size_t)bs*NNODE*HHC + e] = acc;
    }
}

// ---------------- BN apply stage 2 fused with transpose into [B,TC,L] ------
__global__ void bn_apply2_transpose(const float* __restrict__ g2, const float* __restrict__ beta2,
                                    const float* __restrict__ rg2, const float* __restrict__ rbeta2) {
    __shared__ float tile[32][33];
    int s0 = blockIdx.x * 32, c0 = blockIdx.y * 32;
    int bn = blockIdx.z;
    int b = bn / NNODE, n = bn % NNODE;
    int tx = threadIdx.x, ty = threadIdx.y;
    const float invM = 1.f / (float)M1R;
    int c = c0 + tx;
    float m1 = g_stats[c] * invM;
    float v1 = g_stats[HHC + c] * invM - m1*m1;
    float m2 = g_stats[2*HHC + c] * invM;
    float v2 = g_stats[3*HHC + c] * invM - m2*m2;
    float sc1 = rsqrtf(v1 + BNEPS) * g2[c];
    float sh1 = beta2[c] - m1*sc1;
    float sc2 = rsqrtf(v2 + BNEPS) * rg2[c];
    float sh2 = rbeta2[c] - m2*sc2;
#pragma unroll
    for (int j = 0; j < 4; j++) {
        int s = s0 + ty + 8*j;
        size_t ridx = (((size_t)(b*Ss + s) * NNODE) + n) * HHC + c;
        float o = g_xc2[ridx]*sc1 + sh1 + g_res2[ridx]*sc2 + sh2;
        tile[ty + 8*j][tx] = o > 0.f ? o : 0.f;
    }
    __syncthreads();
#pragma unroll
    for (int j = 0; j < 4; j++) {
        int cc = c0 + ty + 8*j;
        int s  = s0 + tx;
        g_ht[((size_t)b*TCC + n*HHC + cc) * LLEN + s] = tile[tx][ty + 8*j];
    }
}

// ---------------- conv1d as GEMM (K fused over 5*1536 with shifted B) ------
__global__ __launch_bounds__(256) void conv_gemm(
        const float* __restrict__ X, const float* __restrict__ Wt, float* __restrict__ Y) {
    const int BK = 8;
    __shared__ float As[2][BK][128];
    __shared__ float Bs[2][BK][128];
    int tid = threadIdx.x;
    int bm = blockIdx.x * 128;   // co
    int bn = blockIdx.y * 128;   // l
    const float* Xb = X + (size_t)blockIdx.z * TCC * LLEN;
    float* Yb = Y + (size_t)blockIdx.z * TCC * LLEN;

    int lrow = tid >> 5;
    int lcol = (tid & 31) * 4;
    int tx = tid & 15, ty = tid >> 4;

    float acc[8][8];
#pragma unroll
    for (int i = 0; i < 8; i++)
#pragma unroll
        for (int j = 0; j < 8; j++) acc[i][j] = 0.f;

    float4 aReg;
    float bReg[4];
    {
        int kk = lrow;
        aReg = *(const float4*)(Wt + (size_t)kk * TCC + bm + lcol);
        int lbase = bn + lcol - 2;           // kseg = 0
        const float* p = Xb + (size_t)kk * LLEN;
#pragma unroll
        for (int j = 0; j < 4; j++) {
            int l = lbase + j;
            bReg[j] = (l >= 0 && l < LLEN) ? p[l] : 0.f;
        }
        *(float4*)&As[0][lrow][lcol] = aReg;
        *(float4*)&Bs[0][lrow][lcol] = make_float4(bReg[0], bReg[1], bReg[2], bReg[3]);
    }
    __syncthreads();

    const int NT = RKK / BK;   // 960
    int cur = 0;
    for (int t = 0; t < NT; ++t) {
        if (t + 1 < NT) {
            int k0 = (t + 1) * BK;
            int kk = k0 + lrow;
            aReg = *(const float4*)(Wt + (size_t)kk * TCC + bm + lcol);
            int kseg = kk / TCC;
            int ci = kk - kseg * TCC;
            int lbase = bn + lcol + kseg - 2;
            const float* p = Xb + (size_t)ci * LLEN;
#pragma unroll
            for (int j = 0; j < 4; j++) {
                int l = lbase + j;
                bReg[j] = (l >= 0 && l < LLEN) ? p[l] : 0.f;
            }
        }
#pragma unroll
        for (int kk = 0; kk < BK; ++kk) {
            float4 a0 = *(const float4*)&As[cur][kk][ty*8];
            float4 a1 = *(const float4*)&As[cur][kk][ty*8+4];
            float4 b0 = *(const float4*)&Bs[cur][kk][tx*8];
            float4 b1 = *(const float4*)&Bs[cur][kk][tx*8+4];
            float av[8] = {a0.x,a0.y,a0.z,a0.w,a1.x,a1.y,a1.z,a1.w};
            float bv[8] = {b0.x,b0.y,b0.z,b0.w,b1.x,b1.y,b1.z,b1.w};
#pragma unroll
            for (int i = 0; i < 8; i++)
#pragma unroll
                for (int j = 0; j < 8; j++) acc[i][j] += av[i]*bv[j];
        }
        if (t + 1 < NT) {
            int nxt = cur ^ 1;
            *(float4*)&As[nxt][lrow][lcol] = aReg;
            *(float4*)&Bs[nxt][lrow][lcol] = make_float4(bReg[0], bReg[1], bReg[2], bReg[3]);
        }
        __syncthreads();
        cur ^= 1;
    }
#pragma unroll
    for (int i = 0; i < 8; i++) {
        float* yp = Yb + (size_t)(bm + ty*8 + i) * LLEN + bn + tx*8;
        *(float4*)yp     = make_float4(acc[i][0], acc[i][1], acc[i][2], acc[i][3]);
        *(float4*)(yp+4) = make_float4(acc[i][4], acc[i][5], acc[i][6], acc[i][7]);
    }
}

// ---------------- conv BN stats / apply -------------------------------------
__global__ void conv_stats(const float* __restrict__ T) {
    int c = blockIdx.x;
    int tid = threadIdx.x;
    float s = 0.f, q = 0.f;
    for (int b = 0; b < Bb; b++) {
        const float* p = T + ((size_t)b * TCC + c) * LLEN;
        for (int l = tid; l < LLEN; l += blockDim.x) {
            float v = p[l]; s += v; q += v*v;
        }
    }
    __shared__ float ss[256], qq[256];
    ss[tid] = s; qq[tid] = q;
    __syncthreads();
    for (int o = 128; o > 0; o >>= 1) {
        if (tid < o) { ss[tid] += ss[tid+o]; qq[tid] += qq[tid+o]; }
        __syncthreads();
    }
    if (tid == 0) { g_stats[c] = ss[0]; g_stats[TCC + c] = qq[0]; }
}

__global__ void conv_bn(float* __restrict__ T, const float* __restrict__ g,
                        const float* __restrict__ beta, const float* __restrict__ resid) {
    size_t idx = (size_t)blockIdx.x * blockDim.x + threadIdx.x;
    if (idx >= (size_t)Bb*TCC*LLEN) return;
    int c = (int)((idx / LLEN) % TCC);
    const float invM = 1.f / (float)(Bb * LLEN);
    float m = g_stats[c] * invM;
    float v = g_stats[TCC + c] * invM - m*m;
    float o = (T[idx] - m) * rsqrtf(v + BNEPS) * g[c] + beta[c];
    o = o > 0.f ? o : 0.f;
    if (resid) o += resid[idx];
    T[idx] = o;
}

// ---------------- output GEMM: A=[K=TC, M=512] K-major, B=owT[TC,256] ------
__global__ __launch_bounds__(256) void out_gemm(
        const float* __restrict__ T2, const float* __restrict__ Bw,
        const float* __restrict__ ob, float* __restrict__ out) {
    const int BK = 8;
    __shared__ float As[2][BK][128];
    __shared__ float Bs[2][BK][128];
    int tid = threadIdx.x;
    int bm = blockIdx.x * 128;   // s
    int bn = blockIdx.y * 128;   // o
    int b = blockIdx.z;
    const float* Ab = T2 + (size_t)b * TCC * LLEN;

    int lrow = tid >> 5;
    int lcol = (tid & 31) * 4;
    int tx = tid & 15, ty = tid >> 4;

    float acc[8][8];
#pragma unroll
    for (int i = 0; i < 8; i++)
#pragma unroll
        for (int j = 0; j < 8; j++) acc[i][j] = 0.f;

    float4 aReg = *(const float4*)(Ab + (size_t)lrow * LLEN + bm + lcol);
    float4 bReg = *(const float4*)(Bw + (size_t)lrow * HHC + bn + lcol);
    *(float4*)&As[0][lrow][lcol] = aReg;
    *(float4*)&Bs[0][lrow][lcol] = bReg;
    __syncthreads();

    const int NT = TCC / BK;  // 192
    int cur = 0;
    for (int t = 0; t < NT; ++t) {
        if (t + 1 < NT) {
            int k0 = (t + 1) * BK;
            aReg = *(const float4*)(Ab + (size_t)(k0 + lrow) * LLEN + bm + lcol);
            bReg = *(const float4*)(Bw + (size_t)(k0 + lrow) * HHC + bn + lcol);
        }
#pragma unroll
        for (int kk = 0; kk < BK; ++kk) {
            float4 a0 = *(const float4*)&As[cur][kk][ty*8];
            float4 a1 = *(const float4*)&As[cur][kk][ty*8+4];
            float4 b0 = *(const float4*)&Bs[cur][kk][tx*8];
            float4 b1 = *(const float4*)&Bs[cur][kk][tx*8+4];
            float av[8] = {a0.x,a0.y,a0.z,a0.w,a1.x,a1.y,a1.z,a1.w};
            float bv[8] = {b0.x,b0.y,b0.z,b0.w,b1.x,b1.y,b1.z,b1.w};
#pragma unroll
            for (int i = 0; i < 8; i++)
#pragma unroll
                for (int j = 0; j < 8; j++) acc[i][j] += av[i]*bv[j];
        }
        if (t + 1 < NT) {
            int nxt = cur ^ 1;
            *(float4*)&As[nxt][lrow][lcol] = aReg;
            *(float4*)&Bs[nxt][lrow][lcol] = bReg;
        }
        __syncthreads();
        cur ^= 1;
    }
#pragma unroll
    for (int i = 0; i < 8; i++) {
        int s = bm + ty*8 + i;
        float* op = out + ((size_t)b * Ss + s) * HHC + bn + tx*8;
#pragma unroll
        for (int j = 0; j < 8; j++) {
            float v = acc[i][j] + ob[bn + tx*8 + j];
            op[j] = v > 0.f ? v : 0.f;
        }
    }
}

// ---------------- launch ----------------------------------------------------
extern "C" void kernel_launch(void* const* d_in, const int* in_sizes, int n_in,
                              void* d_out, int out_size) {
    const float* x     = (const float*)d_in[0];
    const float* adj   = (const float*)d_in[1];
    const float* eimp  = (const float*)d_in[2];
    const float* w1    = (const float*)d_in[3];
    const float* b1    = (const float*)d_in[4];
    const float* rw1   = (const float*)d_in[5];
    const float* rb1   = (const float*)d_in[6];
    const float* rg1   = (const float*)d_in[7];
    const float* rbeta1= (const float*)d_in[8];
    const float* g1    = (const float*)d_in[9];
    const float* beta1 = (const float*)d_in[10];
    const float* w2    = (const float*)d_in[11];
    const float* b2    = (const float*)d_in[12];
    const float* rw2   = (const float*)d_in[13];
    const float* rb2   = (const float*)d_in[14];
    const float* rg2   = (const float*)d_in[15];
    const float* rbeta2= (const float*)d_in[16];
    const float* g2    = (const float*)d_in[17];
    const float* beta2 = (const float*)d_in[18];
    const float* cw1   = (const float*)d_in[19];
    /* cb1 = d_in[20]: cancels exactly through BN mean-subtraction */
    const float* cg1   = (const float*)d_in[21];
    const float* cbeta1= (const float*)d_in[22];
    const float* cw2   = (const float*)d_in[23];
    /* cb2 = d_in[24]: cancels exactly */
    const float* cg2   = (const float*)d_in[25];
    const float* cbeta2= (const float*)d_in[26];
    const float* ow    = (const float*)d_in[27];
    const float* ob    = (const float*)d_in[28];
    float* out = (float*)d_out;

    float *p_xc1, *p_res1, *p_h1, *p_y2, *p_res2, *p_xc2, *p_ht, *p_t1, *p_t2;
    float *p_wt1, *p_wt2, *p_w2T, *p_rw2T, *p_owT;
    cudaGetSymbolAddress((void**)&p_xc1,  g_xc1);
    cudaGetSymbolAddress((void**)&p_res1, g_res1);
    cudaGetSymbolAddress((void**)&p_h1,   g_h1);
    cudaGetSymbolAddress((void**)&p_y2,   g_y2);
    cudaGetSymbolAddress((void**)&p_res2, g_res2);
    cudaGetSymbolAddress((void**)&p_xc2,  g_xc2);
    cudaGetSymbolAddress((void**)&p_ht,   g_ht);
    cudaGetSymbolAddress((void**)&p_t1,   g_t1);
    cudaGetSymbolAddress((void**)&p_t2,   g_t2);
    cudaGetSymbolAddress((void**)&p_wt1,  g_wt1);
    cudaGetSymbolAddress((void**)&p_wt2,  g_wt2);
    cudaGetSymbolAddress((void**)&p_w2T,  g_w2T);
    cudaGetSymbolAddress((void**)&p_rw2T, g_rw2T);
    cudaGetSymbolAddress((void**)&p_owT,  g_owT);

    // -------- GCN stage 1 --------
    gcn1_kernel<<<NBS, 256>>>(x, adj, eimp, w1, b1, rw1, rb1);
    zero_stats_k<<<(4*TCC + 255)/256, 256>>>();
    stats_rows<<<256, H1C>>>(p_xc1, p_res1, M1R, H1C);
    bn_apply1<<<(M1R*H1C)/256, 256>>>(g1, beta1, rg1, rbeta1);

    // -------- GCN stage 2 --------
    transpose_small<<<(HHC*H1C + 255)/256, 256>>>(w2,  p_w2T,  HHC, H1C);
    transpose_small<<<(HHC*H1C + 255)/256, 256>>>(rw2, p_rw2T, HHC, H1C);
    sgemm_rowA<<<dim3(M1R/128, HHC/128), 256>>>(p_h1, p_w2T,  b2,  p_y2,   M1R, HHC, H1C);
    sgemm_rowA<<<dim3(M1R/128, HHC/128), 256>>>(p_h1, p_rw2T, rb2, p_res2, M1R, HHC, H1C);
    nodemix2<<<NBS, 256>>>(adj, eimp);
    zero_stats_k<<<(4*TCC + 255)/256, 256>>>();
    stats_rows<<<256, HHC>>>(p_xc2, p_res2, M1R, HHC);
    bn_apply2_transpose<<<dim3(Ss/32, HHC/32, Bb*NNODE), dim3(32, 8)>>>(g2, beta2, rg2, rbeta2);

    // -------- TCN conv 1 --------
    wtrans_conv<<<(TCC*TCC + 255)/256, 256>>>(cw1, p_wt1);
    conv_gemm<<<dim3(TCC/128, LLEN/128, Bb), 256>>>(p_ht, p_wt1, p_t1);
    conv_stats<<<TCC, 256>>>(p_t1);
    conv_bn<<<(Bb*TCC*LLEN)/256, 256>>>(p_t1, cg1, cbeta1, (const float*)nullptr);

    // -------- TCN conv 2 + residual --------
    wtrans_conv<<<(TCC*TCC + 255)/256, 256>>>(cw2, p_wt2);
    conv_gemm<<<dim3(TCC/128, LLEN/128, Bb), 256>>>(p_t1, p_wt2, p_t2);
    conv_stats<<<TCC, 256>>>(p_t2);
    conv_bn<<<(Bb*TCC*LLEN)/256, 256>>>(p_t2, cg2, cbeta2, p_ht);

    // -------- output layer --------
    transpose_small<<<(HHC*TCC + 255)/256, 256>>>(ow, p_owT, HHC, TCC);
    out_gemm<<<dim3(LLEN/128, HHC/128, Bb), 256>>>(p_t2, p_owT, ob, out);

    (void)in_sizes; (void)n_in; (void)out_size;
}

// round 2
// speedup vs baseline: 1.9150x; 1.9150x over previous
#include <cuda_runtime.h>
#include <math.h>

#define Bb 32
#define Ss 512
#define NNODE 6
#define CIN 12
#define H1C 128
#define HHC 256
#define TCC 1536
#define LLEN 512
#define M1R (Bb*Ss*NNODE)   /* 98304 */
#define NBS (Bb*Ss)         /* 16384 */
#define RKK (5*TCC)         /* 7680  */
#define BNEPS 1e-5f
#define BKc 16

// ---------------- scratch (device globals; no runtime allocation) ----------
__device__ float g_xc1 [M1R*H1C];
__device__ float g_res1[M1R*H1C];
__device__ float g_h1  [M1R*H1C];
__device__ float g_y2  [M1R*HHC];
__device__ float g_res2[M1R*HHC];
__device__ float g_xc2 [M1R*HHC];
__device__ float g_ht  [Bb*TCC*LLEN];
__device__ float g_t1  [Bb*TCC*LLEN];
__device__ float g_t2  [Bb*TCC*LLEN];
__device__ float g_wt1 [RKK*TCC];
__device__ float g_wt2 [RKK*TCC];
__device__ float g_w2T [H1C*HHC];
__device__ float g_rw2T[H1C*HHC];
__device__ float g_owT [TCC*HHC];
__device__ float g_stats[4*TCC];

// ---------------- tf32 helpers ----------------------------------------------
__device__ __forceinline__ unsigned f2tf32(float f) {
    unsigned u; asm("cvt.rna.tf32.f32 %0, %1;" : "=r"(u) : "f"(f)); return u;
}
#define MMA_TF32(c, a, b) \
    asm volatile("mma.sync.aligned.m16n8k8.row.col.f32.tf32.tf32.f32 " \
        "{%0,%1,%2,%3}, {%4,%5,%6,%7}, {%8,%9}, {%0,%1,%2,%3};" \
        : "+f"((c)[0]), "+f"((c)[1]), "+f"((c)[2]), "+f"((c)[3]) \
        : "r"((a)[0]), "r"((a)[1]), "r"((a)[2]), "r"((a)[3]), \
          "r"((b)[0]), "r"((b)[1]))

// ---------------- small utility kernels ------------------------------------
__global__ void zero_stats_k() {
    int i = blockIdx.x * blockDim.x + threadIdx.x;
    if (i < 4*TCC) g_stats[i] = 0.f;
}

__global__ void transpose_small(const float* __restrict__ in, float* __restrict__ out,
                                int R, int C) {
    int idx = blockIdx.x * blockDim.x + threadIdx.x;
    if (idx >= R * C) return;
    int r = idx / C, c = idx % C;
    out[(size_t)c * R + r] = in[idx];
}

// wt[(k*TC+ci)*TC + co] = cw[(co*TC+ci)*5 + k]
__global__ void wtrans_conv(const float* __restrict__ cw, float* __restrict__ wt) {
    int idx = blockIdx.x * blockDim.x + threadIdx.x;
    if (idx >= TCC * TCC) return;
    int ci = idx / TCC;
    int co = idx % TCC;
    const float* src = cw + ((size_t)co * TCC + ci) * 5;
#pragma unroll
    for (int k = 0; k < 5; k++)
        wt[((size_t)k * TCC + ci) * TCC + co] = src[k];
}

// ---------------- GCN stage 1 (K=12, fused linear + node mix) --------------
__global__ void gcn1_kernel(const float* __restrict__ x, const float* __restrict__ adj,
                            const float* __restrict__ eimp,
                            const float* __restrict__ w1, const float* __restrict__ b1,
                            const float* __restrict__ rw1, const float* __restrict__ rb1) {
    __shared__ float xs[NNODE*CIN];
    __shared__ float Asm[NNODE*NNODE];
    __shared__ float xts[NNODE*H1C];
    int bs = blockIdx.x;
    int tid = threadIdx.x;
    if (tid < NNODE*CIN) xs[tid] = x[(size_t)bs*NNODE*CIN + tid];
    if (tid >= 128 && tid < 128 + NNODE*NNODE) Asm[tid-128] = adj[tid-128] * eimp[tid-128];
    __syncthreads();
    for (int e = tid; e < NNODE*H1C; e += blockDim.x) {
        int n = e / H1C, c = e % H1C;
        float ws = b1[c], rs = rb1[c];
#pragma unroll
        for (int i = 0; i < CIN; i++) {
            float xv = xs[n*CIN + i];
            ws += xv * w1[c*CIN + i];
            rs += xv * rw1[c*CIN + i];
        }
        xts[e] = ws;
        g_res1[(size_t)bs*(NNODE*H1C) + e] = rs;
    }
    __syncthreads();
    for (int e = tid; e < NNODE*H1C; e += blockDim.x) {
        int n = e / H1C, c = e % H1C;
        float acc = 0.f;
#pragma unroll
        for (int m = 0; m < NNODE; m++) acc += Asm[n*NNODE + m] * xts[m*H1C + c];
        g_xc1[(size_t)bs*(NNODE*H1C) + e] = acc;
    }
}

__global__ void stats_rows(const float* __restrict__ a, const float* __restrict__ b,
                           int Mrows, int C) {
    int c = threadIdx.x;
    int rows_per = Mrows / gridDim.x;
    int r0 = blockIdx.x * rows_per;
    int r1 = r0 + rows_per;
    float sa = 0.f, qa = 0.f, sb = 0.f, qb = 0.f;
    for (int r = r0; r < r1; r++) {
        float v = a[(size_t)r*C + c]; sa += v; qa += v*v;
        float u = b[(size_t)r*C + c]; sb += u; qb += u*u;
    }
    atomicAdd(&g_stats[c],       sa);
    atomicAdd(&g_stats[C + c],   qa);
    atomicAdd(&g_stats[2*C + c], sb);
    atomicAdd(&g_stats[3*C + c], qb);
}

__global__ void bn_apply1(const float* __restrict__ g1, const float* __restrict__ beta1,
                          const float* __restrict__ rg1, const float* __restrict__ rbeta1) {
    size_t idx = (size_t)blockIdx.x * blockDim.x + threadIdx.x;
    if (idx >= (size_t)M1R*H1C) return;
    int c = (int)(idx % H1C);
    const float invM = 1.f / (float)M1R;
    float m1 = g_stats[c] * invM;
    float v1 = g_stats[H1C + c] * invM - m1*m1;
    float m2 = g_stats[2*H1C + c] * invM;
    float v2 = g_stats[3*H1C + c] * invM - m2*m2;
    float a = (g_xc1[idx]  - m1) * rsqrtf(v1 + BNEPS) * g1[c]  + beta1[c];
    float r = (g_res1[idx] - m2) * rsqrtf(v2 + BNEPS) * rg1[c] + rbeta1[c];
    float o = a + r;
    g_h1[idx] = o > 0.f ? o : 0.f;
}

// ---------------- generic fp32 SGEMM (small GCN GEMMs) ----------------------
__global__ __launch_bounds__(256) void sgemm_rowA(
        const float* __restrict__ A, const float* __restrict__ B,
        const float* __restrict__ bias, float* __restrict__ C,
        int M, int N, int K) {
    const int BK = 8;
    __shared__ float As[2][BK][128];
    __shared__ float Bs[2][BK][128];
    int tid = threadIdx.x;
    int bm = blockIdx.x * 128;
    int bn = blockIdx.y * 128;

    int arow = tid >> 1;
    int acol = (tid & 1) * 4;
    int brow = tid >> 5;
    int bcol = (tid & 31) * 4;
    int tx = tid & 15, ty = tid >> 4;

    float acc[8][8];
#pragma unroll
    for (int i = 0; i < 8; i++)
#pragma unroll
        for (int j = 0; j < 8; j++) acc[i][j] = 0.f;

    float4 aReg = *(const float4*)(A + (size_t)(bm + arow) * K + acol);
    float4 bReg = *(const float4*)(B + (size_t)brow * N + bn + bcol);
    As[0][acol+0][arow] = aReg.x; As[0][acol+1][arow] = aReg.y;
    As[0][acol+2][arow] = aReg.z; As[0][acol+3][arow] = aReg.w;
    *(float4*)&Bs[0][brow][bcol] = bReg;
    __syncthreads();

    int nt = K / BK, cur = 0;
    for (int t = 0; t < nt; ++t) {
        if (t + 1 < nt) {
            int k0 = (t + 1) * BK;
            aReg = *(const float4*)(A + (size_t)(bm + arow) * K + k0 + acol);
            bReg = *(const float4*)(B + (size_t)(k0 + brow) * N + bn + bcol);
        }
#pragma unroll
        for (int kk = 0; kk < BK; ++kk) {
            float4 a0 = *(const float4*)&As[cur][kk][ty*8];
            float4 a1 = *(const float4*)&As[cur][kk][ty*8+4];
            float4 b0 = *(const float4*)&Bs[cur][kk][tx*8];
            float4 b1 = *(const float4*)&Bs[cur][kk][tx*8+4];
            float av[8] = {a0.x,a0.y,a0.z,a0.w,a1.x,a1.y,a1.z,a1.w};
            float bv[8] = {b0.x,b0.y,b0.z,b0.w,b1.x,b1.y,b1.z,b1.w};
#pragma unroll
            for (int i = 0; i < 8; i++)
#pragma unroll
                for (int j = 0; j < 8; j++) acc[i][j] += av[i]*bv[j];
        }
        if (t + 1 < nt) {
            int nxt = cur ^ 1;
            As[nxt][acol+0][arow] = aReg.x; As[nxt][acol+1][arow] = aReg.y;
            As[nxt][acol+2][arow] = aReg.z; As[nxt][acol+3][arow] = aReg.w;
            *(float4*)&Bs[nxt][brow][bcol] = bReg;
        }
        __syncthreads();
        cur ^= 1;
    }
#pragma unroll
    for (int i = 0; i < 8; i++) {
        int m = bm + ty*8 + i;
        float* cp = C + (size_t)m * N + bn + tx*8;
#pragma unroll
        for (int j = 0; j < 8; j++) cp[j] = acc[i][j] + bias[bn + tx*8 + j];
    }
}

// ---------------- node mix for stage 2 --------------------------------------
__global__ void nodemix2(const float* __restrict__ adj, const float* __restrict__ eimp) {
    __shared__ float ys[NNODE*HHC];
    __shared__ float Asm[NNODE*NNODE];
    int bs = blockIdx.x, tid = threadIdx.x;
    if (tid < NNODE*NNODE) Asm[tid] = adj[tid] * eimp[tid];
    for (int e = tid; e < NNODE*HHC; e += blockDim.x)
        ys[e] = g_y2[(size_t)bs*NNODE*HHC + e];
    __syncthreads();
    for (int e = tid; e < NNODE*HHC; e += blockDim.x) {
        int n = e / HHC, c = e % HHC;
        float acc = 0.f;
#pragma unroll
        for (int m = 0; m < NNODE; m++) acc += Asm[n*NNODE + m] * ys[m*HHC + c];
        g_xc2[(size_t)bs*NNODE*HHC + e] = acc;
    }
}

// ---------------- BN apply stage 2 fused with transpose into [B,TC,L] ------
__global__ void bn_apply2_transpose(const float* __restrict__ g2, const float* __restrict__ beta2,
                                    const float* __restrict__ rg2, const float* __restrict__ rbeta2) {
    __shared__ float tile[32][33];
    int s0 = blockIdx.x * 32, c0 = blockIdx.y * 32;
    int bn = blockIdx.z;
    int b = bn / NNODE, n = bn % NNODE;
    int tx = threadIdx.x, ty = threadIdx.y;
    const float invM = 1.f / (float)M1R;
    int c = c0 + tx;
    float m1 = g_stats[c] * invM;
    float v1 = g_stats[HHC + c] * invM - m1*m1;
    float m2 = g_stats[2*HHC + c] * invM;
    float v2 = g_stats[3*HHC + c] * invM - m2*m2;
    float sc1 = rsqrtf(v1 + BNEPS) * g2[c];
    float sh1 = beta2[c] - m1*sc1;
    float sc2 = rsqrtf(v2 + BNEPS) * rg2[c];
    float sh2 = rbeta2[c] - m2*sc2;
#pragma unroll
    for (int j = 0; j < 4; j++) {
        int s = s0 + ty + 8*j;
        size_t ridx = (((size_t)(b*Ss + s) * NNODE) + n) * HHC + c;
        float o = g_xc2[ridx]*sc1 + sh1 + g_res2[ridx]*sc2 + sh2;
        tile[ty + 8*j][tx] = o > 0.f ? o : 0.f;
    }
    __syncthreads();
#pragma unroll
    for (int j = 0; j < 4; j++) {
        int cc = c0 + ty + 8*j;
        int s  = s0 + tx;
        g_ht[((size_t)b*TCC + n*HHC + cc) * LLEN + s] = tile[tx][ty + 8*j];
    }
}

// ---------------- conv1d as tf32 tensor-core GEMM ---------------------------
// A = Wt [RKK, TCC] k-major; B = shifted X [RKK-fused, LLEN]; C = Y [TCC, LLEN]
__global__ __launch_bounds__(256) void conv_gemm_tf32(
        const float* __restrict__ X, const float* __restrict__ Wt, float* __restrict__ Y) {
    __shared__ float As[2][BKc][132];
    __shared__ float Bs[2][BKc][132];
    const int tid = threadIdx.x;
    const int bm = blockIdx.x * 128;   // co
    const int bn = blockIdx.y * 128;   // l
    const float* Xb = X + (size_t)blockIdx.z * TCC * LLEN;
    float* Yb = Y + (size_t)blockIdx.z * TCC * LLEN;
    const int lane = tid & 31, wid = tid >> 5;
    const int wm = (wid & 1) * 64, wn = (wid >> 1) * 32;
    const int g = lane >> 2, tg = lane & 3;
    const int lkk = tid >> 4;           // 0..15
    const int lnb = (tid & 15) * 8;     // 0..120

    float acc[4][4][4];
#pragma unroll
    for (int mi = 0; mi < 4; mi++)
#pragma unroll
        for (int ni = 0; ni < 4; ni++)
#pragma unroll
            for (int r = 0; r < 4; r++) acc[mi][ni][r] = 0.f;

    float aS[8], bS[8];
    // prologue: stage tile 0
    {
        const float* wp = Wt + (size_t)lkk * TCC + bm + lnb;
        *(float4*)aS     = *(const float4*)wp;
        *(float4*)(aS+4) = *(const float4*)(wp + 4);
        const float* p = Xb + (size_t)lkk * LLEN;   // kseg=0
        int lbase = bn + lnb - 2;
#pragma unroll
        for (int j = 0; j < 8; j++) {
            int l = lbase + j;
            bS[j] = (l >= 0 && l < LLEN) ? p[l] : 0.f;
        }
        float4 v;
        v.x=__uint_as_float(f2tf32(aS[0])); v.y=__uint_as_float(f2tf32(aS[1]));
        v.z=__uint_as_float(f2tf32(aS[2])); v.w=__uint_as_float(f2tf32(aS[3]));
        *(float4*)&As[0][lkk][lnb] = v;
        v.x=__uint_as_float(f2tf32(aS[4])); v.y=__uint_as_float(f2tf32(aS[5]));
        v.z=__uint_as_float(f2tf32(aS[6])); v.w=__uint_as_float(f2tf32(aS[7]));
        *(float4*)&As[0][lkk][lnb+4] = v;
        v.x=__uint_as_float(f2tf32(bS[0])); v.y=__uint_as_float(f2tf32(bS[1]));
        v.z=__uint_as_float(f2tf32(bS[2])); v.w=__uint_as_float(f2tf32(bS[3]));
        *(float4*)&Bs[0][lkk][lnb] = v;
        v.x=__uint_as_float(f2tf32(bS[4])); v.y=__uint_as_float(f2tf32(bS[5]));
        v.z=__uint_as_float(f2tf32(bS[6])); v.w=__uint_as_float(f2tf32(bS[7]));
        *(float4*)&Bs[0][lkk][lnb+4] = v;
    }
    __syncthreads();

    const int NT = RKK / BKc;   // 480
    int cur = 0;
    for (int t = 0; t < NT; ++t) {
        if (t + 1 < NT) {
            int kkg = (t + 1) * BKc + lkk;
            const float* wp = Wt + (size_t)kkg * TCC + bm + lnb;
            *(float4*)aS     = *(const float4*)wp;
            *(float4*)(aS+4) = *(const float4*)(wp + 4);
            int kseg = kkg / TCC;
            int ci = kkg - kseg * TCC;
            const float* p = Xb + (size_t)ci * LLEN;
            int lbase = bn + lnb + kseg - 2;
#pragma unroll
            for (int j = 0; j < 8; j++) {
                int l = lbase + j;
                bS[j] = (l >= 0 && l < LLEN) ? p[l] : 0.f;
            }
        }
#pragma unroll
        for (int ks = 0; ks < BKc; ks += 8) {
            unsigned a[4][4], b[4][2];
#pragma unroll
            for (int mi = 0; mi < 4; mi++) {
                int m = wm + mi * 16;
                a[mi][0] = __float_as_uint(As[cur][ks+tg  ][m+g  ]);
                a[mi][1] = __float_as_uint(As[cur][ks+tg  ][m+g+8]);
                a[mi][2] = __float_as_uint(As[cur][ks+tg+4][m+g  ]);
                a[mi][3] = __float_as_uint(As[cur][ks+tg+4][m+g+8]);
            }
#pragma unroll
            for (int ni = 0; ni < 4; ni++) {
                int n = wn + ni * 8;
                b[ni][0] = __float_as_uint(Bs[cur][ks+tg  ][n+g]);
                b[ni][1] = __float_as_uint(Bs[cur][ks+tg+4][n+g]);
            }
#pragma unroll
            for (int mi = 0; mi < 4; mi++)
#pragma unroll
                for (int ni = 0; ni < 4; ni++)
                    MMA_TF32(acc[mi][ni], a[mi], b[ni]);
        }
        if (t + 1 < NT) {
            int nxt = cur ^ 1;
            float4 v;
            v.x=__uint_as_float(f2tf32(aS[0])); v.y=__uint_as_float(f2tf32(aS[1]));
            v.z=__uint_as_float(f2tf32(aS[2])); v.w=__uint_as_float(f2tf32(aS[3]));
            *(float4*)&As[nxt][lkk][lnb] = v;
            v.x=__uint_as_float(f2tf32(aS[4])); v.y=__uint_as_float(f2tf32(aS[5]));
            v.z=__uint_as_float(f2tf32(aS[6])); v.w=__uint_as_float(f2tf32(aS[7]));
            *(float4*)&As[nxt][lkk][lnb+4] = v;
            v.x=__uint_as_float(f2tf32(bS[0])); v.y=__uint_as_float(f2tf32(bS[1]));
            v.z=__uint_as_float(f2tf32(bS[2])); v.w=__uint_as_float(f2tf32(bS[3]));
            *(float4*)&Bs[nxt][lkk][lnb] = v;
            v.x=__uint_as_float(f2tf32(bS[4])); v.y=__uint_as_float(f2tf32(bS[5]));
            v.z=__uint_as_float(f2tf32(bS[6])); v.w=__uint_as_float(f2tf32(bS[7]));
            *(float4*)&Bs[nxt][lkk][lnb+4] = v;
        }
        __syncthreads();
        cur ^= 1;
    }

#pragma unroll
    for (int mi = 0; mi < 4; mi++) {
        int m0 = bm + wm + mi * 16 + g;
#pragma unroll
        for (int ni = 0; ni < 4; ni++) {
            int l = bn + wn + ni * 8 + 2 * tg;
            *(float2*)(Yb + (size_t)m0 * LLEN + l)     = make_float2(acc[mi][ni][0], acc[mi][ni][1]);
            *(float2*)(Yb + (size_t)(m0+8) * LLEN + l) = make_float2(acc[mi][ni][2], acc[mi][ni][3]);
        }
    }
}

// ---------------- conv BN stats / apply -------------------------------------
__global__ void conv_stats(const float* __restrict__ T) {
    int c = blockIdx.x;
    int tid = threadIdx.x;
    float s = 0.f, q = 0.f;
    for (int b = 0; b < Bb; b++) {
        const float* p = T + ((size_t)b * TCC + c) * LLEN;
        for (int l = tid; l < LLEN; l += blockDim.x) {
            float v = p[l]; s += v; q += v*v;
        }
    }
    __shared__ float ss[256], qq[256];
    ss[tid] = s; qq[tid] = q;
    __syncthreads();
    for (int o = 128; o > 0; o >>= 1) {
        if (tid < o) { ss[tid] += ss[tid+o]; qq[tid] += qq[tid+o]; }
        __syncthreads();
    }
    if (tid == 0) { g_stats[c] = ss[0]; g_stats[TCC + c] = qq[0]; }
}

__global__ void conv_bn(float* __restrict__ T, const float* __restrict__ g,
                        const float* __restrict__ beta, const float* __restrict__ resid) {
    size_t idx = (size_t)blockIdx.x * blockDim.x + threadIdx.x;
    if (idx >= (size_t)Bb*TCC*LLEN) return;
    int c = (int)((idx / LLEN) % TCC);
    const float invM = 1.f / (float)(Bb * LLEN);
    float m = g_stats[c] * invM;
    float v = g_stats[TCC + c] * invM - m*m;
    float o = (T[idx] - m) * rsqrtf(v + BNEPS) * g[c] + beta[c];
    o = o > 0.f ? o : 0.f;
    if (resid) o += resid[idx];
    T[idx] = o;
}

// ---------------- output GEMM (fp32, small) ---------------------------------
__global__ __launch_bounds__(256) void out_gemm(
        const float* __restrict__ T2, const float* __restrict__ Bw,
        const float* __restrict__ ob, float* __restrict__ out) {
    const int BK = 8;
    __shared__ float As[2][BK][128];
    __shared__ float Bs[2][BK][128];
    int tid = threadIdx.x;
    int bm = blockIdx.x * 128;   // s
    int bn = blockIdx.y * 128;   // o
    int b = blockIdx.z;
    const float* Ab = T2 + (size_t)b * TCC * LLEN;

    int lrow = tid >> 5;
    int lcol = (tid & 31) * 4;
    int tx = tid & 15, ty = tid >> 4;

    float acc[8][8];
#pragma unroll
    for (int i = 0; i < 8; i++)
#pragma unroll
        for (int j = 0; j < 8; j++) acc[i][j] = 0.f;

    float4 aReg = *(const float4*)(Ab + (size_t)lrow * LLEN + bm + lcol);
    float4 bReg = *(const float4*)(Bw + (size_t)lrow * HHC + bn + lcol);
    *(float4*)&As[0][lrow][lcol] = aReg;
    *(float4*)&Bs[0][lrow][lcol] = bReg;
    __syncthreads();

    const int NT = TCC / BK;  // 192
    int cur = 0;
    for (int t = 0; t < NT; ++t) {
        if (t + 1 < NT) {
            int k0 = (t + 1) * BK;
            aReg = *(const float4*)(Ab + (size_t)(k0 + lrow) * LLEN + bm + lcol);
            bReg = *(const float4*)(Bw + (size_t)(k0 + lrow) * HHC + bn + lcol);
        }
#pragma unroll
        for (int kk = 0; kk < BK; ++kk) {
            float4 a0 = *(const float4*)&As[cur][kk][ty*8];
            float4 a1 = *(const float4*)&As[cur][kk][ty*8+4];
            float4 b0 = *(const float4*)&Bs[cur][kk][tx*8];
            float4 b1 = *(const float4*)&Bs[cur][kk][tx*8+4];
            float av[8] = {a0.x,a0.y,a0.z,a0.w,a1.x,a1.y,a1.z,a1.w};
            float bv[8] = {b0.x,b0.y,b0.z,b0.w,b1.x,b1.y,b1.z,b1.w};
#pragma unroll
            for (int i = 0; i < 8; i++)
#pragma unroll
                for (int j = 0; j < 8; j++) acc[i][j] += av[i]*bv[j];
        }
        if (t + 1 < NT) {
            int nxt = cur ^ 1;
            *(float4*)&As[nxt][lrow][lcol] = aReg;
            *(float4*)&Bs[nxt][lrow][lcol] = bReg;
        }
        __syncthreads();
        cur ^= 1;
    }
#pragma unroll
    for (int i = 0; i < 8; i++) {
        int s = bm + ty*8 + i;
        float* op = out + ((size_t)b * Ss + s) * HHC + bn + tx*8;
#pragma unroll
        for (int j = 0; j < 8; j++) {
            float v = acc[i][j] + ob[bn + tx*8 + j];
            op[j] = v > 0.f ? v : 0.f;
        }
    }
}

// ---------------- launch ----------------------------------------------------
extern "C" void kernel_launch(void* const* d_in, const int* in_sizes, int n_in,
                              void* d_out, int out_size) {
    const float* x     = (const float*)d_in[0];
    const float* adj   = (const float*)d_in[1];
    const float* eimp  = (const float*)d_in[2];
    const float* w1    = (const float*)d_in[3];
    const float* b1    = (const float*)d_in[4];
    const float* rw1   = (const float*)d_in[5];
    const float* rb1   = (const float*)d_in[6];
    const float* rg1   = (const float*)d_in[7];
    const float* rbeta1= (const float*)d_in[8];
    const float* g1    = (const float*)d_in[9];
    const float* beta1 = (const float*)d_in[10];
    const float* w2    = (const float*)d_in[11];
    const float* b2    = (const float*)d_in[12];
    const float* rw2   = (const float*)d_in[13];
    const float* rb2   = (const float*)d_in[14];
    const float* rg2   = (const float*)d_in[15];
    const float* rbeta2= (const float*)d_in[16];
    const float* g2    = (const float*)d_in[17];
    const float* beta2 = (const float*)d_in[18];
    const float* cw1   = (const float*)d_in[19];
    /* cb1 = d_in[20]: cancels exactly through BN mean-subtraction */
    const float* cg1   = (const float*)d_in[21];
    const float* cbeta1= (const float*)d_in[22];
    const float* cw2   = (const float*)d_in[23];
    /* cb2 = d_in[24]: cancels exactly */
    const float* cg2   = (const float*)d_in[25];
    const float* cbeta2= (const float*)d_in[26];
    const float* ow    = (const float*)d_in[27];
    const float* ob    = (const float*)d_in[28];
    float* out = (float*)d_out;

    float *p_xc1, *p_res1, *p_h1, *p_y2, *p_res2, *p_xc2, *p_ht, *p_t1, *p_t2;
    float *p_wt1, *p_wt2, *p_w2T, *p_rw2T, *p_owT;
    cudaGetSymbolAddress((void**)&p_xc1,  g_xc1);
    cudaGetSymbolAddress((void**)&p_res1, g_res1);
    cudaGetSymbolAddress((void**)&p_h1,   g_h1);
    cudaGetSymbolAddress((void**)&p_y2,   g_y2);
    cudaGetSymbolAddress((void**)&p_res2, g_res2);
    cudaGetSymbolAddress((void**)&p_xc2,  g_xc2);
    cudaGetSymbolAddress((void**)&p_ht,   g_ht);
    cudaGetSymbolAddress((void**)&p_t1,   g_t1);
    cudaGetSymbolAddress((void**)&p_t2,   g_t2);
    cudaGetSymbolAddress((void**)&p_wt1,  g_wt1);
    cudaGetSymbolAddress((void**)&p_wt2,  g_wt2);
    cudaGetSymbolAddress((void**)&p_w2T,  g_w2T);
    cudaGetSymbolAddress((void**)&p_rw2T, g_rw2T);
    cudaGetSymbolAddress((void**)&p_owT,  g_owT);

    // -------- GCN stage 1 --------
    gcn1_kernel<<<NBS, 256>>>(x, adj, eimp, w1, b1, rw1, rb1);
    zero_stats_k<<<(4*TCC + 255)/256, 256>>>();
    stats_rows<<<256, H1C>>>(p_xc1, p_res1, M1R, H1C);
    bn_apply1<<<(M1R*H1C)/256, 256>>>(g1, beta1, rg1, rbeta1);

    // -------- GCN stage 2 --------
    transpose_small<<<(HHC*H1C + 255)/256, 256>>>(w2,  p_w2T,  HHC, H1C);
    transpose_small<<<(HHC*H1C + 255)/256, 256>>>(rw2, p_rw2T, HHC, H1C);
    sgemm_rowA<<<dim3(M1R/128, HHC/128), 256>>>(p_h1, p_w2T,  b2,  p_y2,   M1R, HHC, H1C);
    sgemm_rowA<<<dim3(M1R/128, HHC/128), 256>>>(p_h1, p_rw2T, rb2, p_res2, M1R, HHC, H1C);
    nodemix2<<<NBS, 256>>>(adj, eimp);
    zero_stats_k<<<(4*TCC + 255)/256, 256>>>();
    stats_rows<<<256, HHC>>>(p_xc2, p_res2, M1R, HHC);
    bn_apply2_transpose<<<dim3(Ss/32, HHC/32, Bb*NNODE), dim3(32, 8)>>>(g2, beta2, rg2, rbeta2);

    // -------- TCN conv 1 (tf32 tensor cores) --------
    wtrans_conv<<<(TCC*TCC + 255)/256, 256>>>(cw1, p_wt1);
    conv_gemm_tf32<<<dim3(TCC/128, LLEN/128, Bb), 256>>>(p_ht, p_wt1, p_t1);
    conv_stats<<<TCC, 256>>>(p_t1);
    conv_bn<<<(Bb*TCC*LLEN)/256, 256>>>(p_t1, cg1, cbeta1, (const float*)nullptr);

    // -------- TCN conv 2 + residual (tf32 tensor cores) --------
    wtrans_conv<<<(TCC*TCC + 255)/256, 256>>>(cw2, p_wt2);
    conv_gemm_tf32<<<dim3(TCC/128, LLEN/128, Bb), 256>>>(p_t1, p_wt2, p_t2);
    conv_stats<<<TCC, 256>>>(p_t2);
    conv_bn<<<(Bb*TCC*LLEN)/256, 256>>>(p_t2, cg2, cbeta2, p_ht);

    // -------- output layer --------
    transpose_small<<<(HHC*TCC + 255)/256, 256>>>(ow, p_owT, HHC, TCC);
    out_gemm<<<dim3(LLEN/128, HHC/128, Bb), 256>>>(p_t2, p_owT, ob, out);

    (void)in_sizes; (void)n_in; (void)out_size;
}

// round 4
// speedup vs baseline: 3.0243x; 1.5792x over previous
#include <cuda_runtime.h>
#include <math.h>
#include <stdint.h>

#define Bb 32
#define Ss 512
#define NNODE 6
#define CIN 12
#define H1C 128
#define HHC 256
#define TCC 1536
#define LLEN 512
#define LP 544              /* padded row stride: 16 | 512 | 16 */
#define OFFX 16
#define M1R (Bb*Ss*NNODE)   /* 98304 */
#define NBS (Bb*Ss)         /* 16384 */
#define RKK (5*TCC)         /* 7680  */
#define BNEPS 1e-5f

// ---------------- scratch (device globals; no runtime allocation) ----------
__device__ float g_xc1 [M1R*H1C];
__device__ float g_res1[M1R*H1C];
__device__ float g_h1  [M1R*H1C];
__device__ float g_y2  [M1R*HHC];
__device__ float g_res2[M1R*HHC];
__device__ float g_xc2 [M1R*HHC];
__device__ float g_ht  [Bb*TCC*LP];   // padded
__device__ float g_t1  [Bb*TCC*LP];   // padded
__device__ float g_t2  [Bb*TCC*LP];   // padded
__device__ float g_wt1 [RKK*TCC];     // [kk][co], tf32-rounded bits
__device__ float g_wt2 [RKK*TCC];
__device__ float g_w2T [H1C*HHC];
__device__ float g_rw2T[H1C*HHC];
__device__ float g_owT [TCC*HHC];
__device__ float g_stats[4*TCC];

// ---------------- helpers ----------------------------------------------------
__device__ __forceinline__ unsigned f2tf32(float f) {
    unsigned u; asm("cvt.rna.tf32.f32 %0, %1;" : "=r"(u) : "f"(f)); return u;
}
#define MMA_TF32(c, a, b) \
    asm volatile("mma.sync.aligned.m16n8k8.row.col.f32.tf32.tf32.f32 " \
        "{%0,%1,%2,%3}, {%4,%5,%6,%7}, {%8,%9}, {%0,%1,%2,%3};" \
        : "+f"((c)[0]), "+f"((c)[1]), "+f"((c)[2]), "+f"((c)[3]) \
        : "r"((a)[0]), "r"((a)[1]), "r"((a)[2]), "r"((a)[3]), \
          "r"((b)[0]), "r"((b)[1]))

__device__ __forceinline__ void cpasync16(uint32_t dst, const void* src) {
    asm volatile("cp.async.cg.shared.global [%0], [%1], 16;" :: "r"(dst), "l"(src));
}
__device__ __forceinline__ void cpa_commit() {
    asm volatile("cp.async.commit_group;" ::: "memory");
}
template<int N>
__device__ __forceinline__ void cpa_wait() {
    asm volatile("cp.async.wait_group %0;" :: "n"(N) : "memory");
}
__device__ __forceinline__ uint32_t s2u(const void* p) {
    return (uint32_t)__cvta_generic_to_shared(p);
}

// ---------------- small utility kernels ------------------------------------
__global__ void zero_stats_k() {
    int i = blockIdx.x * blockDim.x + threadIdx.x;
    if (i < 4*TCC) g_stats[i] = 0.f;
}

__global__ void zero_pads(float* __restrict__ a, float* __restrict__ b) {
    int idx = blockIdx.x * blockDim.x + threadIdx.x;
    if (idx >= Bb*TCC*8) return;
    int row = idx >> 3, j = idx & 7;
    size_t off = (size_t)row * LP + (j < 4 ? j * 4 : 528 + (j - 4) * 4);
    *(float4*)(a + off) = make_float4(0.f, 0.f, 0.f, 0.f);
    *(float4*)(b + off) = make_float4(0.f, 0.f, 0.f, 0.f);
}

__global__ void transpose_small(const float* __restrict__ in, float* __restrict__ out,
                                int R, int C) {
    int idx = blockIdx.x * blockDim.x + threadIdx.x;
    if (idx >= R * C) return;
    int r = idx / C, c = idx % C;
    out[(size_t)c * R + r] = in[idx];
}

// wt[(k*TC+ci)*TC + co] = rna(cw[(co*TC+ci)*5 + k])   [kk][co] layout, tf32 bits
__global__ void wtrans_conv(const float* __restrict__ cw, float* __restrict__ wt) {
    int idx = blockIdx.x * blockDim.x + threadIdx.x;
    if (idx >= TCC * TCC) return;
    int ci = idx / TCC;
    int co = idx % TCC;
    const float* src = cw + ((size_t)co * TCC + ci) * 5;
    unsigned* dst = (unsigned*)wt;
#pragma unroll
    for (int k = 0; k < 5; k++)
        dst[((size_t)k * TCC + ci) * TCC + co] = f2tf32(src[k]);
}

// ---------------- GCN stage 1 ------------------------------------------------
__global__ void gcn1_kernel(const float* __restrict__ x, const float* __restrict__ adj,
                            const float* __restrict__ eimp,
                            const float* __restrict__ w1, const float* __restrict__ b1,
                            const float* __restrict__ rw1, const float* __restrict__ rb1) {
    __shared__ float xs[NNODE*CIN];
    __shared__ float Asm[NNODE*NNODE];
    __shared__ float xts[NNODE*H1C];
    int bs = blockIdx.x;
    int tid = threadIdx.x;
    if (tid < NNODE*CIN) xs[tid] = x[(size_t)bs*NNODE*CIN + tid];
    if (tid >= 128 && tid < 128 + NNODE*NNODE) Asm[tid-128] = adj[tid-128] * eimp[tid-128];
    __syncthreads();
    for (int e = tid; e < NNODE*H1C; e += blockDim.x) {
        int n = e / H1C, c = e % H1C;
        float ws = b1[c], rs = rb1[c];
#pragma unroll
        for (int i = 0; i < CIN; i++) {
            float xv = xs[n*CIN + i];
            ws += xv * w1[c*CIN + i];
            rs += xv * rw1[c*CIN + i];
        }
        xts[e] = ws;
        g_res1[(size_t)bs*(NNODE*H1C) + e] = rs;
    }
    __syncthreads();
    for (int e = tid; e < NNODE*H1C; e += blockDim.x) {
        int n = e / H1C, c = e % H1C;
        float acc = 0.f;
#pragma unroll
        for (int m = 0; m < NNODE; m++) acc += Asm[n*NNODE + m] * xts[m*H1C + c];
        g_xc1[(size_t)bs*(NNODE*H1C) + e] = acc;
    }
}

__global__ void stats_rows(const float* __restrict__ a, const float* __restrict__ b,
                           int Mrows, int C) {
    int c = threadIdx.x;
    int rows_per = Mrows / gridDim.x;
    int r0 = blockIdx.x * rows_per;
    int r1 = r0 + rows_per;
    float sa = 0.f, qa = 0.f, sb = 0.f, qb = 0.f;
    for (int r = r0; r < r1; r++) {
        float v = a[(size_t)r*C + c]; sa += v; qa += v*v;
        float u = b[(size_t)r*C + c]; sb += u; qb += u*u;
    }
    atomicAdd(&g_stats[c],       sa);
    atomicAdd(&g_stats[C + c],   qa);
    atomicAdd(&g_stats[2*C + c], sb);
    atomicAdd(&g_stats[3*C + c], qb);
}

__global__ void bn_apply1(const float* __restrict__ g1, const float* __restrict__ beta1,
                          const float* __restrict__ rg1, const float* __restrict__ rbeta1) {
    size_t idx = (size_t)blockIdx.x * blockDim.x + threadIdx.x;
    if (idx >= (size_t)M1R*H1C) return;
    int c = (int)(idx % H1C);
    const float invM = 1.f / (float)M1R;
    float m1 = g_stats[c] * invM;
    float v1 = g_stats[H1C + c] * invM - m1*m1;
    float m2 = g_stats[2*H1C + c] * invM;
    float v2 = g_stats[3*H1C + c] * invM - m2*m2;
    float a = (g_xc1[idx]  - m1) * rsqrtf(v1 + BNEPS) * g1[c]  + beta1[c];
    float r = (g_res1[idx] - m2) * rsqrtf(v2 + BNEPS) * rg1[c] + rbeta1[c];
    float o = a + r;
    g_h1[idx] = o > 0.f ? o : 0.f;
}

// ---------------- generic fp32 SGEMM (small GCN GEMMs) ----------------------
__global__ __launch_bounds__(256) void sgemm_rowA(
        const float* __restrict__ A, const float* __restrict__ B,
        const float* __restrict__ bias, float* __restrict__ C,
        int M, int N, int K) {
    const int BK = 8;
    __shared__ float As[2][BK][128];
    __shared__ float Bs[2][BK][128];
    int tid = threadIdx.x;
    int bm = blockIdx.x * 128;
    int bn = blockIdx.y * 128;

    int arow = tid >> 1;
    int acol = (tid & 1) * 4;
    int brow = tid >> 5;
    int bcol = (tid & 31) * 4;
    int tx = tid & 15, ty = tid >> 4;

    float acc[8][8];
#pragma unroll
    for (int i = 0; i < 8; i++)
#pragma unroll
        for (int j = 0; j < 8; j++) acc[i][j] = 0.f;

    float4 aReg = *(const float4*)(A + (size_t)(bm + arow) * K + acol);
    float4 bReg = *(const float4*)(B + (size_t)brow * N + bn + bcol);
    As[0][acol+0][arow] = aReg.x; As[0][acol+1][arow] = aReg.y;
    As[0][acol+2][arow] = aReg.z; As[0][acol+3][arow] = aReg.w;
    *(float4*)&Bs[0][brow][bcol] = bReg;
    __syncthreads();

    int nt = K / BK, cur = 0;
    for (int t = 0; t < nt; ++t) {
        if (t + 1 < nt) {
            int k0 = (t + 1) * BK;
            aReg = *(const float4*)(A + (size_t)(bm + arow) * K + k0 + acol);
            bReg = *(const float4*)(B + (size_t)(k0 + brow) * N + bn + bcol);
        }
#pragma unroll
        for (int kk = 0; kk < BK; ++kk) {
            float4 a0 = *(const float4*)&As[cur][kk][ty*8];
            float4 a1 = *(const float4*)&As[cur][kk][ty*8+4];
            float4 b0 = *(const float4*)&Bs[cur][kk][tx*8];
            float4 b1 = *(const float4*)&Bs[cur][kk][tx*8+4];
            float av[8] = {a0.x,a0.y,a0.z,a0.w,a1.x,a1.y,a1.z,a1.w};
            float bv[8] = {b0.x,b0.y,b0.z,b0.w,b1.x,b1.y,b1.z,b1.w};
#pragma unroll
            for (int i = 0; i < 8; i++)
#pragma unroll
                for (int j = 0; j < 8; j++) acc[i][j] += av[i]*bv[j];
        }
        if (t + 1 < nt) {
            int nxt = cur ^ 1;
            As[nxt][acol+0][arow] = aReg.x; As[nxt][acol+1][arow] = aReg.y;
            As[nxt][acol+2][arow] = aReg.z; As[nxt][acol+3][arow] = aReg.w;
            *(float4*)&Bs[nxt][brow][bcol] = bReg;
        }
        __syncthreads();
        cur ^= 1;
    }
#pragma unroll
    for (int i = 0; i < 8; i++) {
        int m = bm + ty*8 + i;
        float* cp = C + (size_t)m * N + bn + tx*8;
#pragma unroll
        for (int j = 0; j < 8; j++) cp[j] = acc[i][j] + bias[bn + tx*8 + j];
    }
}

// ---------------- node mix for stage 2 --------------------------------------
__global__ void nodemix2(const float* __restrict__ adj, const float* __restrict__ eimp) {
    __shared__ float ys[NNODE*HHC];
    __shared__ float Asm[NNODE*NNODE];
    int bs = blockIdx.x, tid = threadIdx.x;
    if (tid < NNODE*NNODE) Asm[tid] = adj[tid] * eimp[tid];
    for (int e = tid; e < NNODE*HHC; e += blockDim.x)
        ys[e] = g_y2[(size_t)bs*NNODE*HHC + e];
    __syncthreads();
    for (int e = tid; e < NNODE*HHC; e += blockDim.x) {
        int n = e / HHC, c = e % HHC;
        float acc = 0.f;
#pragma unroll
        for (int m = 0; m < NNODE; m++) acc += Asm[n*NNODE + m] * ys[m*HHC + c];
        g_xc2[(size_t)bs*NNODE*HHC + e] = acc;
    }
}

// ---------------- BN apply stage 2 fused with transpose into padded [B,TC,LP]
__global__ void bn_apply2_transpose(const float* __restrict__ g2, const float* __restrict__ beta2,
                                    const float* __restrict__ rg2, const float* __restrict__ rbeta2) {
    __shared__ float tile[32][33];
    int s0 = blockIdx.x * 32, c0 = blockIdx.y * 32;
    int bn = blockIdx.z;
    int b = bn / NNODE, n = bn % NNODE;
    int tx = threadIdx.x, ty = threadIdx.y;
    const float invM = 1.f / (float)M1R;
    int c = c0 + tx;
    float m1 = g_stats[c] * invM;
    float v1 = g_stats[HHC + c] * invM - m1*m1;
    float m2 = g_stats[2*HHC + c] * invM;
    float v2 = g_stats[3*HHC + c] * invM - m2*m2;
    float sc1 = rsqrtf(v1 + BNEPS) * g2[c];
    float sh1 = beta2[c] - m1*sc1;
    float sc2 = rsqrtf(v2 + BNEPS) * rg2[c];
    float sh2 = rbeta2[c] - m2*sc2;
#pragma unroll
    for (int j = 0; j < 4; j++) {
        int s = s0 + ty + 8*j;
        size_t ridx = (((size_t)(b*Ss + s) * NNODE) + n) * HHC + c;
        float o = g_xc2[ridx]*sc1 + sh1 + g_res2[ridx]*sc2 + sh2;
        tile[ty + 8*j][tx] = o > 0.f ? o : 0.f;
    }
    __syncthreads();
#pragma unroll
    for (int j = 0; j < 4; j++) {
        int cc = c0 + ty + 8*j;
        int s  = s0 + tx;
        g_ht[((size_t)b*TCC + n*HHC + cc) * LP + OFFX + s] = tile[tx][ty + 8*j];
    }
}

// ======================= conv1d as tf32 mma GEMM, cp.async 3-stage ==========
// D[co, l] = sum_kk W[kk][co] * X[ci(kk)][l + kseg(kk) - 2]
// X is padded (stride LP, OFFX front pad) -> unconditional aligned 16B loads.
#define ASTR 136
#define BSTR 152
#define ASZ (16*ASTR*4)
#define BSZ (16*BSTR*4)
#define STG (ASZ + BSZ)
#define STAGES 3

__global__ __launch_bounds__(256, 2) void conv_gemm_tf32(
        const float* __restrict__ X, const float* __restrict__ Wt, float* __restrict__ Y) {
    extern __shared__ __align__(128) char dsm[];
    const int tid = threadIdx.x;
    const int bm = blockIdx.x * 128;   // co
    const int bn = blockIdx.y * 128;   // l
    const float* Xb = X + (size_t)blockIdx.z * TCC * LP;
    float* Yb = Y + (size_t)blockIdx.z * TCC * LP;
    const int lane = tid & 31, wid = tid >> 5;
    const int wm = (wid & 1) * 64, wn = (wid >> 1) * 32;
    const int g = lane >> 2, tg = lane & 3;

    const uint32_t smem_u = s2u(dsm);
    // A-load mapping: one (row, 8-col) chunk per thread
    const int arow = tid >> 4;
    const int acol = (tid & 15) * 8;

    float acc[4][4][4];
#pragma unroll
    for (int mi = 0; mi < 4; mi++)
#pragma unroll
        for (int ni = 0; ni < 4; ni++)
#pragma unroll
            for (int r = 0; r < 4; r++) acc[mi][ni][r] = 0.f;

    const int NT = RKK / 16;   // 480

    // stage loader
    auto load_stage = [&](int slot, int t) {
        const int kk0  = t * 16;
        const int kseg = kk0 / TCC;          // t / 96
        const int ci0  = kk0 - kseg * TCC;
        const uint32_t sa = smem_u + slot * STG;
        const uint32_t sb = sa + ASZ;
        // A: W tile [16 kk x 128 co], pre-rounded tf32 bits
        {
            const float* src = Wt + (size_t)(kk0 + arow) * TCC + bm + acol;
            uint32_t dst = sa + (arow * ASTR + acol) * 4;
            cpasync16(dst, src);
            cpasync16(dst + 16, src + 4);
        }
        // B: X tile [16 kk x 144 l], window [bn-4, bn+140) in logical l,
        //    i.e. padded columns [bn+12, bn+156)
#pragma unroll
        for (int i = tid; i < 576; i += 256) {
            int row = i / 36, ch = i % 36;
            const float* src = Xb + (size_t)(ci0 + row) * LP + 12 + bn + ch * 4;
            cpasync16(sb + (row * BSTR + ch * 4) * 4, src);
        }
    };

    // prologue: stages for tiles 0,1
    load_stage(0, 0); cpa_commit();
    load_stage(1, 1); cpa_commit();

    for (int t = 0; t < NT; ++t) {
        cpa_wait<STAGES - 2>();
        __syncthreads();
        // issue loads for t+2 into the slot consumed at iteration t-1
        if (t + 2 < NT) load_stage((t + 2) % STAGES, t + 2);
        cpa_commit();

        const int cur = t % STAGES;
        const float* As = (const float*)(dsm + cur * STG);
        const float* Bs = (const float*)(dsm + cur * STG + ASZ);
        const int kseg = (t * 16) / TCC;
        const int sh4  = kseg + 2;          // (kseg - 2) + 4

#pragma unroll
        for (int ks = 0; ks < 16; ks += 8) {
            unsigned a[4][4], b[4][2];
#pragma unroll
            for (int mi = 0; mi < 4; mi++) {
                int m = wm + mi * 16;
                a[mi][0] = __float_as_uint(As[(ks+tg  )*ASTR + m + g    ]);
                a[mi][1] = __float_as_uint(As[(ks+tg  )*ASTR + m + g + 8]);
                a[mi][2] = __float_as_uint(As[(ks+tg+4)*ASTR + m + g    ]);
                a[mi][3] = __float_as_uint(As[(ks+tg+4)*ASTR + m + g + 8]);
            }
#pragma unroll
            for (int ni = 0; ni < 4; ni++) {
                int c = sh4 + wn + ni * 8 + g;
                b[ni][0] = f2tf32(Bs[(ks+tg  )*BSTR + c]);
                b[ni][1] = f2tf32(Bs[(ks+tg+4)*BSTR + c]);
            }
#pragma unroll
            for (int mi = 0; mi < 4; mi++)
#pragma unroll
                for (int ni = 0; ni < 4; ni++)
                    MMA_TF32(acc[mi][ni], a[mi], b[ni]);
        }
        __syncthreads();
    }

#pragma unroll
    for (int mi = 0; mi < 4; mi++) {
        int m0 = bm + wm + mi * 16 + g;
#pragma unroll
        for (int ni = 0; ni < 4; ni++) {
            int l = bn + wn + ni * 8 + 2 * tg;
            *(float2*)(Yb + (size_t)m0 * LP + OFFX + l)
                = make_float2(acc[mi][ni][0], acc[mi][ni][1]);
            *(float2*)(Yb + (size_t)(m0+8) * LP + OFFX + l)
                = make_float2(acc[mi][ni][2], acc[mi][ni][3]);
        }
    }
}

// ---------------- conv BN stats / apply (padded layout) ---------------------
__global__ void conv_stats(const float* __restrict__ T) {
    int c = blockIdx.x;
    int tid = threadIdx.x;
    float s = 0.f, q = 0.f;
    for (int b = 0; b < Bb; b++) {
        const float* p = T + ((size_t)b * TCC + c) * LP + OFFX;
        for (int l = tid; l < LLEN; l += blockDim.x) {
            float v = p[l]; s += v; q += v*v;
        }
    }
    __shared__ float ss[256], qq[256];
    ss[tid] = s; qq[tid] = q;
    __syncthreads();
    for (int o = 128; o > 0; o >>= 1) {
        if (tid < o) { ss[tid] += ss[tid+o]; qq[tid] += qq[tid+o]; }
        __syncthreads();
    }
    if (tid == 0) { g_stats[c] = ss[0]; g_stats[TCC + c] = qq[0]; }
}

__global__ void conv_bn(float* __restrict__ T, const float* __restrict__ g,
                        const float* __restrict__ beta, const float* __restrict__ resid) {
    size_t idx = (size_t)blockIdx.x * blockDim.x + threadIdx.x;
    if (idx >= (size_t)Bb*TCC*LLEN) return;
    size_t row = idx / LLEN;
    int l = (int)(idx % LLEN);
    int c = (int)(row % TCC);
    size_t a = row * LP + OFFX + l;
    const float invM = 1.f / (float)(Bb * LLEN);
    float m = g_stats[c] * invM;
    float v = g_stats[TCC + c] * invM - m*m;
    float o = (T[a] - m) * rsqrtf(v + BNEPS) * g[c] + beta[c];
    o = o > 0.f ? o : 0.f;
    if (resid) o += resid[a];
    T[a] = o;
}

// ---------------- output GEMM (fp32, padded A stride) -----------------------
__global__ __launch_bounds__(256) void out_gemm(
        const float* __restrict__ T2, const float* __restrict__ Bw,
        const float* __restrict__ ob, float* __restrict__ out) {
    const int BK = 8;
    __shared__ float As[2][BK][128];
    __shared__ float Bs[2][BK][128];
    int tid = threadIdx.x;
    int bm = blockIdx.x * 128;   // s
    int bn = blockIdx.y * 128;   // o
    int b = blockIdx.z;
    const float* Ab = T2 + (size_t)b * TCC * LP + OFFX;

    int lrow = tid >> 5;
    int lcol = (tid & 31) * 4;
    int tx = tid & 15, ty = tid >> 4;

    float acc[8][8];
#pragma unroll
    for (int i = 0; i < 8; i++)
#pragma unroll
        for (int j = 0; j < 8; j++) acc[i][j] = 0.f;

    float4 aReg = *(const float4*)(Ab + (size_t)lrow * LP + bm + lcol);
    float4 bReg = *(const float4*)(Bw + (size_t)lrow * HHC + bn + lcol);
    *(float4*)&As[0][lrow][lcol] = aReg;
    *(float4*)&Bs[0][lrow][lcol] = bReg;
    __syncthreads();

    const int NT = TCC / BK;  // 192
    int cur = 0;
    for (int t = 0; t < NT; ++t) {
        if (t + 1 < NT) {
            int k0 = (t + 1) * BK;
            aReg = *(const float4*)(Ab + (size_t)(k0 + lrow) * LP + bm + lcol);
            bReg = *(const float4*)(Bw + (size_t)(k0 + lrow) * HHC + bn + lcol);
        }
#pragma unroll
        for (int kk = 0; kk < BK; ++kk) {
            float4 a0 = *(const float4*)&As[cur][kk][ty*8];
            float4 a1 = *(const float4*)&As[cur][kk][ty*8+4];
            float4 b0 = *(const float4*)&Bs[cur][kk][tx*8];
            float4 b1 = *(const float4*)&Bs[cur][kk][tx*8+4];
            float av[8] = {a0.x,a0.y,a0.z,a0.w,a1.x,a1.y,a1.z,a1.w};
            float bv[8] = {b0.x,b0.y,b0.z,b0.w,b1.x,b1.y,b1.z,b1.w};
#pragma unroll
            for (int i = 0; i < 8; i++)
#pragma unroll
                for (int j = 0; j < 8; j++) acc[i][j] += av[i]*bv[j];
        }
        if (t + 1 < NT) {
            int nxt = cur ^ 1;
            *(float4*)&As[nxt][lrow][lcol] = aReg;
            *(float4*)&Bs[nxt][lrow][lcol] = bReg;
        }
        __syncthreads();
        cur ^= 1;
    }
#pragma unroll
    for (int i = 0; i < 8; i++) {
        int s = bm + ty*8 + i;
        float* op = out + ((size_t)b * Ss + s) * HHC + bn + tx*8;
#pragma unroll
        for (int j = 0; j < 8; j++) {
            float v = acc[i][j] + ob[bn + tx*8 + j];
            op[j] = v > 0.f ? v : 0.f;
        }
    }
}

// ---------------- launch ----------------------------------------------------
extern "C" void kernel_launch(void* const* d_in, const int* in_sizes, int n_in,
                              void* d_out, int out_size) {
    const float* x     = (const float*)d_in[0];
    const float* adj   = (const float*)d_in[1];
    const float* eimp  = (const float*)d_in[2];
    const float* w1    = (const float*)d_in[3];
    const float* b1    = (const float*)d_in[4];
    const float* rw1   = (const float*)d_in[5];
    const float* rb1   = (const float*)d_in[6];
    const float* rg1   = (const float*)d_in[7];
    const float* rbeta1= (const float*)d_in[8];
    const float* g1    = (const float*)d_in[9];
    const float* beta1 = (const float*)d_in[10];
    const float* w2    = (const float*)d_in[11];
    const float* b2    = (const float*)d_in[12];
    const float* rw2   = (const float*)d_in[13];
    const float* rb2   = (const float*)d_in[14];
    const float* rg2   = (const float*)d_in[15];
    const float* rbeta2= (const float*)d_in[16];
    const float* g2    = (const float*)d_in[17];
    const float* beta2 = (const float*)d_in[18];
    const float* cw1   = (const float*)d_in[19];
    /* cb1 = d_in[20]: cancels exactly through BN mean-subtraction */
    const float* cg1   = (const float*)d_in[21];
    const float* cbeta1= (const float*)d_in[22];
    const float* cw2   = (const float*)d_in[23];
    /* cb2 = d_in[24]: cancels exactly */
    const float* cg2   = (const float*)d_in[25];
    const float* cbeta2= (const float*)d_in[26];
    const float* ow    = (const float*)d_in[27];
    const float* ob    = (const float*)d_in[28];
    float* out = (float*)d_out;

    float *p_xc1, *p_res1, *p_h1, *p_y2, *p_res2, *p_xc2, *p_ht, *p_t1, *p_t2;
    float *p_wt1, *p_wt2, *p_w2T, *p_rw2T, *p_owT;
    cudaGetSymbolAddress((void**)&p_xc1,  g_xc1);
    cudaGetSymbolAddress((void**)&p_res1, g_res1);
    cudaGetSymbolAddress((void**)&p_h1,   g_h1);
    cudaGetSymbolAddress((void**)&p_y2,   g_y2);
    cudaGetSymbolAddress((void**)&p_res2, g_res2);
    cudaGetSymbolAddress((void**)&p_xc2,  g_xc2);
    cudaGetSymbolAddress((void**)&p_ht,   g_ht);
    cudaGetSymbolAddress((void**)&p_t1,   g_t1);
    cudaGetSymbolAddress((void**)&p_t2,   g_t2);
    cudaGetSymbolAddress((void**)&p_wt1,  g_wt1);
    cudaGetSymbolAddress((void**)&p_wt2,  g_wt2);
    cudaGetSymbolAddress((void**)&p_w2T,  g_w2T);
    cudaGetSymbolAddress((void**)&p_rw2T, g_rw2T);
    cudaGetSymbolAddress((void**)&p_owT,  g_owT);

    cudaFuncSetAttribute(conv_gemm_tf32, cudaFuncAttributeMaxDynamicSharedMemorySize,
                         STAGES * STG);

    // -------- GCN stage 1 --------
    gcn1_kernel<<<NBS, 256>>>(x, adj, eimp, w1, b1, rw1, rb1);
    zero_stats_k<<<(4*TCC + 255)/256, 256>>>();
    zero_pads<<<(Bb*TCC*8 + 255)/256, 256>>>(p_ht, p_t1);
    stats_rows<<<256, H1C>>>(p_xc1, p_res1, M1R, H1C);
    bn_apply1<<<(M1R*H1C)/256, 256>>>(g1, beta1, rg1, rbeta1);

    // -------- GCN stage 2 --------
    transpose_small<<<(HHC*H1C + 255)/256, 256>>>(w2,  p_w2T,  HHC, H1C);
    transpose_small<<<(HHC*H1C + 255)/256, 256>>>(rw2, p_rw2T, HHC, H1C);
    sgemm_rowA<<<dim3(M1R/128, HHC/128), 256>>>(p_h1, p_w2T,  b2,  p_y2,   M1R, HHC, H1C);
    sgemm_rowA<<<dim3(M1R/128, HHC/128), 256>>>(p_h1, p_rw2T, rb2, p_res2, M1R, HHC, H1C);
    nodemix2<<<NBS, 256>>>(adj, eimp);
    zero_stats_k<<<(4*TCC + 255)/256, 256>>>();
    stats_rows<<<256, HHC>>>(p_xc2, p_res2, M1R, HHC);
    bn_apply2_transpose<<<dim3(Ss/32, HHC/32, Bb*NNODE), dim3(32, 8)>>>(g2, beta2, rg2, rbeta2);

    // -------- TCN conv 1 (tf32 mma + cp.async pipeline) --------
    wtrans_conv<<<(TCC*TCC + 255)/256, 256>>>(cw1, p_wt1);
    conv_gemm_tf32<<<dim3(TCC/128, LLEN/128, Bb), 256, STAGES*STG>>>(p_ht, p_wt1, p_t1);
    conv_stats<<<TCC, 256>>>(p_t1);
    conv_bn<<<(Bb*TCC*LLEN)/256, 256>>>(p_t1, cg1, cbeta1, (const float*)nullptr);

    // -------- TCN conv 2 + residual --------
    wtrans_conv<<<(TCC*TCC + 255)/256, 256>>>(cw2, p_wt2);
    conv_gemm_tf32<<<dim3(TCC/128, LLEN/128, Bb), 256, STAGES*STG>>>(p_t1, p_wt2, p_t2);
    conv_stats<<<TCC, 256>>>(p_t2);
    conv_bn<<<(Bb*TCC*LLEN)/256, 256>>>(p_t2, cg2, cbeta2, p_ht);

    // -------- output layer --------
    transpose_small<<<(HHC*TCC + 255)/256, 256>>>(ow, p_owT, HHC, TCC);
    out_gemm<<<dim3(LLEN/128, HHC/128, Bb), 256>>>(p_t2, p_owT, ob, out);

    (void)in_sizes; (void)n_in; (void)out_size;
}

// round 5
// speedup vs baseline: 3.4721x; 1.1481x over previous
#include <cuda_runtime.h>
#include <math.h>
#include <stdint.h>

#define Bb 32
#define Ss 512
#define NNODE 6
#define CIN 12
#define H1C 128
#define HHC 256
#define TCC 1536
#define LLEN 512
#define LP 544              /* padded row stride: 16 | 512 | 16 */
#define OFFX 16
#define M1R (Bb*Ss*NNODE)   /* 98304 */
#define NBS (Bb*Ss)         /* 16384 */
#define RKK (5*TCC)         /* 7680  */
#define BNEPS 1e-5f

// ---------------- scratch (device globals; no runtime allocation) ----------
__device__ float g_xc1 [M1R*H1C];
__device__ float g_res1[M1R*H1C];
__device__ float g_h1  [M1R*H1C];     // tf32-rounded at write
__device__ float g_y2  [M1R*HHC];
__device__ float g_res2[M1R*HHC];
__device__ float g_xc2 [M1R*HHC];
__device__ float g_ht  [Bb*TCC*LP];   // padded, fp32
__device__ float g_t1  [Bb*TCC*LP];   // padded, tf32-rounded after bn
__device__ float g_t2  [Bb*TCC*LP];   // padded, tf32-rounded after bn
__device__ float g_wt1 [RKK*TCC];     // [kk][co], tf32 bits
__device__ float g_wt2 [RKK*TCC];
__device__ float g_wB  [H1C*512];     // packed (w2T | rw2T), tf32 bits
__device__ float g_biasP[512];
__device__ float g_owR [TCC*HHC];     // ow transposed [c][o], tf32 bits
__device__ float g_stats[4*TCC];

// ---------------- helpers ----------------------------------------------------
__device__ __forceinline__ unsigned f2tf32(float f) {
    unsigned u; asm("cvt.rna.tf32.f32 %0, %1;" : "=r"(u) : "f"(f)); return u;
}
#define MMA_TF32(c, a, b) \
    asm volatile("mma.sync.aligned.m16n8k8.row.col.f32.tf32.tf32.f32 " \
        "{%0,%1,%2,%3}, {%4,%5,%6,%7}, {%8,%9}, {%0,%1,%2,%3};" \
        : "+f"((c)[0]), "+f"((c)[1]), "+f"((c)[2]), "+f"((c)[3]) \
        : "r"((a)[0]), "r"((a)[1]), "r"((a)[2]), "r"((a)[3]), \
          "r"((b)[0]), "r"((b)[1]))

__device__ __forceinline__ void cpasync16(uint32_t dst, const void* src) {
    asm volatile("cp.async.cg.shared.global [%0], [%1], 16;" :: "r"(dst), "l"(src));
}
__device__ __forceinline__ void cpa_commit() {
    asm volatile("cp.async.commit_group;" ::: "memory");
}
template<int N>
__device__ __forceinline__ void cpa_wait() {
    asm volatile("cp.async.wait_group %0;" :: "n"(N) : "memory");
}
__device__ __forceinline__ uint32_t s2u(const void* p) {
    return (uint32_t)__cvta_generic_to_shared(p);
}

// ---------------- small utility kernels ------------------------------------
__global__ void zero_stats_k() {
    int i = blockIdx.x * blockDim.x + threadIdx.x;
    if (i < 4*TCC) g_stats[i] = 0.f;
}

__global__ void zero_pads(float* __restrict__ a, float* __restrict__ b) {
    int idx = blockIdx.x * blockDim.x + threadIdx.x;
    if (idx >= Bb*TCC*8) return;
    int row = idx >> 3, j = idx & 7;
    size_t off = (size_t)row * LP + (j < 4 ? j * 4 : 528 + (j - 4) * 4);
    *(float4*)(a + off) = make_float4(0.f, 0.f, 0.f, 0.f);
    *(float4*)(b + off) = make_float4(0.f, 0.f, 0.f, 0.f);
}

// pack w2/rw2 into wB[i][0:256]=rna(w2[o][i]), wB[i][256:512]=rna(rw2[o][i])
__global__ void pack_gcn2(const float* __restrict__ w2, const float* __restrict__ rw2,
                          const float* __restrict__ b2, const float* __restrict__ rb2) {
    int idx = blockIdx.x * blockDim.x + threadIdx.x;
    if (idx >= H1C * HHC) return;
    int i = idx >> 8;         // 0..127
    int o = idx & 255;        // 0..255
    unsigned* wB = (unsigned*)g_wB;
    wB[i * 512 + o]       = f2tf32(w2[(size_t)o * H1C + i]);
    wB[i * 512 + 256 + o] = f2tf32(rw2[(size_t)o * H1C + i]);
    if (i == 0) { g_biasP[o] = b2[o]; g_biasP[256 + o] = rb2[o]; }
}

// owR[c][o] = rna(ow[o][c])
__global__ void pack_ow(const float* __restrict__ ow) {
    int idx = blockIdx.x * blockDim.x + threadIdx.x;
    if (idx >= TCC * HHC) return;
    int c = idx >> 8;
    int o = idx & 255;
    ((unsigned*)g_owR)[idx] = f2tf32(ow[(size_t)o * TCC + c]);
}

// tiled transpose: wt[(k*TCC+ci)*TCC+co] = rna(cw[(co*TCC+ci)*5+k])
__global__ void wtrans_conv(const float* __restrict__ cw, float* __restrict__ wt) {
    __shared__ float tile[5][32][33];
    int ci0 = blockIdx.x * 32, co0 = blockIdx.y * 32;
    int tx = threadIdx.x, ty = threadIdx.y;      // (32, 8)
#pragma unroll
    for (int j = 0; j < 4; j++) {
        int co = co0 + ty + 8*j;
        int ci = ci0 + tx;
        const float* src = cw + ((size_t)co * TCC + ci) * 5;
#pragma unroll
        for (int k = 0; k < 5; k++)
            tile[k][ty + 8*j][tx] = __uint_as_float(f2tf32(src[k]));
    }
    __syncthreads();
#pragma unroll
    for (int k = 0; k < 5; k++)
#pragma unroll
        for (int j = 0; j < 4; j++) {
            int ci = ci0 + ty + 8*j;
            int co = co0 + tx;
            wt[((size_t)k * TCC + ci) * TCC + co] = tile[k][tx][ty + 8*j];
        }
}

// ---------------- GCN stage 1 ------------------------------------------------
__global__ void gcn1_kernel(const float* __restrict__ x, const float* __restrict__ adj,
                            const float* __restrict__ eimp,
                            const float* __restrict__ w1, const float* __restrict__ b1,
                            const float* __restrict__ rw1, const float* __restrict__ rb1) {
    __shared__ float xs[NNODE*CIN];
    __shared__ float Asm[NNODE*NNODE];
    __shared__ float xts[NNODE*H1C];
    int bs = blockIdx.x;
    int tid = threadIdx.x;
    if (tid < NNODE*CIN) xs[tid] = x[(size_t)bs*NNODE*CIN + tid];
    if (tid >= 128 && tid < 128 + NNODE*NNODE) Asm[tid-128] = adj[tid-128] * eimp[tid-128];
    __syncthreads();
    for (int e = tid; e < NNODE*H1C; e += blockDim.x) {
        int n = e / H1C, c = e % H1C;
        float ws = b1[c], rs = rb1[c];
#pragma unroll
        for (int i = 0; i < CIN; i++) {
            float xv = xs[n*CIN + i];
            ws += xv * w1[c*CIN + i];
            rs += xv * rw1[c*CIN + i];
        }
        xts[e] = ws;
        g_res1[(size_t)bs*(NNODE*H1C) + e] = rs;
    }
    __syncthreads();
    for (int e = tid; e < NNODE*H1C; e += blockDim.x) {
        int n = e / H1C, c = e % H1C;
        float acc = 0.f;
#pragma unroll
        for (int m = 0; m < NNODE; m++) acc += Asm[n*NNODE + m] * xts[m*H1C + c];
        g_xc1[(size_t)bs*(NNODE*H1C) + e] = acc;
    }
}

__global__ void stats_rows(const float* __restrict__ a, const float* __restrict__ b,
                           int Mrows, int C) {
    int c = threadIdx.x;
    int rows_per = Mrows / gridDim.x;
    int r0 = blockIdx.x * rows_per;
    int r1 = r0 + rows_per;
    float sa = 0.f, qa = 0.f, sb = 0.f, qb = 0.f;
    for (int r = r0; r < r1; r++) {
        float v = a[(size_t)r*C + c]; sa += v; qa += v*v;
        float u = b[(size_t)r*C + c]; sb += u; qb += u*u;
    }
    atomicAdd(&g_stats[c],       sa);
    atomicAdd(&g_stats[C + c],   qa);
    atomicAdd(&g_stats[2*C + c], sb);
    atomicAdd(&g_stats[3*C + c], qb);
}

__global__ void bn_apply1(const float* __restrict__ g1, const float* __restrict__ beta1,
                          const float* __restrict__ rg1, const float* __restrict__ rbeta1) {
    size_t idx = (size_t)blockIdx.x * blockDim.x + threadIdx.x;
    if (idx >= (size_t)M1R*H1C) return;
    int c = (int)(idx % H1C);
    const float invM = 1.f / (float)M1R;
    float m1 = g_stats[c] * invM;
    float v1 = g_stats[H1C + c] * invM - m1*m1;
    float m2 = g_stats[2*H1C + c] * invM;
    float v2 = g_stats[3*H1C + c] * invM - m2*m2;
    float a = (g_xc1[idx]  - m1) * rsqrtf(v1 + BNEPS) * g1[c]  + beta1[c];
    float r = (g_res1[idx] - m2) * rsqrtf(v2 + BNEPS) * rg1[c] + rbeta1[c];
    float o = a + r;
    o = o > 0.f ? o : 0.f;
    g_h1[idx] = __uint_as_float(f2tf32(o));     // pre-rounded for tf32 gemm
}

// ---------------- gcn2 dual GEMM (tf32 mma): y2 = h1*w2T+b2, res2 = h1*rw2T+rb2
#define A2STR 20
#define B2STR 136
#define A2SZ (128*A2STR*4)
#define B2SZ (16*B2STR*4)
#define STG2 (A2SZ + B2SZ)

__global__ __launch_bounds__(256, 2) void gcn2_gemm_tf32() {
    extern __shared__ __align__(128) char dsm[];
    const int tid = threadIdx.x;
    const int bm = blockIdx.x * 128;
    const int by = blockIdx.y;            // 0,1: y2 cols; 2,3: res2 cols
    const int bn = by * 128;
    const int lane = tid & 31, wid = tid >> 5;
    const int wm = (wid & 1) * 64, wn = (wid >> 1) * 32;
    const int g = lane >> 2, tg = lane & 3;
    const uint32_t smem_u = s2u(dsm);
    const float* A = g_h1;

    float acc[4][4][4];
#pragma unroll
    for (int mi = 0; mi < 4; mi++)
#pragma unroll
        for (int ni = 0; ni < 4; ni++)
#pragma unroll
            for (int r = 0; r < 4; r++) acc[mi][ni][r] = 0.f;

    const int NT = H1C / 16;   // 8

    auto load_stage = [&](int slot, int t) {
        const int kk0 = t * 16;
        const uint32_t sa = smem_u + slot * STG2;
        const uint32_t sb = sa + A2SZ;
#pragma unroll
        for (int i = 0; i < 2; i++) {       // A [128 m][16 k], m-major
            int idx = tid + i * 256;
            int m = idx >> 2, kc = (idx & 3) * 4;
            cpasync16(sa + (m * A2STR + kc) * 4,
                      A + (size_t)(bm + m) * H1C + kk0 + kc);
        }
#pragma unroll
        for (int i = 0; i < 2; i++) {       // B [16 k][128 n]
            int idx = tid + i * 256;
            int row = idx >> 5, ch = idx & 31;
            cpasync16(sb + (row * B2STR + ch * 4) * 4,
                      g_wB + (size_t)(kk0 + row) * 512 + bn + ch * 4);
        }
    };
    load_stage(0, 0); cpa_commit();
    load_stage(1, 1); cpa_commit();

    for (int t = 0; t < NT; ++t) {
        cpa_wait<1>();
        __syncthreads();
        if (t + 2 < NT) load_stage((t + 2) % 3, t + 2);
        cpa_commit();
        const int cur = t % 3;
        const float* As = (const float*)(dsm + cur * STG2);
        const float* Bs = (const float*)(dsm + cur * STG2 + A2SZ);
#pragma unroll
        for (int ks = 0; ks < 16; ks += 8) {
            unsigned a[4][4], b[4][2];
#pragma unroll
            for (int mi = 0; mi < 4; mi++) {
                int m = wm + mi * 16 + g;
                a[mi][0] = __float_as_uint(As[(m    ) * A2STR + ks + tg]);
                a[mi][1] = __float_as_uint(As[(m + 8) * A2STR + ks + tg]);
                a[mi][2] = __float_as_uint(As[(m    ) * A2STR + ks + tg + 4]);
                a[mi][3] = __float_as_uint(As[(m + 8) * A2STR + ks + tg + 4]);
            }
#pragma unroll
            for (int ni = 0; ni < 4; ni++) {
                int c = wn + ni * 8 + g;
                b[ni][0] = __float_as_uint(Bs[(ks + tg    ) * B2STR + c]);
                b[ni][1] = __float_as_uint(Bs[(ks + tg + 4) * B2STR + c]);
            }
#pragma unroll
            for (int mi = 0; mi < 4; mi++)
#pragma unroll
                for (int ni = 0; ni < 4; ni++)
                    MMA_TF32(acc[mi][ni], a[mi], b[ni]);
        }
        __syncthreads();
    }

    float* tgt = (by < 2) ? g_y2 : g_res2;
    const int nb = (by & 1) * 128;
#pragma unroll
    for (int mi = 0; mi < 4; mi++) {
        int m0 = bm + wm + mi * 16 + g;
#pragma unroll
        for (int ni = 0; ni < 4; ni++) {
            int n = nb + wn + ni * 8 + 2 * tg;
            int pb = bn + wn + ni * 8 + 2 * tg;
            float b0 = g_biasP[pb], b1 = g_biasP[pb + 1];
            *(float2*)(tgt + (size_t)m0 * HHC + n)
                = make_float2(acc[mi][ni][0] + b0, acc[mi][ni][1] + b1);
            *(float2*)(tgt + (size_t)(m0 + 8) * HHC + n)
                = make_float2(acc[mi][ni][2] + b0, acc[mi][ni][3] + b1);
        }
    }
}

// ---------------- node mix for stage 2 --------------------------------------
__global__ void nodemix2(const float* __restrict__ adj, const float* __restrict__ eimp) {
    __shared__ float ys[NNODE*HHC];
    __shared__ float Asm[NNODE*NNODE];
    int bs = blockIdx.x, tid = threadIdx.x;
    if (tid < NNODE*NNODE) Asm[tid] = adj[tid] * eimp[tid];
    for (int e = tid; e < NNODE*HHC; e += blockDim.x)
        ys[e] = g_y2[(size_t)bs*NNODE*HHC + e];
    __syncthreads();
    for (int e = tid; e < NNODE*HHC; e += blockDim.x) {
        int n = e / HHC, c = e % HHC;
        float acc = 0.f;
#pragma unroll
        for (int m = 0; m < NNODE; m++) acc += Asm[n*NNODE + m] * ys[m*HHC + c];
        g_xc2[(size_t)bs*NNODE*HHC + e] = acc;
    }
}

// ---------------- BN apply stage 2 fused with transpose into padded [B,TC,LP]
__global__ void bn_apply2_transpose(const float* __restrict__ g2, const float* __restrict__ beta2,
                                    const float* __restrict__ rg2, const float* __restrict__ rbeta2) {
    __shared__ float tile[32][33];
    int s0 = blockIdx.x * 32, c0 = blockIdx.y * 32;
    int bn = blockIdx.z;
    int b = bn / NNODE, n = bn % NNODE;
    int tx = threadIdx.x, ty = threadIdx.y;
    const float invM = 1.f / (float)M1R;
    int c = c0 + tx;
    float m1 = g_stats[c] * invM;
    float v1 = g_stats[HHC + c] * invM - m1*m1;
    float m2 = g_stats[2*HHC + c] * invM;
    float v2 = g_stats[3*HHC + c] * invM - m2*m2;
    float sc1 = rsqrtf(v1 + BNEPS) * g2[c];
    float sh1 = beta2[c] - m1*sc1;
    float sc2 = rsqrtf(v2 + BNEPS) * rg2[c];
    float sh2 = rbeta2[c] - m2*sc2;
#pragma unroll
    for (int j = 0; j < 4; j++) {
        int s = s0 + ty + 8*j;
        size_t ridx = (((size_t)(b*Ss + s) * NNODE) + n) * HHC + c;
        float o = g_xc2[ridx]*sc1 + sh1 + g_res2[ridx]*sc2 + sh2;
        tile[ty + 8*j][tx] = o > 0.f ? o : 0.f;
    }
    __syncthreads();
#pragma unroll
    for (int j = 0; j < 4; j++) {
        int cc = c0 + ty + 8*j;
        int s  = s0 + tx;
        g_ht[((size_t)b*TCC + n*HHC + cc) * LP + OFFX + s] = tile[tx][ty + 8*j];
    }
}

// ======================= conv1d as tf32 mma GEMM, cp.async 3-stage ==========
// D[co, l] = sum_kk W[kk][co] * X[ci(kk)][l + kseg(kk) - 2]
// Epilogue folds per-channel sum/sumsq stats (atomicAdd into g_stats).
#define ASTR 136
#define BSTR 152
#define ASZ (16*ASTR*4)
#define BSZ (16*BSTR*4)
#define STG (ASZ + BSZ)
#define STAGES 3

template<bool CVT_B>
__global__ __launch_bounds__(256, 2) void conv_gemm_tf32(
        const float* __restrict__ X, const float* __restrict__ Wt, float* __restrict__ Y) {
    extern __shared__ __align__(128) char dsm[];
    const int tid = threadIdx.x;
    const int bm = blockIdx.x * 128;   // co
    const int bn = blockIdx.y * 128;   // l
    const float* Xb = X + (size_t)blockIdx.z * TCC * LP;
    float* Yb = Y + (size_t)blockIdx.z * TCC * LP;
    const int lane = tid & 31, wid = tid >> 5;
    const int wm = (wid & 1) * 64, wn = (wid >> 1) * 32;
    const int g = lane >> 2, tg = lane & 3;

    const uint32_t smem_u = s2u(dsm);
    const int arow = tid >> 4;
    const int acol = (tid & 15) * 8;

    float acc[4][4][4];
#pragma unroll
    for (int mi = 0; mi < 4; mi++)
#pragma unroll
        for (int ni = 0; ni < 4; ni++)
#pragma unroll
            for (int r = 0; r < 4; r++) acc[mi][ni][r] = 0.f;

    const int NT = RKK / 16;   // 480

    auto load_stage = [&](int slot, int t) {
        const int kk0  = t * 16;
        const int kseg = kk0 / TCC;
        const int ci0  = kk0 - kseg * TCC;
        const uint32_t sa = smem_u + slot * STG;
        const uint32_t sb = sa + ASZ;
        {
            const float* src = Wt + (size_t)(kk0 + arow) * TCC + bm + acol;
            uint32_t dst = sa + (arow * ASTR + acol) * 4;
            cpasync16(dst, src);
            cpasync16(dst + 16, src + 4);
        }
#pragma unroll
        for (int i = tid; i < 576; i += 256) {
            int row = i / 36, ch = i % 36;
            const float* src = Xb + (size_t)(ci0 + row) * LP + 12 + bn + ch * 4;
            cpasync16(sb + (row * BSTR + ch * 4) * 4, src);
        }
    };

    load_stage(0, 0); cpa_commit();
    load_stage(1, 1); cpa_commit();

    for (int t = 0; t < NT; ++t) {
        cpa_wait<STAGES - 2>();
        __syncthreads();
        if (t + 2 < NT) load_stage((t + 2) % STAGES, t + 2);
        cpa_commit();

        const int cur = t % STAGES;
        const float* As = (const float*)(dsm + cur * STG);
        const float* Bs = (const float*)(dsm + cur * STG + ASZ);
        const int kseg = (t * 16) / TCC;
        const int sh4  = kseg + 2;

#pragma unroll
        for (int ks = 0; ks < 16; ks += 8) {
            unsigned a[4][4], b[4][2];
#pragma unroll
            for (int mi = 0; mi < 4; mi++) {
                int m = wm + mi * 16;
                a[mi][0] = __float_as_uint(As[(ks+tg  )*ASTR + m + g    ]);
                a[mi][1] = __float_as_uint(As[(ks+tg  )*ASTR + m + g + 8]);
                a[mi][2] = __float_as_uint(As[(ks+tg+4)*ASTR + m + g    ]);
                a[mi][3] = __float_as_uint(As[(ks+tg+4)*ASTR + m + g + 8]);
            }
#pragma unroll
            for (int ni = 0; ni < 4; ni++) {
                int c = sh4 + wn + ni * 8 + g;
                if (CVT_B) {
                    b[ni][0] = f2tf32(Bs[(ks+tg  )*BSTR + c]);
                    b[ni][1] = f2tf32(Bs[(ks+tg+4)*BSTR + c]);
                } else {
                    b[ni][0] = __float_as_uint(Bs[(ks+tg  )*BSTR + c]);
                    b[ni][1] = __float_as_uint(Bs[(ks+tg+4)*BSTR + c]);
                }
            }
#pragma unroll
            for (int mi = 0; mi < 4; mi++)
#pragma unroll
                for (int ni = 0; ni < 4; ni++)
                    MMA_TF32(acc[mi][ni], a[mi], b[ni]);
        }
        __syncthreads();
    }

#pragma unroll
    for (int mi = 0; mi < 4; mi++) {
        int m0 = bm + wm + mi * 16 + g;
        float s0 = 0.f, q0 = 0.f, s1 = 0.f, q1 = 0.f;
#pragma unroll
        for (int ni = 0; ni < 4; ni++) {
            float v0 = acc[mi][ni][0], v1 = acc[mi][ni][1];
            float v2 = acc[mi][ni][2], v3 = acc[mi][ni][3];
            s0 += v0 + v1; q0 += v0*v0 + v1*v1;
            s1 += v2 + v3; q1 += v2*v2 + v3*v3;
            int l = bn + wn + ni * 8 + 2 * tg;
            *(float2*)(Yb + (size_t)m0 * LP + OFFX + l)     = make_float2(v0, v1);
            *(float2*)(Yb + (size_t)(m0+8) * LP + OFFX + l) = make_float2(v2, v3);
        }
        s0 += __shfl_xor_sync(0xffffffffu, s0, 1);
        s0 += __shfl_xor_sync(0xffffffffu, s0, 2);
        q0 += __shfl_xor_sync(0xffffffffu, q0, 1);
        q0 += __shfl_xor_sync(0xffffffffu, q0, 2);
        s1 += __shfl_xor_sync(0xffffffffu, s1, 1);
        s1 += __shfl_xor_sync(0xffffffffu, s1, 2);
        q1 += __shfl_xor_sync(0xffffffffu, q1, 1);
        q1 += __shfl_xor_sync(0xffffffffu, q1, 2);
        if (tg == 0) {
            atomicAdd(&g_stats[m0],         s0);
            atomicAdd(&g_stats[TCC + m0],   q0);
            atomicAdd(&g_stats[m0 + 8],     s1);
            atomicAdd(&g_stats[TCC + m0+8], q1);
        }
    }
}

// ---------------- conv BN apply (padded layout; writes tf32-rounded) --------
__global__ void conv_bn(float* __restrict__ T, const float* __restrict__ g,
                        const float* __restrict__ beta, const float* __restrict__ resid) {
    size_t idx = (size_t)blockIdx.x * blockDim.x + threadIdx.x;
    if (idx >= (size_t)Bb*TCC*LLEN) return;
    size_t row = idx / LLEN;
    int l = (int)(idx % LLEN);
    int c = (int)(row % TCC);
    size_t a = row * LP + OFFX + l;
    const float invM = 1.f / (float)(Bb * LLEN);
    float m = g_stats[c] * invM;
    float v = g_stats[TCC + c] * invM - m*m;
    float o = (T[a] - m) * rsqrtf(v + BNEPS) * g[c] + beta[c];
    o = o > 0.f ? o : 0.f;
    if (resid) o += resid[a];
    T[a] = __uint_as_float(f2tf32(o));
}

// ======================= output GEMM (tf32 mma) =============================
// D[o, s] = sum_c owR[c][o] * t2[b][c][s];  epilogue: +ob, relu, store [b,s,o]
#define AOSTR 136
#define AOSZ (16*AOSTR*4)
#define STGO (2*AOSZ)

__global__ __launch_bounds__(256, 2) void out_gemm_tf32(
        const float* __restrict__ T2, const float* __restrict__ OB,
        float* __restrict__ OUT) {
    extern __shared__ __align__(128) char dsm[];
    const int tid = threadIdx.x;
    const int bm = blockIdx.x * 128;   // o
    const int bn = blockIdx.y * 128;   // s
    const int b  = blockIdx.z;
    const float* T2b = T2 + (size_t)b * TCC * LP;
    const int lane = tid & 31, wid = tid >> 5;
    const int wm = (wid & 1) * 64, wn = (wid >> 1) * 32;
    const int g = lane >> 2, tg = lane & 3;
    const uint32_t smem_u = s2u(dsm);

    float acc[4][4][4];
#pragma unroll
    for (int mi = 0; mi < 4; mi++)
#pragma unroll
        for (int ni = 0; ni < 4; ni++)
#pragma unroll
            for (int r = 0; r < 4; r++) acc[mi][ni][r] = 0.f;

    const int NT = TCC / 16;   // 96

    auto load_stage = [&](int slot, int t) {
        const int kk0 = t * 16;
        const uint32_t sa = smem_u + slot * STGO;
        const uint32_t sb = sa + AOSZ;
#pragma unroll
        for (int i = 0; i < 2; i++) {       // A: owR [16 c][128 o]
            int idx = tid + i * 256;
            int row = idx >> 5, ch = idx & 31;
            cpasync16(sa + (row * AOSTR + ch * 4) * 4,
                      g_owR + (size_t)(kk0 + row) * HHC + bm + ch * 4);
        }
#pragma unroll
        for (int i = 0; i < 2; i++) {       // B: t2 [16 c][128 s]
            int idx = tid + i * 256;
            int row = idx >> 5, ch = idx & 31;
            cpasync16(sb + (row * AOSTR + ch * 4) * 4,
                      T2b + (size_t)(kk0 + row) * LP + OFFX + bn + ch * 4);
        }
    };
    load_stage(0, 0); cpa_commit();
    load_stage(1, 1); cpa_commit();

    for (int t = 0; t < NT; ++t) {
        cpa_wait<1>();
        __syncthreads();
        if (t + 2 < NT) load_stage((t + 2) % 3, t + 2);
        cpa_commit();
        const int cur = t % 3;
        const float* As = (const float*)(dsm + cur * STGO);
        const float* Bs = (const float*)(dsm + cur * STGO + AOSZ);
#pragma unroll
        for (int ks = 0; ks < 16; ks += 8) {
            unsigned a[4][4], b[4][2];
#pragma unroll
            for (int mi = 0; mi < 4; mi++) {
                int m = wm + mi * 16;
                a[mi][0] = __float_as_uint(As[(ks+tg  )*AOSTR + m + g    ]);
                a[mi][1] = __float_as_uint(As[(ks+tg  )*AOSTR + m + g + 8]);
                a[mi][2] = __float_as_uint(As[(ks+tg+4)*AOSTR + m + g    ]);
                a[mi][3] = __float_as_uint(As[(ks+tg+4)*AOSTR + m + g + 8]);
            }
#pragma unroll
            for (int ni = 0; ni < 4; ni++) {
                int c = wn + ni * 8 + g;
                b[ni][0] = __float_as_uint(Bs[(ks+tg  )*AOSTR + c]);
                b[ni][1] = __float_as_uint(Bs[(ks+tg+4)*AOSTR + c]);
            }
#pragma unroll
            for (int mi = 0; mi < 4; mi++)
#pragma unroll
                for (int ni = 0; ni < 4; ni++)
                    MMA_TF32(acc[mi][ni], a[mi], b[ni]);
        }
        __syncthreads();
    }

#pragma unroll
    for (int mi = 0; mi < 4; mi++) {
        int o0 = bm + wm + mi * 16 + g;
        float bo0 = OB[o0], bo1 = OB[o0 + 8];
#pragma unroll
        for (int ni = 0; ni < 4; ni++) {
            int sL = bn + wn + ni * 8 + 2 * tg;
            float v0 = acc[mi][ni][0] + bo0; v0 = v0 > 0.f ? v0 : 0.f;
            float v1 = acc[mi][ni][1] + bo0; v1 = v1 > 0.f ? v1 : 0.f;
            float v2 = acc[mi][ni][2] + bo1; v2 = v2 > 0.f ? v2 : 0.f;
            float v3 = acc[mi][ni][3] + bo1; v3 = v3 > 0.f ? v3 : 0.f;
            OUT[((size_t)b * Ss + sL    ) * HHC + o0    ] = v0;
            OUT[((size_t)b * Ss + sL + 1) * HHC + o0    ] = v1;
            OUT[((size_t)b * Ss + sL    ) * HHC + o0 + 8] = v2;
            OUT[((size_t)b * Ss + sL + 1) * HHC + o0 + 8] = v3;
        }
    }
}

// ---------------- launch ----------------------------------------------------
extern "C" void kernel_launch(void* const* d_in, const int* in_sizes, int n_in,
                              void* d_out, int out_size) {
    const float* x     = (const float*)d_in[0];
    const float* adj   = (const float*)d_in[1];
    const float* eimp  = (const float*)d_in[2];
    const float* w1    = (const float*)d_in[3];
    const float* b1    = (const float*)d_in[4];
    const float* rw1   = (const float*)d_in[5];
    const float* rb1   = (const float*)d_in[6];
    const float* rg1   = (const float*)d_in[7];
    const float* rbeta1= (const float*)d_in[8];
    const float* g1    = (const float*)d_in[9];
    const float* beta1 = (const float*)d_in[10];
    const float* w2    = (const float*)d_in[11];
    const float* b2    = (const float*)d_in[12];
    const float* rw2   = (const float*)d_in[13];
    const float* rb2   = (const float*)d_in[14];
    const float* rg2   = (const float*)d_in[15];
    const float* rbeta2= (const float*)d_in[16];
    const float* g2    = (const float*)d_in[17];
    const float* beta2 = (const float*)d_in[18];
    const float* cw1   = (const float*)d_in[19];
    /* cb1 = d_in[20]: cancels exactly through BN mean-subtraction */
    const float* cg1   = (const float*)d_in[21];
    const float* cbeta1= (const float*)d_in[22];
    const float* cw2   = (const float*)d_in[23];
    /* cb2 = d_in[24]: cancels exactly */
    const float* cg2   = (const float*)d_in[25];
    const float* cbeta2= (const float*)d_in[26];
    const float* ow    = (const float*)d_in[27];
    const float* ob    = (const float*)d_in[28];
    float* out = (float*)d_out;

    float *p_xc1, *p_res1, *p_xc2, *p_res2, *p_ht, *p_t1, *p_t2, *p_wt1, *p_wt2;
    cudaGetSymbolAddress((void**)&p_xc1,  g_xc1);
    cudaGetSymbolAddress((void**)&p_res1, g_res1);
    cudaGetSymbolAddress((void**)&p_xc2,  g_xc2);
    cudaGetSymbolAddress((void**)&p_res2, g_res2);
    cudaGetSymbolAddress((void**)&p_ht,   g_ht);
    cudaGetSymbolAddress((void**)&p_t1,   g_t1);
    cudaGetSymbolAddress((void**)&p_t2,   g_t2);
    cudaGetSymbolAddress((void**)&p_wt1,  g_wt1);
    cudaGetSymbolAddress((void**)&p_wt2,  g_wt2);

    cudaFuncSetAttribute(conv_gemm_tf32<true>,
                         cudaFuncAttributeMaxDynamicSharedMemorySize, STAGES * STG);
    cudaFuncSetAttribute(conv_gemm_tf32<false>,
                         cudaFuncAttributeMaxDynamicSharedMemorySize, STAGES * STG);
    cudaFuncSetAttribute(gcn2_gemm_tf32,
                         cudaFuncAttributeMaxDynamicSharedMemorySize, 3 * STG2);
    cudaFuncSetAttribute(out_gemm_tf32,
                         cudaFuncAttributeMaxDynamicSharedMemorySize, 3 * STGO);

    // -------- GCN stage 1 --------
    gcn1_kernel<<<NBS, 256>>>(x, adj, eimp, w1, b1, rw1, rb1);
    zero_stats_k<<<(4*TCC + 255)/256, 256>>>();
    zero_pads<<<(Bb*TCC*8 + 255)/256, 256>>>(p_ht, p_t1);
    pack_gcn2<<<(H1C*HHC + 255)/256, 256>>>(w2, rw2, b2, rb2);
    pack_ow<<<(TCC*HHC + 255)/256, 256>>>(ow);
    stats_rows<<<1024, H1C>>>(p_xc1, p_res1, M1R, H1C);
    bn_apply1<<<(M1R*H1C)/256, 256>>>(g1, beta1, rg1, rbeta1);

    // -------- GCN stage 2 (tf32 dual GEMM) --------
    gcn2_gemm_tf32<<<dim3(M1R/128, 4), 256, 3*STG2>>>();
    nodemix2<<<NBS, 256>>>(adj, eimp);
    zero_stats_k<<<(4*TCC + 255)/256, 256>>>();
    stats_rows<<<1024, HHC>>>(p_xc2, p_res2, M1R, HHC);
    bn_apply2_transpose<<<dim3(Ss/32, HHC/32, Bb*NNODE), dim3(32, 8)>>>(g2, beta2, rg2, rbeta2);

    // -------- TCN conv 1 (stats fused in epilogue) --------
    wtrans_conv<<<dim3(TCC/32, TCC/32), dim3(32, 8)>>>(cw1, p_wt1);
    zero_stats_k<<<(4*TCC + 255)/256, 256>>>();
    conv_gemm_tf32<true><<<dim3(TCC/128, LLEN/128, Bb), 256, STAGES*STG>>>(p_ht, p_wt1, p_t1);
    conv_bn<<<(Bb*TCC*LLEN)/256, 256>>>(p_t1, cg1, cbeta1, (const float*)nullptr);

    // -------- TCN conv 2 + residual (pre-rounded input, no in-loop cvt) ----
    wtrans_conv<<<dim3(TCC/32, TCC/32), dim3(32, 8)>>>(cw2, p_wt2);
    zero_stats_k<<<(4*TCC + 255)/256, 256>>>();
    conv_gemm_tf32<false><<<dim3(TCC/128, LLEN/128, Bb), 256, STAGES*STG>>>(p_t1, p_wt2, p_t2);
    conv_bn<<<(Bb*TCC*LLEN)/256, 256>>>(p_t2, cg2, cbeta2, p_ht);

    // -------- output layer (tf32) --------
    out_gemm_tf32<<<dim3(HHC/128, LLEN/128, Bb), 256, 3*STGO>>>(p_t2, ob, out);

    (void)in_sizes; (void)n_in; (void)out_size;
}

// round 6
// speedup vs baseline: 3.8053x; 1.0959x over previous
#include <cuda_runtime.h>
#include <math.h>
#include <stdint.h>

#define Bb 32
#define Ss 512
#define NNODE 6
#define CIN 12
#define H1C 128
#define HHC 256
#define TCC 1536
#define LLEN 512
#define LP 544              /* padded row stride: 16 | 512 | 16 */
#define OFFX 16
#define M1R (Bb*Ss*NNODE)   /* 98304 */
#define NBS (Bb*Ss)         /* 16384 */
#define RKK (5*TCC)         /* 7680  */
#define BNEPS 1e-5f

// ---------------- scratch (device globals; no runtime allocation) ----------
__device__ float g_xc1 [M1R*H1C];
__device__ float g_res1[M1R*H1C];
__device__ float g_h1  [M1R*H1C];     // tf32-rounded at write
__device__ float g_y2  [M1R*HHC];
__device__ float g_res2[M1R*HHC];
__device__ float g_xc2 [M1R*HHC];
__device__ float g_ht  [Bb*TCC*LP];   // padded, fp32
__device__ float g_t1  [Bb*TCC*LP];   // padded, tf32-rounded after bn
__device__ float g_t2  [Bb*TCC*LP];   // padded, tf32-rounded after bn
__device__ float g_wt1 [RKK*TCC];     // fragment-permuted tiles, tf32 bits
__device__ float g_wt2 [RKK*TCC];
__device__ float g_wB  [H1C*512];     // packed (w2T | rw2T), tf32 bits
__device__ float g_biasP[512];
__device__ float g_owR [TCC*HHC];     // fragment-permuted ow tiles, tf32 bits
__device__ float g_stats[4*TCC];

// ---------------- helpers ----------------------------------------------------
__device__ __forceinline__ unsigned f2tf32(float f) {
    unsigned u; asm("cvt.rna.tf32.f32 %0, %1;" : "=r"(u) : "f"(f)); return u;
}
#define MMA_TF32(c, a, b) \
    asm volatile("mma.sync.aligned.m16n8k8.row.col.f32.tf32.tf32.f32 " \
        "{%0,%1,%2,%3}, {%4,%5,%6,%7}, {%8,%9}, {%0,%1,%2,%3};" \
        : "+f"((c)[0]), "+f"((c)[1]), "+f"((c)[2]), "+f"((c)[3]) \
        : "r"((a)[0]), "r"((a)[1]), "r"((a)[2]), "r"((a)[3]), \
          "r"((b)[0]), "r"((b)[1]))

__device__ __forceinline__ void cpasync16(uint32_t dst, const void* src) {
    asm volatile("cp.async.cg.shared.global [%0], [%1], 16;" :: "r"(dst), "l"(src));
}
__device__ __forceinline__ void cpa_commit() {
    asm volatile("cp.async.commit_group;" ::: "memory");
}
template<int N>
__device__ __forceinline__ void cpa_wait() {
    asm volatile("cp.async.wait_group %0;" :: "n"(N) : "memory");
}
__device__ __forceinline__ uint32_t s2u(const void* p) {
    return (uint32_t)__cvta_generic_to_shared(p);
}

// ---------------- small utility kernels ------------------------------------
__global__ void zero_stats_k() {
    int i = blockIdx.x * blockDim.x + threadIdx.x;
    if (i < 4*TCC) g_stats[i] = 0.f;
}

__global__ void zero_pads(float* __restrict__ a, float* __restrict__ b) {
    int idx = blockIdx.x * blockDim.x + threadIdx.x;
    if (idx >= Bb*TCC*8) return;
    int row = idx >> 3, j = idx & 7;
    size_t off = (size_t)row * LP + (j < 4 ? j * 4 : 528 + (j - 4) * 4);
    *(float4*)(a + off) = make_float4(0.f, 0.f, 0.f, 0.f);
    *(float4*)(b + off) = make_float4(0.f, 0.f, 0.f, 0.f);
}

// pack w2/rw2 into wB[i][0:256]=rna(w2[o][i]), wB[i][256:512]=rna(rw2[o][i])
__global__ void pack_gcn2(const float* __restrict__ w2, const float* __restrict__ rw2,
                          const float* __restrict__ b2, const float* __restrict__ rb2) {
    int idx = blockIdx.x * blockDim.x + threadIdx.x;
    if (idx >= H1C * HHC) return;
    int i = idx >> 8;         // 0..127
    int o = idx & 255;        // 0..255
    unsigned* wB = (unsigned*)g_wB;
    wB[i * 512 + o]       = f2tf32(w2[(size_t)o * H1C + i]);
    wB[i * 512 + 256 + o] = f2tf32(rw2[(size_t)o * H1C + i]);
    if (i == 0) { g_biasP[o] = b2[o]; g_biasP[256 + o] = rb2[o]; }
}

// ---- fragment permutation: tile (tk over k16, cb over m128) stored as
//      pos = ((ks8*8 + mi)*32 + lane)*4 + q  holding
//      kk_loc = ks8*8 + (lane&3) + (q>>1)*4 ; m_loc = mi*16 + (lane>>2) + (q&1)*8

// conv weights: tiles over [RKK][TCC]; src cw[(co*TCC+ci)*5 + k]
__global__ void wtrans_conv(const float* __restrict__ cw, float* __restrict__ wt) {
    int tile = blockIdx.x;                    // tk*12 + cb
    int tk = tile / 12, cb = tile % 12;
    int k = (tk * 16) / TCC, ci0 = (tk * 16) % TCC;
    unsigned* dst = (unsigned*)wt + (size_t)tile * 2048 + threadIdx.x * 8;
#pragma unroll
    for (int u = 0; u < 8; u++) {
        int pos = threadIdx.x * 8 + u;
        int q = pos & 3, lp = (pos >> 2) & 31, mi = (pos >> 7) & 7, ks8 = pos >> 10;
        int ci = ci0 + ks8 * 8 + (lp & 3) + ((q >> 1) << 2);
        int co = cb * 128 + mi * 16 + (lp >> 2) + ((q & 1) << 3);
        dst[u] = f2tf32(cw[((size_t)co * TCC + ci) * 5 + k]);
    }
}

// output weights: tiles over [TCC][HHC]; src ow[o*TCC + c]
__global__ void pack_ow(const float* __restrict__ ow) {
    int tile = blockIdx.x;                    // tk*2 + cb
    int tk = tile >> 1, cb = tile & 1;
    unsigned* dst = (unsigned*)g_owR + (size_t)tile * 2048 + threadIdx.x * 8;
#pragma unroll
    for (int u = 0; u < 8; u++) {
        int pos = threadIdx.x * 8 + u;
        int q = pos & 3, lp = (pos >> 2) & 31, mi = (pos >> 7) & 7, ks8 = pos >> 10;
        int c = tk * 16 + ks8 * 8 + (lp & 3) + ((q >> 1) << 2);
        int o = cb * 128 + mi * 16 + (lp >> 2) + ((q & 1) << 3);
        dst[u] = f2tf32(ow[(size_t)o * TCC + c]);
    }
}

// ---------------- GCN stage 1 ------------------------------------------------
__global__ void gcn1_kernel(const float* __restrict__ x, const float* __restrict__ adj,
                            const float* __restrict__ eimp,
                            const float* __restrict__ w1, const float* __restrict__ b1,
                            const float* __restrict__ rw1, const float* __restrict__ rb1) {
    __shared__ float xs[NNODE*CIN];
    __shared__ float Asm[NNODE*NNODE];
    __shared__ float xts[NNODE*H1C];
    int bs = blockIdx.x;
    int tid = threadIdx.x;
    if (tid < NNODE*CIN) xs[tid] = x[(size_t)bs*NNODE*CIN + tid];
    if (tid >= 128 && tid < 128 + NNODE*NNODE) Asm[tid-128] = adj[tid-128] * eimp[tid-128];
    __syncthreads();
    for (int e = tid; e < NNODE*H1C; e += blockDim.x) {
        int n = e / H1C, c = e % H1C;
        float ws = b1[c], rs = rb1[c];
#pragma unroll
        for (int i = 0; i < CIN; i++) {
            float xv = xs[n*CIN + i];
            ws += xv * w1[c*CIN + i];
            rs += xv * rw1[c*CIN + i];
        }
        xts[e] = ws;
        g_res1[(size_t)bs*(NNODE*H1C) + e] = rs;
    }
    __syncthreads();
    for (int e = tid; e < NNODE*H1C; e += blockDim.x) {
        int n = e / H1C, c = e % H1C;
        float acc = 0.f;
#pragma unroll
        for (int m = 0; m < NNODE; m++) acc += Asm[n*NNODE + m] * xts[m*H1C + c];
        g_xc1[(size_t)bs*(NNODE*H1C) + e] = acc;
    }
}

__global__ void stats_rows(const float* __restrict__ a, const float* __restrict__ b,
                           int Mrows, int C) {
    int c = threadIdx.x;
    int rows_per = Mrows / gridDim.x;
    int r0 = blockIdx.x * rows_per;
    int r1 = r0 + rows_per;
    float sa = 0.f, qa = 0.f, sb = 0.f, qb = 0.f;
    for (int r = r0; r < r1; r++) {
        float v = a[(size_t)r*C + c]; sa += v; qa += v*v;
        float u = b[(size_t)r*C + c]; sb += u; qb += u*u;
    }
    atomicAdd(&g_stats[c],       sa);
    atomicAdd(&g_stats[C + c],   qa);
    atomicAdd(&g_stats[2*C + c], sb);
    atomicAdd(&g_stats[3*C + c], qb);
}

__global__ void bn_apply1(const float* __restrict__ g1, const float* __restrict__ beta1,
                          const float* __restrict__ rg1, const float* __restrict__ rbeta1) {
    size_t idx = (size_t)blockIdx.x * blockDim.x + threadIdx.x;
    if (idx >= (size_t)M1R*H1C) return;
    int c = (int)(idx % H1C);
    const float invM = 1.f / (float)M1R;
    float m1 = g_stats[c] * invM;
    float v1 = g_stats[H1C + c] * invM - m1*m1;
    float m2 = g_stats[2*H1C + c] * invM;
    float v2 = g_stats[3*H1C + c] * invM - m2*m2;
    float a = (g_xc1[idx]  - m1) * rsqrtf(v1 + BNEPS) * g1[c]  + beta1[c];
    float r = (g_res1[idx] - m2) * rsqrtf(v2 + BNEPS) * rg1[c] + rbeta1[c];
    float o = a + r;
    o = o > 0.f ? o : 0.f;
    g_h1[idx] = __uint_as_float(f2tf32(o));
}

// ---------------- gcn2 dual GEMM (tf32 mma) ---------------------------------
#define A2STR 20
#define B2STR 136
#define A2SZ (128*A2STR*4)
#define B2SZ (16*B2STR*4)
#define STG2 (A2SZ + B2SZ)

__global__ __launch_bounds__(256, 2) void gcn2_gemm_tf32() {
    extern __shared__ __align__(128) char dsm[];
    const int tid = threadIdx.x;
    const int bm = blockIdx.x * 128;
    const int by = blockIdx.y;
    const int bn = by * 128;
    const int lane = tid & 31, wid = tid >> 5;
    const int wm = (wid & 1) * 64, wn = (wid >> 1) * 32;
    const int g = lane >> 2, tg = lane & 3;
    const uint32_t smem_u = s2u(dsm);
    const float* A = g_h1;

    float acc[4][4][4];
#pragma unroll
    for (int mi = 0; mi < 4; mi++)
#pragma unroll
        for (int ni = 0; ni < 4; ni++)
#pragma unroll
            for (int r = 0; r < 4; r++) acc[mi][ni][r] = 0.f;

    const int NT = H1C / 16;   // 8

    auto load_stage = [&](int slot, int t) {
        const int kk0 = t * 16;
        const uint32_t sa = smem_u + slot * STG2;
        const uint32_t sb = sa + A2SZ;
#pragma unroll
        for (int i = 0; i < 2; i++) {
            int idx = tid + i * 256;
            int m = idx >> 2, kc = (idx & 3) * 4;
            cpasync16(sa + (m * A2STR + kc) * 4,
                      A + (size_t)(bm + m) * H1C + kk0 + kc);
        }
#pragma unroll
        for (int i = 0; i < 2; i++) {
            int idx = tid + i * 256;
            int row = idx >> 5, ch = idx & 31;
            cpasync16(sb + (row * B2STR + ch * 4) * 4,
                      g_wB + (size_t)(kk0 + row) * 512 + bn + ch * 4);
        }
    };
    load_stage(0, 0); cpa_commit();
    load_stage(1, 1); cpa_commit();

    for (int t = 0; t < NT; ++t) {
        cpa_wait<1>();
        __syncthreads();
        if (t + 2 < NT) load_stage((t + 2) % 3, t + 2);
        cpa_commit();
        const int cur = t % 3;
        const float* As = (const float*)(dsm + cur * STG2);
        const float* Bs = (const float*)(dsm + cur * STG2 + A2SZ);
#pragma unroll
        for (int ks = 0; ks < 16; ks += 8) {
            unsigned a[4][4], b[4][2];
#pragma unroll
            for (int mi = 0; mi < 4; mi++) {
                int m = wm + mi * 16 + g;
                a[mi][0] = __float_as_uint(As[(m    ) * A2STR + ks + tg]);
                a[mi][1] = __float_as_uint(As[(m + 8) * A2STR + ks + tg]);
                a[mi][2] = __float_as_uint(As[(m    ) * A2STR + ks + tg + 4]);
                a[mi][3] = __float_as_uint(As[(m + 8) * A2STR + ks + tg + 4]);
            }
#pragma unroll
            for (int ni = 0; ni < 4; ni++) {
                int c = wn + ni * 8 + g;
                b[ni][0] = __float_as_uint(Bs[(ks + tg    ) * B2STR + c]);
                b[ni][1] = __float_as_uint(Bs[(ks + tg + 4) * B2STR + c]);
            }
#pragma unroll
            for (int mi = 0; mi < 4; mi++)
#pragma unroll
                for (int ni = 0; ni < 4; ni++)
                    MMA_TF32(acc[mi][ni], a[mi], b[ni]);
        }
        __syncthreads();
    }

    float* tgt = (by < 2) ? g_y2 : g_res2;
    const int nb = (by & 1) * 128;
#pragma unroll
    for (int mi = 0; mi < 4; mi++) {
        int m0 = bm + wm + mi * 16 + g;
#pragma unroll
        for (int ni = 0; ni < 4; ni++) {
            int n = nb + wn + ni * 8 + 2 * tg;
            int pb = bn + wn + ni * 8 + 2 * tg;
            float b0 = g_biasP[pb], b1 = g_biasP[pb + 1];
            *(float2*)(tgt + (size_t)m0 * HHC + n)
                = make_float2(acc[mi][ni][0] + b0, acc[mi][ni][1] + b1);
            *(float2*)(tgt + (size_t)(m0 + 8) * HHC + n)
                = make_float2(acc[mi][ni][2] + b0, acc[mi][ni][3] + b1);
        }
    }
}

// ---------------- node mix for stage 2 --------------------------------------
__global__ void nodemix2(const float* __restrict__ adj, const float* __restrict__ eimp) {
    __shared__ float ys[NNODE*HHC];
    __shared__ float Asm[NNODE*NNODE];
    int bs = blockIdx.x, tid = threadIdx.x;
    if (tid < NNODE*NNODE) Asm[tid] = adj[tid] * eimp[tid];
    for (int e = tid; e < NNODE*HHC; e += blockDim.x)
        ys[e] = g_y2[(size_t)bs*NNODE*HHC + e];
    __syncthreads();
    for (int e = tid; e < NNODE*HHC; e += blockDim.x) {
        int n = e / HHC, c = e % HHC;
        float acc = 0.f;
#pragma unroll
        for (int m = 0; m < NNODE; m++) acc += Asm[n*NNODE + m] * ys[m*HHC + c];
        g_xc2[(size_t)bs*NNODE*HHC + e] = acc;
    }
}

// ---------------- BN apply stage 2 fused with transpose into padded [B,TC,LP]
__global__ void bn_apply2_transpose(const float* __restrict__ g2, const float* __restrict__ beta2,
                                    const float* __restrict__ rg2, const float* __restrict__ rbeta2) {
    __shared__ float tile[32][33];
    int s0 = blockIdx.x * 32, c0 = blockIdx.y * 32;
    int bn = blockIdx.z;
    int b = bn / NNODE, n = bn % NNODE;
    int tx = threadIdx.x, ty = threadIdx.y;
    const float invM = 1.f / (float)M1R;
    int c = c0 + tx;
    float m1 = g_stats[c] * invM;
    float v1 = g_stats[HHC + c] * invM - m1*m1;
    float m2 = g_stats[2*HHC + c] * invM;
    float v2 = g_stats[3*HHC + c] * invM - m2*m2;
    float sc1 = rsqrtf(v1 + BNEPS) * g2[c];
    float sh1 = beta2[c] - m1*sc1;
    float sc2 = rsqrtf(v2 + BNEPS) * rg2[c];
    float sh2 = rbeta2[c] - m2*sc2;
#pragma unroll
    for (int j = 0; j < 4; j++) {
        int s = s0 + ty + 8*j;
        size_t ridx = (((size_t)(b*Ss + s) * NNODE) + n) * HHC + c;
        float o = g_xc2[ridx]*sc1 + sh1 + g_res2[ridx]*sc2 + sh2;
        tile[ty + 8*j][tx] = o > 0.f ? o : 0.f;
    }
    __syncthreads();
#pragma unroll
    for (int j = 0; j < 4; j++) {
        int cc = c0 + ty + 8*j;
        int s  = s0 + tx;
        g_ht[((size_t)b*TCC + n*HHC + cc) * LP + OFFX + s] = tile[tx][ty + 8*j];
    }
}

// ======================= conv1d tf32 mma GEMM, 4-stage cp.async =============
// A operand is fragment-permuted in global -> LDS.128 fragment loads.
#define ASZ 8192
#define BSTR 152
#define BSZ (16*BSTR*4)
#define STG (ASZ + BSZ)
#define STAGES 4

template<bool CVT_B>
__global__ __launch_bounds__(256, 2) void conv_gemm_tf32(
        const float* __restrict__ X, const float* __restrict__ Wt, float* __restrict__ Y) {
    extern __shared__ __align__(128) char dsm[];
    const int tid = threadIdx.x;
    const int cb = blockIdx.x;
    const int bm = cb * 128;           // co
    const int bn = blockIdx.y * 128;   // l
    const float* Xb = X + (size_t)blockIdx.z * TCC * LP;
    float* Yb = Y + (size_t)blockIdx.z * TCC * LP;
    const int lane = tid & 31, wid = tid >> 5;
    const int wm = (wid & 1) * 64, wn = (wid >> 1) * 32;
    const int g = lane >> 2, tg = lane & 3;
    const int aoff = (wid & 1) * 4;

    const uint32_t smem_u = s2u(dsm);

    float acc[4][4][4];
#pragma unroll
    for (int mi = 0; mi < 4; mi++)
#pragma unroll
        for (int ni = 0; ni < 4; ni++)
#pragma unroll
            for (int r = 0; r < 4; r++) acc[mi][ni][r] = 0.f;

    const int NT = RKK / 16;   // 480

    auto load_stage = [&](int slot, int t) {
        const int kk0  = t * 16;
        const int kseg = kk0 / TCC;
        const int ci0  = kk0 - kseg * TCC;
        const uint32_t sa = smem_u + slot * STG;
        const uint32_t sb = sa + ASZ;
        {   // A: permuted weight tile, straight 8KB copy
            const float* src = Wt + ((size_t)t * 12 + cb) * 2048 + tid * 8;
            cpasync16(sa + tid * 32, src);
            cpasync16(sa + tid * 32 + 16, src + 4);
        }
#pragma unroll
        for (int i = tid; i < 576; i += 256) {
            int row = i / 36, ch = i % 36;
            const float* src = Xb + (size_t)(ci0 + row) * LP + 12 + bn + ch * 4;
            cpasync16(sb + (row * BSTR + ch * 4) * 4, src);
        }
    };

    load_stage(0, 0); cpa_commit();
    load_stage(1, 1); cpa_commit();
    load_stage(2, 2); cpa_commit();

    for (int t = 0; t < NT; ++t) {
        cpa_wait<STAGES - 2>();
        __syncthreads();
        if (t + 3 < NT) load_stage((t + 3) % STAGES, t + 3);
        cpa_commit();

        const int cur = t % STAGES;
        const float4* Af = (const float4*)(dsm + cur * STG);
        const float* Bs = (const float*)(dsm + cur * STG + ASZ);
        const int kseg = (t * 16) / TCC;
        const int sh4  = kseg + 2;

#pragma unroll
        for (int ks8 = 0; ks8 < 2; ks8++) {
            const int ks = ks8 * 8;
            unsigned a[4][4], b[4][2];
#pragma unroll
            for (int mi = 0; mi < 4; mi++) {
                float4 v = Af[(ks8 * 8 + aoff + mi) * 32 + lane];
                a[mi][0] = __float_as_uint(v.x);
                a[mi][1] = __float_as_uint(v.y);
                a[mi][2] = __float_as_uint(v.z);
                a[mi][3] = __float_as_uint(v.w);
            }
#pragma unroll
            for (int ni = 0; ni < 4; ni++) {
                int c = sh4 + wn + ni * 8 + g;
                if (CVT_B) {
                    b[ni][0] = f2tf32(Bs[(ks+tg  )*BSTR + c]);
                    b[ni][1] = f2tf32(Bs[(ks+tg+4)*BSTR + c]);
                } else {
                    b[ni][0] = __float_as_uint(Bs[(ks+tg  )*BSTR + c]);
                    b[ni][1] = __float_as_uint(Bs[(ks+tg+4)*BSTR + c]);
                }
            }
#pragma unroll
            for (int mi = 0; mi < 4; mi++)
#pragma unroll
                for (int ni = 0; ni < 4; ni++)
                    MMA_TF32(acc[mi][ni], a[mi], b[ni]);
        }
        __syncthreads();
    }

#pragma unroll
    for (int mi = 0; mi < 4; mi++) {
        int m0 = bm + wm + mi * 16 + g;
        float s0 = 0.f, q0 = 0.f, s1 = 0.f, q1 = 0.f;
#pragma unroll
        for (int ni = 0; ni < 4; ni++) {
            float v0 = acc[mi][ni][0], v1 = acc[mi][ni][1];
            float v2 = acc[mi][ni][2], v3 = acc[mi][ni][3];
            s0 += v0 + v1; q0 += v0*v0 + v1*v1;
            s1 += v2 + v3; q1 += v2*v2 + v3*v3;
            int l = bn + wn + ni * 8 + 2 * tg;
            *(float2*)(Yb + (size_t)m0 * LP + OFFX + l)     = make_float2(v0, v1);
            *(float2*)(Yb + (size_t)(m0+8) * LP + OFFX + l) = make_float2(v2, v3);
        }
        s0 += __shfl_xor_sync(0xffffffffu, s0, 1);
        s0 += __shfl_xor_sync(0xffffffffu, s0, 2);
        q0 += __shfl_xor_sync(0xffffffffu, q0, 1);
        q0 += __shfl_xor_sync(0xffffffffu, q0, 2);
        s1 += __shfl_xor_sync(0xffffffffu, s1, 1);
        s1 += __shfl_xor_sync(0xffffffffu, s1, 2);
        q1 += __shfl_xor_sync(0xffffffffu, q1, 1);
        q1 += __shfl_xor_sync(0xffffffffu, q1, 2);
        if (tg == 0) {
            atomicAdd(&g_stats[m0],         s0);
            atomicAdd(&g_stats[TCC + m0],   q0);
            atomicAdd(&g_stats[m0 + 8],     s1);
            atomicAdd(&g_stats[TCC + m0+8], q1);
        }
    }
}

// ---------------- conv BN apply (padded layout; writes tf32-rounded) --------
__global__ void conv_bn(float* __restrict__ T, const float* __restrict__ g,
                        const float* __restrict__ beta, const float* __restrict__ resid) {
    size_t idx = (size_t)blockIdx.x * blockDim.x + threadIdx.x;
    if (idx >= (size_t)Bb*TCC*LLEN) return;
    size_t row = idx / LLEN;
    int l = (int)(idx % LLEN);
    int c = (int)(row % TCC);
    size_t a = row * LP + OFFX + l;
    const float invM = 1.f / (float)(Bb * LLEN);
    float m = g_stats[c] * invM;
    float v = g_stats[TCC + c] * invM - m*m;
    float o = (T[a] - m) * rsqrtf(v + BNEPS) * g[c] + beta[c];
    o = o > 0.f ? o : 0.f;
    if (resid) o += resid[a];
    T[a] = __uint_as_float(f2tf32(o));
}

// ======================= output GEMM (tf32 mma, permuted A) =================
#define BOSTR 136
#define BOSZ (16*BOSTR*4)
#define STGO (ASZ + BOSZ)

__global__ __launch_bounds__(256, 2) void out_gemm_tf32(
        const float* __restrict__ T2, const float* __restrict__ OB,
        float* __restrict__ OUT) {
    extern __shared__ __align__(128) char dsm[];
    const int tid = threadIdx.x;
    const int cb = blockIdx.x;
    const int bm = cb * 128;           // o
    const int bn = blockIdx.y * 128;   // s
    const int b  = blockIdx.z;
    const float* T2b = T2 + (size_t)b * TCC * LP;
    const int lane = tid & 31, wid = tid >> 5;
    const int wm = (wid & 1) * 64, wn = (wid >> 1) * 32;
    const int g = lane >> 2, tg = lane & 3;
    const int aoff = (wid & 1) * 4;
    const uint32_t smem_u = s2u(dsm);

    float acc[4][4][4];
#pragma unroll
    for (int mi = 0; mi < 4; mi++)
#pragma unroll
        for (int ni = 0; ni < 4; ni++)
#pragma unroll
            for (int r = 0; r < 4; r++) acc[mi][ni][r] = 0.f;

    const int NT = TCC / 16;   // 96

    auto load_stage = [&](int slot, int t) {
        const int kk0 = t * 16;
        const uint32_t sa = smem_u + slot * STGO;
        const uint32_t sb = sa + ASZ;
        {
            const float* src = g_owR + ((size_t)t * 2 + cb) * 2048 + tid * 8;
            cpasync16(sa + tid * 32, src);
            cpasync16(sa + tid * 32 + 16, src + 4);
        }
#pragma unroll
        for (int i = 0; i < 2; i++) {
            int idx = tid + i * 256;
            int row = idx >> 5, ch = idx & 31;
            cpasync16(sb + (row * BOSTR + ch * 4) * 4,
                      T2b + (size_t)(kk0 + row) * LP + OFFX + bn + ch * 4);
        }
    };
    load_stage(0, 0); cpa_commit();
    load_stage(1, 1); cpa_commit();

    for (int t = 0; t < NT; ++t) {
        cpa_wait<1>();
        __syncthreads();
        if (t + 2 < NT) load_stage((t + 2) % 3, t + 2);
        cpa_commit();
        const int cur = t % 3;
        const float4* Af = (const float4*)(dsm + cur * STGO);
        const float* Bs = (const float*)(dsm + cur * STGO + ASZ);
#pragma unroll
        for (int ks8 = 0; ks8 < 2; ks8++) {
            const int ks = ks8 * 8;
            unsigned a[4][4], b[4][2];
#pragma unroll
            for (int mi = 0; mi < 4; mi++) {
                float4 v = Af[(ks8 * 8 + aoff + mi) * 32 + lane];
                a[mi][0] = __float_as_uint(v.x);
                a[mi][1] = __float_as_uint(v.y);
                a[mi][2] = __float_as_uint(v.z);
                a[mi][3] = __float_as_uint(v.w);
            }
#pragma unroll
            for (int ni = 0; ni < 4; ni++) {
                int c = wn + ni * 8 + g;
                b[ni][0] = __float_as_uint(Bs[(ks+tg  )*BOSTR + c]);
                b[ni][1] = __float_as_uint(Bs[(ks+tg+4)*BOSTR + c]);
            }
#pragma unroll
            for (int mi = 0; mi < 4; mi++)
#pragma unroll
                for (int ni = 0; ni < 4; ni++)
                    MMA_TF32(acc[mi][ni], a[mi], b[ni]);
        }
        __syncthreads();
    }

#pragma unroll
    for (int mi = 0; mi < 4; mi++) {
        int o0 = bm + wm + mi * 16 + g;
        float bo0 = OB[o0], bo1 = OB[o0 + 8];
#pragma unroll
        for (int ni = 0; ni < 4; ni++) {
            int sL = bn + wn + ni * 8 + 2 * tg;
            float v0 = acc[mi][ni][0] + bo0; v0 = v0 > 0.f ? v0 : 0.f;
            float v1 = acc[mi][ni][1] + bo0; v1 = v1 > 0.f ? v1 : 0.f;
            float v2 = acc[mi][ni][2] + bo1; v2 = v2 > 0.f ? v2 : 0.f;
            float v3 = acc[mi][ni][3] + bo1; v3 = v3 > 0.f ? v3 : 0.f;
            OUT[((size_t)b * Ss + sL    ) * HHC + o0    ] = v0;
            OUT[((size_t)b * Ss + sL + 1) * HHC + o0    ] = v1;
            OUT[((size_t)b * Ss + sL    ) * HHC + o0 + 8] = v2;
            OUT[((size_t)b * Ss + sL + 1) * HHC + o0 + 8] = v3;
        }
    }
}

// ---------------- launch ----------------------------------------------------
extern "C" void kernel_launch(void* const* d_in, const int* in_sizes, int n_in,
                              void* d_out, int out_size) {
    const float* x     = (const float*)d_in[0];
    const float* adj   = (const float*)d_in[1];
    const float* eimp  = (const float*)d_in[2];
    const float* w1    = (const float*)d_in[3];
    const float* b1    = (const float*)d_in[4];
    const float* rw1   = (const float*)d_in[5];
    const float* rb1   = (const float*)d_in[6];
    const float* rg1   = (const float*)d_in[7];
    const float* rbeta1= (const float*)d_in[8];
    const float* g1    = (const float*)d_in[9];
    const float* beta1 = (const float*)d_in[10];
    const float* w2    = (const float*)d_in[11];
    const float* b2    = (const float*)d_in[12];
    const float* rw2   = (const float*)d_in[13];
    const float* rb2   = (const float*)d_in[14];
    const float* rg2   = (const float*)d_in[15];
    const float* rbeta2= (const float*)d_in[16];
    const float* g2    = (const float*)d_in[17];
    const float* beta2 = (const float*)d_in[18];
    const float* cw1   = (const float*)d_in[19];
    /* cb1 = d_in[20]: cancels exactly through BN mean-subtraction */
    const float* cg1   = (const float*)d_in[21];
    const float* cbeta1= (const float*)d_in[22];
    const float* cw2   = (const float*)d_in[23];
    /* cb2 = d_in[24]: cancels exactly */
    const float* cg2   = (const float*)d_in[25];
    const float* cbeta2= (const float*)d_in[26];
    const float* ow    = (const float*)d_in[27];
    const float* ob    = (const float*)d_in[28];
    float* out = (float*)d_out;

    float *p_xc1, *p_res1, *p_xc2, *p_res2, *p_ht, *p_t1, *p_t2, *p_wt1, *p_wt2;
    cudaGetSymbolAddress((void**)&p_xc1,  g_xc1);
    cudaGetSymbolAddress((void**)&p_res1, g_res1);
    cudaGetSymbolAddress((void**)&p_xc2,  g_xc2);
    cudaGetSymbolAddress((void**)&p_res2, g_res2);
    cudaGetSymbolAddress((void**)&p_ht,   g_ht);
    cudaGetSymbolAddress((void**)&p_t1,   g_t1);
    cudaGetSymbolAddress((void**)&p_t2,   g_t2);
    cudaGetSymbolAddress((void**)&p_wt1,  g_wt1);
    cudaGetSymbolAddress((void**)&p_wt2,  g_wt2);

    cudaFuncSetAttribute(conv_gemm_tf32<true>,
                         cudaFuncAttributeMaxDynamicSharedMemorySize, STAGES * STG);
    cudaFuncSetAttribute(conv_gemm_tf32<false>,
                         cudaFuncAttributeMaxDynamicSharedMemorySize, STAGES * STG);
    cudaFuncSetAttribute(gcn2_gemm_tf32,
                         cudaFuncAttributeMaxDynamicSharedMemorySize, 3 * STG2);
    cudaFuncSetAttribute(out_gemm_tf32,
                         cudaFuncAttributeMaxDynamicSharedMemorySize, 3 * STGO);

    // -------- GCN stage 1 --------
    gcn1_kernel<<<NBS, 256>>>(x, adj, eimp, w1, b1, rw1, rb1);
    zero_stats_k<<<(4*TCC + 255)/256, 256>>>();
    zero_pads<<<(Bb*TCC*8 + 255)/256, 256>>>(p_ht, p_t1);
    pack_gcn2<<<(H1C*HHC + 255)/256, 256>>>(w2, rw2, b2, rb2);
    pack_ow<<<(TCC*HHC)/2048, 256>>>(ow);
    stats_rows<<<1024, H1C>>>(p_xc1, p_res1, M1R, H1C);
    bn_apply1<<<(M1R*H1C)/256, 256>>>(g1, beta1, rg1, rbeta1);

    // -------- GCN stage 2 (tf32 dual GEMM) --------
    gcn2_gemm_tf32<<<dim3(M1R/128, 4), 256, 3*STG2>>>();
    nodemix2<<<NBS, 256>>>(adj, eimp);
    zero_stats_k<<<(4*TCC + 255)/256, 256>>>();
    stats_rows<<<1024, HHC>>>(p_xc2, p_res2, M1R, HHC);
    bn_apply2_transpose<<<dim3(Ss/32, HHC/32, Bb*NNODE), dim3(32, 8)>>>(g2, beta2, rg2, rbeta2);

    // -------- TCN conv 1 (fragment-permuted weights) --------
    wtrans_conv<<<(RKK/16)*12, 256>>>(cw1, p_wt1);
    zero_stats_k<<<(4*TCC + 255)/256, 256>>>();
    conv_gemm_tf32<true><<<dim3(TCC/128, LLEN/128, Bb), 256, STAGES*STG>>>(p_ht, p_wt1, p_t1);
    conv_bn<<<(Bb*TCC*LLEN)/256, 256>>>(p_t1, cg1, cbeta1, (const float*)nullptr);

    // -------- TCN conv 2 + residual --------
    wtrans_conv<<<(RKK/16)*12, 256>>>(cw2, p_wt2);
    zero_stats_k<<<(4*TCC + 255)/256, 256>>>();
    conv_gemm_tf32<false><<<dim3(TCC/128, LLEN/128, Bb), 256, STAGES*STG>>>(p_t1, p_wt2, p_t2);
    conv_bn<<<(Bb*TCC*LLEN)/256, 256>>>(p_t2, cg2, cbeta2, p_ht);

    // -------- output layer (tf32, permuted A) --------
    out_gemm_tf32<<<dim3(HHC/128, LLEN/128, Bb), 256, 3*STGO>>>(p_t2, ob, out);

    (void)in_sizes; (void)n_in; (void)out_size;
}

// round 7
// speedup vs baseline: 4.1344x; 1.0865x over previous
#include <cuda_runtime.h>
#include <math.h>
#include <stdint.h>

#define Bb 32
#define Ss 512
#define NNODE 6
#define CIN 12
#define H1C 128
#define HHC 256
#define TCC 1536
#define LLEN 512
#define LP 544              /* padded row stride: 16 | 512 | 16 */
#define OFFX 16
#define M1R (Bb*Ss*NNODE)   /* 98304 */
#define NBS (Bb*Ss)         /* 16384 */
#define RKK (5*TCC)         /* 7680  */
#define BNEPS 1e-5f

// ---------------- scratch (device globals; no runtime allocation) ----------
__device__ float g_xc1 [M1R*H1C];
__device__ float g_res1[M1R*H1C];
__device__ float g_h1  [M1R*H1C];     // tf32-rounded at write
__device__ float g_y2  [M1R*HHC];
__device__ float g_res2[M1R*HHC];
__device__ float g_xc2 [M1R*HHC];
__device__ float g_ht  [Bb*TCC*LP];   // padded, tf32-rounded at write
__device__ float g_t1  [Bb*TCC*LP];   // padded, tf32-rounded after bn
__device__ float g_t2  [Bb*TCC*LP];   // padded, tf32-rounded after bn
__device__ float g_wt1 [RKK*TCC];     // fragment-permuted tiles, tf32 bits
__device__ float g_wt2 [RKK*TCC];
__device__ float g_wB  [H1C*512];     // packed (w2T | rw2T), tf32 bits
__device__ float g_biasP[512];
__device__ float g_owR [TCC*HHC];     // fragment-permuted ow tiles, tf32 bits
__device__ float g_stats[4*TCC];

// ---------------- helpers ----------------------------------------------------
__device__ __forceinline__ unsigned f2tf32(float f) {
    unsigned u; asm("cvt.rna.tf32.f32 %0, %1;" : "=r"(u) : "f"(f)); return u;
}
#define MMA_TF32(c, a, b) \
    asm volatile("mma.sync.aligned.m16n8k8.row.col.f32.tf32.tf32.f32 " \
        "{%0,%1,%2,%3}, {%4,%5,%6,%7}, {%8,%9}, {%0,%1,%2,%3};" \
        : "+f"((c)[0]), "+f"((c)[1]), "+f"((c)[2]), "+f"((c)[3]) \
        : "r"((a)[0]), "r"((a)[1]), "r"((a)[2]), "r"((a)[3]), \
          "r"((b)[0]), "r"((b)[1]))

__device__ __forceinline__ void cpasync16(uint32_t dst, const void* src) {
    asm volatile("cp.async.cg.shared.global [%0], [%1], 16;" :: "r"(dst), "l"(src));
}
__device__ __forceinline__ void cpa_commit() {
    asm volatile("cp.async.commit_group;" ::: "memory");
}
template<int N>
__device__ __forceinline__ void cpa_wait() {
    asm volatile("cp.async.wait_group %0;" :: "n"(N) : "memory");
}
__device__ __forceinline__ uint32_t s2u(const void* p) {
    return (uint32_t)__cvta_generic_to_shared(p);
}

// ---------------- small utility kernels ------------------------------------
__global__ void zero_stats_k() {
    int i = blockIdx.x * blockDim.x + threadIdx.x;
    if (i < 4*TCC) g_stats[i] = 0.f;
}

__global__ void zero_pads(float* __restrict__ a, float* __restrict__ b) {
    int idx = blockIdx.x * blockDim.x + threadIdx.x;
    if (idx >= Bb*TCC*8) return;
    int row = idx >> 3, j = idx & 7;
    size_t off = (size_t)row * LP + (j < 4 ? j * 4 : 528 + (j - 4) * 4);
    *(float4*)(a + off) = make_float4(0.f, 0.f, 0.f, 0.f);
    *(float4*)(b + off) = make_float4(0.f, 0.f, 0.f, 0.f);
}

// pack w2/rw2 into wB[i][0:256]=rna(w2[o][i]), wB[i][256:512]=rna(rw2[o][i])
__global__ void pack_gcn2(const float* __restrict__ w2, const float* __restrict__ rw2,
                          const float* __restrict__ b2, const float* __restrict__ rb2) {
    int idx = blockIdx.x * blockDim.x + threadIdx.x;
    if (idx >= H1C * HHC) return;
    int i = idx >> 8;
    int o = idx & 255;
    unsigned* wB = (unsigned*)g_wB;
    wB[i * 512 + o]       = f2tf32(w2[(size_t)o * H1C + i]);
    wB[i * 512 + 256 + o] = f2tf32(rw2[(size_t)o * H1C + i]);
    if (i == 0) { g_biasP[o] = b2[o]; g_biasP[256 + o] = rb2[o]; }
}

// ---- fragment permutation (see round 6) ------------------------------------
__global__ void wtrans_conv(const float* __restrict__ cw, float* __restrict__ wt) {
    int tile = blockIdx.x;                    // tk*12 + cb
    int tk = tile / 12, cb = tile % 12;
    int k = (tk * 16) / TCC, ci0 = (tk * 16) % TCC;
    unsigned* dst = (unsigned*)wt + (size_t)tile * 2048 + threadIdx.x * 8;
#pragma unroll
    for (int u = 0; u < 8; u++) {
        int pos = threadIdx.x * 8 + u;
        int q = pos & 3, lp = (pos >> 2) & 31, mi = (pos >> 7) & 7, ks8 = pos >> 10;
        int ci = ci0 + ks8 * 8 + (lp & 3) + ((q >> 1) << 2);
        int co = cb * 128 + mi * 16 + (lp >> 2) + ((q & 1) << 3);
        dst[u] = f2tf32(cw[((size_t)co * TCC + ci) * 5 + k]);
    }
}

__global__ void pack_ow(const float* __restrict__ ow) {
    int tile = blockIdx.x;                    // tk*2 + cb
    int tk = tile >> 1, cb = tile & 1;
    unsigned* dst = (unsigned*)g_owR + (size_t)tile * 2048 + threadIdx.x * 8;
#pragma unroll
    for (int u = 0; u < 8; u++) {
        int pos = threadIdx.x * 8 + u;
        int q = pos & 3, lp = (pos >> 2) & 31, mi = (pos >> 7) & 7, ks8 = pos >> 10;
        int c = tk * 16 + ks8 * 8 + (lp & 3) + ((q >> 1) << 2);
        int o = cb * 128 + mi * 16 + (lp >> 2) + ((q & 1) << 3);
        dst[u] = f2tf32(ow[(size_t)o * TCC + c]);
    }
}

// ---------------- GCN stage 1 ------------------------------------------------
__global__ void gcn1_kernel(const float* __restrict__ x, const float* __restrict__ adj,
                            const float* __restrict__ eimp,
                            const float* __restrict__ w1, const float* __restrict__ b1,
                            const float* __restrict__ rw1, const float* __restrict__ rb1) {
    __shared__ float xs[NNODE*CIN];
    __shared__ float Asm[NNODE*NNODE];
    __shared__ float xts[NNODE*H1C];
    int bs = blockIdx.x;
    int tid = threadIdx.x;
    if (tid < NNODE*CIN) xs[tid] = x[(size_t)bs*NNODE*CIN + tid];
    if (tid >= 128 && tid < 128 + NNODE*NNODE) Asm[tid-128] = adj[tid-128] * eimp[tid-128];
    __syncthreads();
    for (int e = tid; e < NNODE*H1C; e += blockDim.x) {
        int n = e / H1C, c = e % H1C;
        float ws = b1[c], rs = rb1[c];
#pragma unroll
        for (int i = 0; i < CIN; i++) {
            float xv = xs[n*CIN + i];
            ws += xv * w1[c*CIN + i];
            rs += xv * rw1[c*CIN + i];
        }
        xts[e] = ws;
        g_res1[(size_t)bs*(NNODE*H1C) + e] = rs;
    }
    __syncthreads();
    for (int e = tid; e < NNODE*H1C; e += blockDim.x) {
        int n = e / H1C, c = e % H1C;
        float acc = 0.f;
#pragma unroll
        for (int m = 0; m < NNODE; m++) acc += Asm[n*NNODE + m] * xts[m*H1C + c];
        g_xc1[(size_t)bs*(NNODE*H1C) + e] = acc;
    }
}

__global__ void stats_rows(const float* __restrict__ a, const float* __restrict__ b,
                           int Mrows, int C) {
    int c = threadIdx.x;
    int rows_per = Mrows / gridDim.x;
    int r0 = blockIdx.x * rows_per;
    int r1 = r0 + rows_per;
    float sa = 0.f, qa = 0.f, sb = 0.f, qb = 0.f;
    for (int r = r0; r < r1; r++) {
        float v = a[(size_t)r*C + c]; sa += v; qa += v*v;
        float u = b[(size_t)r*C + c]; sb += u; qb += u*u;
    }
    atomicAdd(&g_stats[c],       sa);
    atomicAdd(&g_stats[C + c],   qa);
    atomicAdd(&g_stats[2*C + c], sb);
    atomicAdd(&g_stats[3*C + c], qb);
}

__global__ void bn_apply1(const float* __restrict__ g1, const float* __restrict__ beta1,
                          const float* __restrict__ rg1, const float* __restrict__ rbeta1) {
    size_t idx = (size_t)blockIdx.x * blockDim.x + threadIdx.x;
    if (idx >= (size_t)M1R*H1C) return;
    int c = (int)(idx % H1C);
    const float invM = 1.f / (float)M1R;
    float m1 = g_stats[c] * invM;
    float v1 = g_stats[H1C + c] * invM - m1*m1;
    float m2 = g_stats[2*H1C + c] * invM;
    float v2 = g_stats[3*H1C + c] * invM - m2*m2;
    float a = (g_xc1[idx]  - m1) * rsqrtf(v1 + BNEPS) * g1[c]  + beta1[c];
    float r = (g_res1[idx] - m2) * rsqrtf(v2 + BNEPS) * rg1[c] + rbeta1[c];
    float o = a + r;
    o = o > 0.f ? o : 0.f;
    g_h1[idx] = __uint_as_float(f2tf32(o));
}

// ---------------- gcn2 dual GEMM (tf32 mma) ---------------------------------
#define A2STR 20
#define B2STR 136
#define A2SZ (128*A2STR*4)
#define B2SZ (16*B2STR*4)
#define STG2 (A2SZ + B2SZ)

__global__ __launch_bounds__(256, 2) void gcn2_gemm_tf32() {
    extern __shared__ __align__(128) char dsm[];
    const int tid = threadIdx.x;
    const int bm = blockIdx.x * 128;
    const int by = blockIdx.y;
    const int bn = by * 128;
    const int lane = tid & 31, wid = tid >> 5;
    const int wm = (wid & 1) * 64, wn = (wid >> 1) * 32;
    const int g = lane >> 2, tg = lane & 3;
    const uint32_t smem_u = s2u(dsm);
    const float* A = g_h1;

    float acc[4][4][4];
#pragma unroll
    for (int mi = 0; mi < 4; mi++)
#pragma unroll
        for (int ni = 0; ni < 4; ni++)
#pragma unroll
            for (int r = 0; r < 4; r++) acc[mi][ni][r] = 0.f;

    const int NT = H1C / 16;   // 8

    auto load_stage = [&](int slot, int t) {
        const int kk0 = t * 16;
        const uint32_t sa = smem_u + slot * STG2;
        const uint32_t sb = sa + A2SZ;
#pragma unroll
        for (int i = 0; i < 2; i++) {
            int idx = tid + i * 256;
            int m = idx >> 2, kc = (idx & 3) * 4;
            cpasync16(sa + (m * A2STR + kc) * 4,
                      A + (size_t)(bm + m) * H1C + kk0 + kc);
        }
#pragma unroll
        for (int i = 0; i < 2; i++) {
            int idx = tid + i * 256;
            int row = idx >> 5, ch = idx & 31;
            cpasync16(sb + (row * B2STR + ch * 4) * 4,
                      g_wB + (size_t)(kk0 + row) * 512 + bn + ch * 4);
        }
    };
    load_stage(0, 0); cpa_commit();
    load_stage(1, 1); cpa_commit();

    for (int t = 0; t < NT; ++t) {
        cpa_wait<1>();
        __syncthreads();
        if (t + 2 < NT) load_stage((t + 2) % 3, t + 2);
        cpa_commit();
        const int cur = t % 3;
        const float* As = (const float*)(dsm + cur * STG2);
        const float* Bs = (const float*)(dsm + cur * STG2 + A2SZ);
#pragma unroll
        for (int ks = 0; ks < 16; ks += 8) {
            unsigned a[4][4], b[4][2];
#pragma unroll
            for (int mi = 0; mi < 4; mi++) {
                int m = wm + mi * 16 + g;
                a[mi][0] = __float_as_uint(As[(m    ) * A2STR + ks + tg]);
                a[mi][1] = __float_as_uint(As[(m + 8) * A2STR + ks + tg]);
                a[mi][2] = __float_as_uint(As[(m    ) * A2STR + ks + tg + 4]);
                a[mi][3] = __float_as_uint(As[(m + 8) * A2STR + ks + tg + 4]);
            }
#pragma unroll
            for (int ni = 0; ni < 4; ni++) {
                int c = wn + ni * 8 + g;
                b[ni][0] = __float_as_uint(Bs[(ks + tg    ) * B2STR + c]);
                b[ni][1] = __float_as_uint(Bs[(ks + tg + 4) * B2STR + c]);
            }
#pragma unroll
            for (int mi = 0; mi < 4; mi++)
#pragma unroll
                for (int ni = 0; ni < 4; ni++)
                    MMA_TF32(acc[mi][ni], a[mi], b[ni]);
        }
    }

    float* tgt = (by < 2) ? g_y2 : g_res2;
    const int nb = (by & 1) * 128;
#pragma unroll
    for (int mi = 0; mi < 4; mi++) {
        int m0 = bm + wm + mi * 16 + g;
#pragma unroll
        for (int ni = 0; ni < 4; ni++) {
            int n = nb + wn + ni * 8 + 2 * tg;
            int pb = bn + wn + ni * 8 + 2 * tg;
            float b0 = g_biasP[pb], b1 = g_biasP[pb + 1];
            *(float2*)(tgt + (size_t)m0 * HHC + n)
                = make_float2(acc[mi][ni][0] + b0, acc[mi][ni][1] + b1);
            *(float2*)(tgt + (size_t)(m0 + 8) * HHC + n)
                = make_float2(acc[mi][ni][2] + b0, acc[mi][ni][3] + b1);
        }
    }
}

// ---------------- node mix for stage 2 --------------------------------------
__global__ void nodemix2(const float* __restrict__ adj, const float* __restrict__ eimp) {
    __shared__ float ys[NNODE*HHC];
    __shared__ float Asm[NNODE*NNODE];
    int bs = blockIdx.x, tid = threadIdx.x;
    if (tid < NNODE*NNODE) Asm[tid] = adj[tid] * eimp[tid];
    for (int e = tid; e < NNODE*HHC; e += blockDim.x)
        ys[e] = g_y2[(size_t)bs*NNODE*HHC + e];
    __syncthreads();
    for (int e = tid; e < NNODE*HHC; e += blockDim.x) {
        int n = e / HHC, c = e % HHC;
        float acc = 0.f;
#pragma unroll
        for (int m = 0; m < NNODE; m++) acc += Asm[n*NNODE + m] * ys[m*HHC + c];
        g_xc2[(size_t)bs*NNODE*HHC + e] = acc;
    }
}

// ---------------- BN apply stage 2 + transpose; writes tf32-rounded ht ------
__global__ void bn_apply2_transpose(const float* __restrict__ g2, const float* __restrict__ beta2,
                                    const float* __restrict__ rg2, const float* __restrict__ rbeta2) {
    __shared__ float tile[32][33];
    int s0 = blockIdx.x * 32, c0 = blockIdx.y * 32;
    int bn = blockIdx.z;
    int b = bn / NNODE, n = bn % NNODE;
    int tx = threadIdx.x, ty = threadIdx.y;
    const float invM = 1.f / (float)M1R;
    int c = c0 + tx;
    float m1 = g_stats[c] * invM;
    float v1 = g_stats[HHC + c] * invM - m1*m1;
    float m2 = g_stats[2*HHC + c] * invM;
    float v2 = g_stats[3*HHC + c] * invM - m2*m2;
    float sc1 = rsqrtf(v1 + BNEPS) * g2[c];
    float sh1 = beta2[c] - m1*sc1;
    float sc2 = rsqrtf(v2 + BNEPS) * rg2[c];
    float sh2 = rbeta2[c] - m2*sc2;
#pragma unroll
    for (int j = 0; j < 4; j++) {
        int s = s0 + ty + 8*j;
        size_t ridx = (((size_t)(b*Ss + s) * NNODE) + n) * HHC + c;
        float o = g_xc2[ridx]*sc1 + sh1 + g_res2[ridx]*sc2 + sh2;
        o = o > 0.f ? o : 0.f;
        tile[ty + 8*j][tx] = __uint_as_float(f2tf32(o));
    }
    __syncthreads();
#pragma unroll
    for (int j = 0; j < 4; j++) {
        int cc = c0 + ty + 8*j;
        int s  = s0 + tx;
        g_ht[((size_t)b*TCC + n*HHC + cc) * LP + OFFX + s] = tile[tx][ty + 8*j];
    }
}

// ======================= conv1d tf32 mma GEMM, 5-stage cp.async =============
// A operand fragment-permuted in global; B pre-rounded tf32; one BAR/iter.
#define ASZ 8192
#define BSTR 152
#define BSZ (16*BSTR*4)
#define STG (ASZ + BSZ)
#define STAGES 5

__global__ __launch_bounds__(256, 2) void conv_gemm_tf32(
        const float* __restrict__ X, const float* __restrict__ Wt, float* __restrict__ Y) {
    extern __shared__ __align__(128) char dsm[];
    const int tid = threadIdx.x;
    const int cb = blockIdx.x;
    const int bm = cb * 128;           // co
    const int bn = blockIdx.y * 128;   // l
    const float* Xb = X + (size_t)blockIdx.z * TCC * LP;
    float* Yb = Y + (size_t)blockIdx.z * TCC * LP;
    const int lane = tid & 31, wid = tid >> 5;
    const int wm = (wid & 1) * 64, wn = (wid >> 1) * 32;
    const int g = lane >> 2, tg = lane & 3;
    const int aoff = (wid & 1) * 4;

    const uint32_t smem_u = s2u(dsm);

    float acc[4][4][4];
#pragma unroll
    for (int mi = 0; mi < 4; mi++)
#pragma unroll
        for (int ni = 0; ni < 4; ni++)
#pragma unroll
            for (int r = 0; r < 4; r++) acc[mi][ni][r] = 0.f;

    const int NT = RKK / 16;   // 480 = 96 * 5

    auto load_stage = [&](int slot, int t) {
        const int kk0  = t * 16;
        const int kseg = kk0 / TCC;
        const int ci0  = kk0 - kseg * TCC;
        const uint32_t sa = smem_u + slot * STG;
        const uint32_t sb = sa + ASZ;
        {
            const float* src = Wt + ((size_t)t * 12 + cb) * 2048 + tid * 8;
            cpasync16(sa + tid * 32, src);
            cpasync16(sa + tid * 32 + 16, src + 4);
        }
#pragma unroll
        for (int i = tid; i < 576; i += 256) {
            int row = i / 36, ch = i % 36;
            const float* src = Xb + (size_t)(ci0 + row) * LP + 12 + bn + ch * 4;
            cpasync16(sb + (row * BSTR + ch * 4) * 4, src);
        }
    };

    load_stage(0, 0); cpa_commit();
    load_stage(1, 1); cpa_commit();
    load_stage(2, 2); cpa_commit();
    load_stage(3, 3); cpa_commit();

    for (int tb = 0; tb < NT; tb += STAGES) {
#pragma unroll
        for (int s = 0; s < STAGES; s++) {
            const int t = tb + s;
            cpa_wait<STAGES - 2>();
            __syncthreads();
            if (t + 4 < NT) load_stage((t + 4) % STAGES, t + 4);
            cpa_commit();

            const float4* Af = (const float4*)(dsm + s * STG);
            const float* Bs = (const float*)(dsm + s * STG + ASZ);
            const int kseg = (t * 16) / TCC;
            const int sh4  = kseg + 2;

#pragma unroll
            for (int ks8 = 0; ks8 < 2; ks8++) {
                const int ks = ks8 * 8;
                unsigned a[4][4], b[4][2];
#pragma unroll
                for (int mi = 0; mi < 4; mi++) {
                    float4 v = Af[(ks8 * 8 + aoff + mi) * 32 + lane];
                    a[mi][0] = __float_as_uint(v.x);
                    a[mi][1] = __float_as_uint(v.y);
                    a[mi][2] = __float_as_uint(v.z);
                    a[mi][3] = __float_as_uint(v.w);
                }
#pragma unroll
                for (int ni = 0; ni < 4; ni++) {
                    int c = sh4 + wn + ni * 8 + g;
                    b[ni][0] = __float_as_uint(Bs[(ks+tg  )*BSTR + c]);
                    b[ni][1] = __float_as_uint(Bs[(ks+tg+4)*BSTR + c]);
                }
#pragma unroll
                for (int mi = 0; mi < 4; mi++)
#pragma unroll
                    for (int ni = 0; ni < 4; ni++)
                        MMA_TF32(acc[mi][ni], a[mi], b[ni]);
            }
        }
    }

#pragma unroll
    for (int mi = 0; mi < 4; mi++) {
        int m0 = bm + wm + mi * 16 + g;
        float s0 = 0.f, q0 = 0.f, s1 = 0.f, q1 = 0.f;
#pragma unroll
        for (int ni = 0; ni < 4; ni++) {
            float v0 = acc[mi][ni][0], v1 = acc[mi][ni][1];
            float v2 = acc[mi][ni][2], v3 = acc[mi][ni][3];
            s0 += v0 + v1; q0 += v0*v0 + v1*v1;
            s1 += v2 + v3; q1 += v2*v2 + v3*v3;
            int l = bn + wn + ni * 8 + 2 * tg;
            *(float2*)(Yb + (size_t)m0 * LP + OFFX + l)     = make_float2(v0, v1);
            *(float2*)(Yb + (size_t)(m0+8) * LP + OFFX + l) = make_float2(v2, v3);
        }
        s0 += __shfl_xor_sync(0xffffffffu, s0, 1);
        s0 += __shfl_xor_sync(0xffffffffu, s0, 2);
        q0 += __shfl_xor_sync(0xffffffffu, q0, 1);
        q0 += __shfl_xor_sync(0xffffffffu, q0, 2);
        s1 += __shfl_xor_sync(0xffffffffu, s1, 1);
        s1 += __shfl_xor_sync(0xffffffffu, s1, 2);
        q1 += __shfl_xor_sync(0xffffffffu, q1, 1);
        q1 += __shfl_xor_sync(0xffffffffu, q1, 2);
        if (tg == 0) {
            atomicAdd(&g_stats[m0],         s0);
            atomicAdd(&g_stats[TCC + m0],   q0);
            atomicAdd(&g_stats[m0 + 8],     s1);
            atomicAdd(&g_stats[TCC + m0+8], q1);
        }
    }
}

// ---------------- conv BN apply (padded layout; writes tf32-rounded) --------
__global__ void conv_bn(float* __restrict__ T, const float* __restrict__ g,
                        const float* __restrict__ beta, const float* __restrict__ resid) {
    size_t idx = (size_t)blockIdx.x * blockDim.x + threadIdx.x;
    if (idx >= (size_t)Bb*TCC*LLEN) return;
    size_t row = idx / LLEN;
    int l = (int)(idx % LLEN);
    int c = (int)(row % TCC);
    size_t a = row * LP + OFFX + l;
    const float invM = 1.f / (float)(Bb * LLEN);
    float m = g_stats[c] * invM;
    float v = g_stats[TCC + c] * invM - m*m;
    float o = (T[a] - m) * rsqrtf(v + BNEPS) * g[c] + beta[c];
    o = o > 0.f ? o : 0.f;
    if (resid) o += resid[a];
    T[a] = __uint_as_float(f2tf32(o));
}

// ======================= output GEMM (tf32 mma, permuted A) =================
#define BOSTR 136
#define BOSZ (16*BOSTR*4)
#define STGO (ASZ + BOSZ)

__global__ __launch_bounds__(256, 2) void out_gemm_tf32(
        const float* __restrict__ T2, const float* __restrict__ OB,
        float* __restrict__ OUT) {
    extern __shared__ __align__(128) char dsm[];
    const int tid = threadIdx.x;
    const int cb = blockIdx.x;
    const int bm = cb * 128;           // o
    const int bn = blockIdx.y * 128;   // s
    const int b  = blockIdx.z;
    const float* T2b = T2 + (size_t)b * TCC * LP;
    const int lane = tid & 31, wid = tid >> 5;
    const int wm = (wid & 1) * 64, wn = (wid >> 1) * 32;
    const int g = lane >> 2, tg = lane & 3;
    const int aoff = (wid & 1) * 4;
    const uint32_t smem_u = s2u(dsm);

    float acc[4][4][4];
#pragma unroll
    for (int mi = 0; mi < 4; mi++)
#pragma unroll
        for (int ni = 0; ni < 4; ni++)
#pragma unroll
            for (int r = 0; r < 4; r++) acc[mi][ni][r] = 0.f;

    const int NT = TCC / 16;   // 96

    auto load_stage = [&](int slot, int t) {
        const int kk0 = t * 16;
        const uint32_t sa = smem_u + slot * STGO;
        const uint32_t sb = sa + ASZ;
        {
            const float* src = g_owR + ((size_t)t * 2 + cb) * 2048 + tid * 8;
            cpasync16(sa + tid * 32, src);
            cpasync16(sa + tid * 32 + 16, src + 4);
        }
#pragma unroll
        for (int i = 0; i < 2; i++) {
            int idx = tid + i * 256;
            int row = idx >> 5, ch = idx & 31;
            cpasync16(sb + (row * BOSTR + ch * 4) * 4,
                      T2b + (size_t)(kk0 + row) * LP + OFFX + bn + ch * 4);
        }
    };
    load_stage(0, 0); cpa_commit();
    load_stage(1, 1); cpa_commit();

    for (int t = 0; t < NT; ++t) {
        cpa_wait<1>();
        __syncthreads();
        if (t + 2 < NT) load_stage((t + 2) % 3, t + 2);
        cpa_commit();
        const int cur = t % 3;
        const float4* Af = (const float4*)(dsm + cur * STGO);
        const float* Bs = (const float*)(dsm + cur * STGO + ASZ);
#pragma unroll
        for (int ks8 = 0; ks8 < 2; ks8++) {
            const int ks = ks8 * 8;
            unsigned a[4][4], b[4][2];
#pragma unroll
            for (int mi = 0; mi < 4; mi++) {
                float4 v = Af[(ks8 * 8 + aoff + mi) * 32 + lane];
                a[mi][0] = __float_as_uint(v.x);
                a[mi][1] = __float_as_uint(v.y);
                a[mi][2] = __float_as_uint(v.z);
                a[mi][3] = __float_as_uint(v.w);
            }
#pragma unroll
            for (int ni = 0; ni < 4; ni++) {
                int c = wn + ni * 8 + g;
                b[ni][0] = __float_as_uint(Bs[(ks+tg  )*BOSTR + c]);
                b[ni][1] = __float_as_uint(Bs[(ks+tg+4)*BOSTR + c]);
            }
#pragma unroll
            for (int mi = 0; mi < 4; mi++)
#pragma unroll
                for (int ni = 0; ni < 4; ni++)
                    MMA_TF32(acc[mi][ni], a[mi], b[ni]);
        }
    }

#pragma unroll
    for (int mi = 0; mi < 4; mi++) {
        int o0 = bm + wm + mi * 16 + g;
        float bo0 = OB[o0], bo1 = OB[o0 + 8];
#pragma unroll
        for (int ni = 0; ni < 4; ni++) {
            int sL = bn + wn + ni * 8 + 2 * tg;
            float v0 = acc[mi][ni][0] + bo0; v0 = v0 > 0.f ? v0 : 0.f;
            float v1 = acc[mi][ni][1] + bo0; v1 = v1 > 0.f ? v1 : 0.f;
            float v2 = acc[mi][ni][2] + bo1; v2 = v2 > 0.f ? v2 : 0.f;
            float v3 = acc[mi][ni][3] + bo1; v3 = v3 > 0.f ? v3 : 0.f;
            OUT[((size_t)b * Ss + sL    ) * HHC + o0    ] = v0;
            OUT[((size_t)b * Ss + sL + 1) * HHC + o0    ] = v1;
            OUT[((size_t)b * Ss + sL    ) * HHC + o0 + 8] = v2;
            OUT[((size_t)b * Ss + sL + 1) * HHC + o0 + 8] = v3;
        }
    }
}

// ---------------- launch ----------------------------------------------------
extern "C" void kernel_launch(void* const* d_in, const int* in_sizes, int n_in,
                              void* d_out, int out_size) {
    const float* x     = (const float*)d_in[0];
    const float* adj   = (const float*)d_in[1];
    const float* eimp  = (const float*)d_in[2];
    const float* w1    = (const float*)d_in[3];
    const float* b1    = (const float*)d_in[4];
    const float* rw1   = (const float*)d_in[5];
    const float* rb1   = (const float*)d_in[6];
    const float* rg1   = (const float*)d_in[7];
    const float* rbeta1= (const float*)d_in[8];
    const float* g1    = (const float*)d_in[9];
    const float* beta1 = (const float*)d_in[10];
    const float* w2    = (const float*)d_in[11];
    const float* b2    = (const float*)d_in[12];
    const float* rw2   = (const float*)d_in[13];
    const float* rb2   = (const float*)d_in[14];
    const float* rg2   = (const float*)d_in[15];
    const float* rbeta2= (const float*)d_in[16];
    const float* g2    = (const float*)d_in[17];
    const float* beta2 = (const float*)d_in[18];
    const float* cw1   = (const float*)d_in[19];
    /* cb1 = d_in[20]: cancels exactly through BN mean-subtraction */
    const float* cg1   = (const float*)d_in[21];
    const float* cbeta1= (const float*)d_in[22];
    const float* cw2   = (const float*)d_in[23];
    /* cb2 = d_in[24]: cancels exactly */
    const float* cg2   = (const float*)d_in[25];
    const float* cbeta2= (const float*)d_in[26];
    const float* ow    = (const float*)d_in[27];
    const float* ob    = (const float*)d_in[28];
    float* out = (float*)d_out;

    float *p_xc1, *p_res1, *p_xc2, *p_res2, *p_ht, *p_t1, *p_t2, *p_wt1, *p_wt2;
    cudaGetSymbolAddress((void**)&p_xc1,  g_xc1);
    cudaGetSymbolAddress((void**)&p_res1, g_res1);
    cudaGetSymbolAddress((void**)&p_xc2,  g_xc2);
    cudaGetSymbolAddress((void**)&p_res2, g_res2);
    cudaGetSymbolAddress((void**)&p_ht,   g_ht);
    cudaGetSymbolAddress((void**)&p_t1,   g_t1);
    cudaGetSymbolAddress((void**)&p_t2,   g_t2);
    cudaGetSymbolAddress((void**)&p_wt1,  g_wt1);
    cudaGetSymbolAddress((void**)&p_wt2,  g_wt2);

    cudaFuncSetAttribute(conv_gemm_tf32,
                         cudaFuncAttributeMaxDynamicSharedMemorySize, STAGES * STG);
    cudaFuncSetAttribute(gcn2_gemm_tf32,
                         cudaFuncAttributeMaxDynamicSharedMemorySize, 3 * STG2);
    cudaFuncSetAttribute(out_gemm_tf32,
                         cudaFuncAttributeMaxDynamicSharedMemorySize, 3 * STGO);

    // -------- GCN stage 1 --------
    gcn1_kernel<<<NBS, 256>>>(x, adj, eimp, w1, b1, rw1, rb1);
    zero_stats_k<<<(4*TCC + 255)/256, 256>>>();
    zero_pads<<<(Bb*TCC*8 + 255)/256, 256>>>(p_ht, p_t1);
    pack_gcn2<<<(H1C*HHC + 255)/256, 256>>>(w2, rw2, b2, rb2);
    pack_ow<<<(TCC*HHC)/2048, 256>>>(ow);
    stats_rows<<<1024, H1C>>>(p_xc1, p_res1, M1R, H1C);
    bn_apply1<<<(M1R*H1C)/256, 256>>>(g1, beta1, rg1, rbeta1);

    // -------- GCN stage 2 (tf32 dual GEMM) --------
    gcn2_gemm_tf32<<<dim3(M1R/128, 4), 256, 3*STG2>>>();
    nodemix2<<<NBS, 256>>>(adj, eimp);
    zero_stats_k<<<(4*TCC + 255)/256, 256>>>();
    stats_rows<<<1024, HHC>>>(p_xc2, p_res2, M1R, HHC);
    bn_apply2_transpose<<<dim3(Ss/32, HHC/32, Bb*NNODE), dim3(32, 8)>>>(g2, beta2, rg2, rbeta2);

    // -------- TCN conv 1 --------
    wtrans_conv<<<(RKK/16)*12, 256>>>(cw1, p_wt1);
    zero_stats_k<<<(4*TCC + 255)/256, 256>>>();
    conv_gemm_tf32<<<dim3(TCC/128, LLEN/128, Bb), 256, STAGES*STG>>>(p_ht, p_wt1, p_t1);
    conv_bn<<<(Bb*TCC*LLEN)/256, 256>>>(p_t1, cg1, cbeta1, (const float*)nullptr);

    // -------- TCN conv 2 + residual --------
    wtrans_conv<<<(RKK/16)*12, 256>>>(cw2, p_wt2);
    zero_stats_k<<<(4*TCC + 255)/256, 256>>>();
    conv_gemm_tf32<<<dim3(TCC/128, LLEN/128, Bb), 256, STAGES*STG>>>(p_t1, p_wt2, p_t2);
    conv_bn<<<(Bb*TCC*LLEN)/256, 256>>>(p_t2, cg2, cbeta2, p_ht);

    // -------- output layer (tf32, permuted A) --------
    out_gemm_tf32<<<dim3(HHC/128, LLEN/128, Bb), 256, 3*STGO>>>(p_t2, ob, out);

    (void)in_sizes; (void)n_in; (void)out_size;
}

// round 8
// speedup vs baseline: 8.0370x; 1.9439x over previous
#include <cuda_runtime.h>
#include <cuda_fp16.h>
#include <math.h>
#include <stdint.h>

#define Bb 32
#define Ss 512
#define NNODE 6
#define CIN 12
#define H1C 128
#define HHC 256
#define TCC 1536
#define LLEN 512
#define LROWS 544           /* 16 pad | 512 | 16 pad rows in [l][c] layout */
#define M1R (Bb*Ss*NNODE)   /* 98304 */
#define NBS (Bb*Ss)         /* 16384 */
#define RKK (5*TCC)         /* 7680  */
#define BNEPS 1e-5f

// ---------------- scratch (device globals; no runtime allocation) ----------
__device__ float  g_xc1 [M1R*H1C];
__device__ float  g_res1[M1R*H1C];
__device__ float  g_h1  [M1R*H1C];     // tf32-rounded at write
__device__ float  g_y2  [M1R*HHC];
__device__ float  g_res2[M1R*HHC];
__device__ float  g_xc2 [M1R*HHC];
__device__ __half g_htH [Bb*LROWS*TCC];  // [l][c] fp16, padded rows
__device__ __half g_t1H [Bb*LROWS*TCC];
__device__ __half g_t2H [Bb*LROWS*TCC];
__device__ __half g_wt1H[RKK*TCC];       // fragment-permuted fp16 tiles
__device__ __half g_wt2H[RKK*TCC];
__device__ float  g_wB  [H1C*512];       // packed (w2T | rw2T), tf32 bits
__device__ float  g_biasP[512];
__device__ __half g_owRH[TCC*HHC];       // fragment-permuted ow fp16 tiles
__device__ float  g_stats[4*TCC];

// ---------------- helpers ----------------------------------------------------
__device__ __forceinline__ unsigned f2tf32(float f) {
    unsigned u; asm("cvt.rna.tf32.f32 %0, %1;" : "=r"(u) : "f"(f)); return u;
}
#define MMA_TF32(c, a, b) \
    asm volatile("mma.sync.aligned.m16n8k8.row.col.f32.tf32.tf32.f32 " \
        "{%0,%1,%2,%3}, {%4,%5,%6,%7}, {%8,%9}, {%0,%1,%2,%3};" \
        : "+f"((c)[0]), "+f"((c)[1]), "+f"((c)[2]), "+f"((c)[3]) \
        : "r"((a)[0]), "r"((a)[1]), "r"((a)[2]), "r"((a)[3]), \
          "r"((b)[0]), "r"((b)[1]))
#define MMA_F16(c, a, b) \
    asm volatile("mma.sync.aligned.m16n8k16.row.col.f32.f16.f16.f32 " \
        "{%0,%1,%2,%3}, {%4,%5,%6,%7}, {%8,%9}, {%0,%1,%2,%3};" \
        : "+f"((c)[0]), "+f"((c)[1]), "+f"((c)[2]), "+f"((c)[3]) \
        : "r"((a)[0]), "r"((a)[1]), "r"((a)[2]), "r"((a)[3]), \
          "r"((b)[0]), "r"((b)[1]))

__device__ __forceinline__ void cpasync16(uint32_t dst, const void* src) {
    asm volatile("cp.async.cg.shared.global [%0], [%1], 16;" :: "r"(dst), "l"(src));
}
__device__ __forceinline__ void cpa_commit() {
    asm volatile("cp.async.commit_group;" ::: "memory");
}
template<int N>
__device__ __forceinline__ void cpa_wait() {
    asm volatile("cp.async.wait_group %0;" :: "n"(N) : "memory");
}
__device__ __forceinline__ uint32_t s2u(const void* p) {
    return (uint32_t)__cvta_generic_to_shared(p);
}
__device__ __forceinline__ unsigned packh2(float a, float b) {
    __half2 h = __floats2half2_rn(a, b);
    return *(unsigned*)&h;
}

// ---------------- small utility kernels ------------------------------------
__global__ void zero_stats_k() {
    int i = blockIdx.x * blockDim.x + threadIdx.x;
    if (i < 4*TCC) g_stats[i] = 0.f;
}

// zero pad rows (0..15, 528..543) of ht and t1 fp16 tensors
__global__ void zero_padsH() {
    int idx = blockIdx.x * blockDim.x + threadIdx.x;
    const int per = Bb * 32 * (TCC/8);          // uint4 chunks per tensor
    if (idx >= per) return;
    int col8 = idx % (TCC/8);
    int rr   = (idx / (TCC/8)) % 32;
    int b    = idx / (32 * (TCC/8));
    int row  = rr < 16 ? rr : 512 + rr;         // 0..15 or 528..543
    size_t off = ((size_t)b * LROWS + row) * TCC + col8 * 8;
    uint4 z = make_uint4(0,0,0,0);
    *(uint4*)((char*)g_htH + off*2) = z;
    *(uint4*)((char*)g_t1H + off*2) = z;
}

// pack w2/rw2 into wB (tf32 bits) -- gcn2 stays tf32
__global__ void pack_gcn2(const float* __restrict__ w2, const float* __restrict__ rw2,
                          const float* __restrict__ b2, const float* __restrict__ rb2) {
    int idx = blockIdx.x * blockDim.x + threadIdx.x;
    if (idx >= H1C * HHC) return;
    int i = idx >> 8;
    int o = idx & 255;
    unsigned* wB = (unsigned*)g_wB;
    wB[i * 512 + o]       = f2tf32(w2[(size_t)o * H1C + i]);
    wB[i * 512 + 256 + o] = f2tf32(rw2[(size_t)o * H1C + i]);
    if (i == 0) { g_biasP[o] = b2[o]; g_biasP[256 + o] = rb2[o]; }
}

// ---- fp16 fragment permutation for m16n8k16 --------------------------------
// tile (tk over k16, cb over m128): uint32 index pos = ((mi)*32 + lane)*4 + r
//   k_loc = 2*(lane&3) + (r>>1)*8 (+h in the packed pair)
//   m_loc = mi*16 + (lane>>2) + (r&1)*8
__global__ void wtrans_convH(const float* __restrict__ cw, __half* __restrict__ wt) {
    int tile = blockIdx.x;                    // tk*12 + cb ; tk in [0,480)
    int tk = tile / 12, cb = tile % 12;
    int kk0 = tk * 16;
    int k = kk0 / TCC, ci0 = kk0 % TCC;
    int tid = threadIdx.x;
    unsigned* dst = (unsigned*)wt + (size_t)tile * 1024 + tid * 4;
#pragma unroll
    for (int u = 0; u < 4; u++) {
        int pos = tid * 4 + u;
        int r = pos & 3, lane = (pos >> 2) & 31, mi = pos >> 7;
        int kl = 2 * (lane & 3) + ((r >> 1) << 3);
        int ml = mi * 16 + (lane >> 2) + ((r & 1) << 3);
        int co = cb * 128 + ml;
        float f0 = cw[((size_t)co * TCC + ci0 + kl    ) * 5 + k];
        float f1 = cw[((size_t)co * TCC + ci0 + kl + 1) * 5 + k];
        dst[u] = packh2(f0, f1);
    }
}

__global__ void pack_owH(const float* __restrict__ ow) {
    int tile = blockIdx.x;                    // tk*2 + cb ; tk in [0,96)
    int tk = tile >> 1, cb = tile & 1;
    int tid = threadIdx.x;
    unsigned* dst = (unsigned*)g_owRH + (size_t)tile * 1024 + tid * 4;
#pragma unroll
    for (int u = 0; u < 4; u++) {
        int pos = tid * 4 + u;
        int r = pos & 3, lane = (pos >> 2) & 31, mi = pos >> 7;
        int kl = 2 * (lane & 3) + ((r >> 1) << 3);
        int ml = mi * 16 + (lane >> 2) + ((r & 1) << 3);
        int c = tk * 16 + kl;
        int o = cb * 128 + ml;
        float f0 = ow[(size_t)o * TCC + c];
        float f1 = ow[(size_t)o * TCC + c + 1];
        dst[u] = packh2(f0, f1);
    }
}

// ---------------- GCN stage 1 ------------------------------------------------
__global__ void gcn1_kernel(const float* __restrict__ x, const float* __restrict__ adj,
                            const float* __restrict__ eimp,
                            const float* __restrict__ w1, const float* __restrict__ b1,
                            const float* __restrict__ rw1, const float* __restrict__ rb1) {
    __shared__ float xs[NNODE*CIN];
    __shared__ float Asm[NNODE*NNODE];
    __shared__ float xts[NNODE*H1C];
    int bs = blockIdx.x;
    int tid = threadIdx.x;
    if (tid < NNODE*CIN) xs[tid] = x[(size_t)bs*NNODE*CIN + tid];
    if (tid >= 128 && tid < 128 + NNODE*NNODE) Asm[tid-128] = adj[tid-128] * eimp[tid-128];
    __syncthreads();
    for (int e = tid; e < NNODE*H1C; e += blockDim.x) {
        int n = e / H1C, c = e % H1C;
        float ws = b1[c], rs = rb1[c];
#pragma unroll
        for (int i = 0; i < CIN; i++) {
            float xv = xs[n*CIN + i];
            ws += xv * w1[c*CIN + i];
            rs += xv * rw1[c*CIN + i];
        }
        xts[e] = ws;
        g_res1[(size_t)bs*(NNODE*H1C) + e] = rs;
    }
    __syncthreads();
    for (int e = tid; e < NNODE*H1C; e += blockDim.x) {
        int n = e / H1C, c = e % H1C;
        float acc = 0.f;
#pragma unroll
        for (int m = 0; m < NNODE; m++) acc += Asm[n*NNODE + m] * xts[m*H1C + c];
        g_xc1[(size_t)bs*(NNODE*H1C) + e] = acc;
    }
}

__global__ void stats_rows(const float* __restrict__ a, const float* __restrict__ b,
                           int Mrows, int C) {
    int c = threadIdx.x;
    int rows_per = Mrows / gridDim.x;
    int r0 = blockIdx.x * rows_per;
    int r1 = r0 + rows_per;
    float sa = 0.f, qa = 0.f, sb = 0.f, qb = 0.f;
    for (int r = r0; r < r1; r++) {
        float v = a[(size_t)r*C + c]; sa += v; qa += v*v;
        float u = b[(size_t)r*C + c]; sb += u; qb += u*u;
    }
    atomicAdd(&g_stats[c],       sa);
    atomicAdd(&g_stats[C + c],   qa);
    atomicAdd(&g_stats[2*C + c], sb);
    atomicAdd(&g_stats[3*C + c], qb);
}

__global__ void bn_apply1(const float* __restrict__ g1, const float* __restrict__ beta1,
                          const float* __restrict__ rg1, const float* __restrict__ rbeta1) {
    size_t idx = (size_t)blockIdx.x * blockDim.x + threadIdx.x;
    if (idx >= (size_t)M1R*H1C) return;
    int c = (int)(idx % H1C);
    const float invM = 1.f / (float)M1R;
    float m1 = g_stats[c] * invM;
    float v1 = g_stats[H1C + c] * invM - m1*m1;
    float m2 = g_stats[2*H1C + c] * invM;
    float v2 = g_stats[3*H1C + c] * invM - m2*m2;
    float a = (g_xc1[idx]  - m1) * rsqrtf(v1 + BNEPS) * g1[c]  + beta1[c];
    float r = (g_res1[idx] - m2) * rsqrtf(v2 + BNEPS) * rg1[c] + rbeta1[c];
    float o = a + r;
    o = o > 0.f ? o : 0.f;
    g_h1[idx] = __uint_as_float(f2tf32(o));
}

// ---------------- gcn2 dual GEMM (tf32 mma, unchanged) ----------------------
#define A2STR 20
#define B2STR 136
#define A2SZ (128*A2STR*4)
#define B2SZ (16*B2STR*4)
#define STG2 (A2SZ + B2SZ)

__global__ __launch_bounds__(256, 2) void gcn2_gemm_tf32() {
    extern __shared__ __align__(128) char dsm[];
    const int tid = threadIdx.x;
    const int bm = blockIdx.x * 128;
    const int by = blockIdx.y;
    const int bn = by * 128;
    const int lane = tid & 31, wid = tid >> 5;
    const int wm = (wid & 1) * 64, wn = (wid >> 1) * 32;
    const int g = lane >> 2, tg = lane & 3;
    const uint32_t smem_u = s2u(dsm);
    const float* A = g_h1;

    float acc[4][4][4];
#pragma unroll
    for (int mi = 0; mi < 4; mi++)
#pragma unroll
        for (int ni = 0; ni < 4; ni++)
#pragma unroll
            for (int r = 0; r < 4; r++) acc[mi][ni][r] = 0.f;

    const int NT = H1C / 16;   // 8

    auto load_stage = [&](int slot, int t) {
        const int kk0 = t * 16;
        const uint32_t sa = smem_u + slot * STG2;
        const uint32_t sb = sa + A2SZ;
#pragma unroll
        for (int i = 0; i < 2; i++) {
            int idx = tid + i * 256;
            int m = idx >> 2, kc = (idx & 3) * 4;
            cpasync16(sa + (m * A2STR + kc) * 4,
                      A + (size_t)(bm + m) * H1C + kk0 + kc);
        }
#pragma unroll
        for (int i = 0; i < 2; i++) {
            int idx = tid + i * 256;
            int row = idx >> 5, ch = idx & 31;
            cpasync16(sb + (row * B2STR + ch * 4) * 4,
                      g_wB + (size_t)(kk0 + row) * 512 + bn + ch * 4);
        }
    };
    load_stage(0, 0); cpa_commit();
    load_stage(1, 1); cpa_commit();

    for (int t = 0; t < NT; ++t) {
        cpa_wait<1>();
        __syncthreads();
        if (t + 2 < NT) load_stage((t + 2) % 3, t + 2);
        cpa_commit();
        const int cur = t % 3;
        const float* As = (const float*)(dsm + cur * STG2);
        const float* Bs = (const float*)(dsm + cur * STG2 + A2SZ);
#pragma unroll
        for (int ks = 0; ks < 16; ks += 8) {
            unsigned a[4][4], b[4][2];
#pragma unroll
            for (int mi = 0; mi < 4; mi++) {
                int m = wm + mi * 16 + g;
                a[mi][0] = __float_as_uint(As[(m    ) * A2STR + ks + tg]);
                a[mi][1] = __float_as_uint(As[(m + 8) * A2STR + ks + tg]);
                a[mi][2] = __float_as_uint(As[(m    ) * A2STR + ks + tg + 4]);
                a[mi][3] = __float_as_uint(As[(m + 8) * A2STR + ks + tg + 4]);
            }
#pragma unroll
            for (int ni = 0; ni < 4; ni++) {
                int c = wn + ni * 8 + g;
                b[ni][0] = __float_as_uint(Bs[(ks + tg    ) * B2STR + c]);
                b[ni][1] = __float_as_uint(Bs[(ks + tg + 4) * B2STR + c]);
            }
#pragma unroll
            for (int mi = 0; mi < 4; mi++)
#pragma unroll
                for (int ni = 0; ni < 4; ni++)
                    MMA_TF32(acc[mi][ni], a[mi], b[ni]);
        }
    }

    float* tgt = (by < 2) ? g_y2 : g_res2;
    const int nb = (by & 1) * 128;
#pragma unroll
    for (int mi = 0; mi < 4; mi++) {
        int m0 = bm + wm + mi * 16 + g;
#pragma unroll
        for (int ni = 0; ni < 4; ni++) {
            int n = nb + wn + ni * 8 + 2 * tg;
            int pb = bn + wn + ni * 8 + 2 * tg;
            float b0 = g_biasP[pb], b1 = g_biasP[pb + 1];
            *(float2*)(tgt + (size_t)m0 * HHC + n)
                = make_float2(acc[mi][ni][0] + b0, acc[mi][ni][1] + b1);
            *(float2*)(tgt + (size_t)(m0 + 8) * HHC + n)
                = make_float2(acc[mi][ni][2] + b0, acc[mi][ni][3] + b1);
        }
    }
}

// ---------------- node mix for stage 2 --------------------------------------
__global__ void nodemix2(const float* __restrict__ adj, const float* __restrict__ eimp) {
    __shared__ float ys[NNODE*HHC];
    __shared__ float Asm[NNODE*NNODE];
    int bs = blockIdx.x, tid = threadIdx.x;
    if (tid < NNODE*NNODE) Asm[tid] = adj[tid] * eimp[tid];
    for (int e = tid; e < NNODE*HHC; e += blockDim.x)
        ys[e] = g_y2[(size_t)bs*NNODE*HHC + e];
    __syncthreads();
    for (int e = tid; e < NNODE*HHC; e += blockDim.x) {
        int n = e / HHC, c = e % HHC;
        float acc = 0.f;
#pragma unroll
        for (int m = 0; m < NNODE; m++) acc += Asm[n*NNODE + m] * ys[m*HHC + c];
        g_xc2[(size_t)bs*NNODE*HHC + e] = acc;
    }
}

// ---------------- BN apply stage 2 -> [l][c] fp16 (no transpose needed) -----
__global__ void bn_apply2_tohalf(const float* __restrict__ g2, const float* __restrict__ beta2,
                                 const float* __restrict__ rg2, const float* __restrict__ rbeta2) {
    int row = blockIdx.x;        // (b*Ss + s)*6 + n
    int c = threadIdx.x;         // 0..255
    const float invM = 1.f / (float)M1R;
    float m1 = g_stats[c] * invM;
    float v1 = g_stats[HHC + c] * invM - m1*m1;
    float m2 = g_stats[2*HHC + c] * invM;
    float v2 = g_stats[3*HHC + c] * invM - m2*m2;
    float sc1 = rsqrtf(v1 + BNEPS) * g2[c];
    float sh1 = beta2[c] - m1*sc1;
    float sc2 = rsqrtf(v2 + BNEPS) * rg2[c];
    float sh2 = rbeta2[c] - m2*sc2;
    size_t ridx = (size_t)row * HHC + c;
    float o = g_xc2[ridx]*sc1 + sh1 + g_res2[ridx]*sc2 + sh2;
    o = o > 0.f ? o : 0.f;
    int n = row % NNODE;
    int bs = row / NNODE;
    int b = bs / Ss, s = bs % Ss;
    g_htH[((size_t)b * LROWS + 16 + s) * TCC + n * HHC + c] = __float2half(o);
}

// ======================= conv1d fp16 mma GEMM, 6-stage cp.async =============
// D[co, l] = sum_kk W[kk][co] * X[ci(kk)][l + kseg(kk) - 2]
// X in [l][c] fp16 padded rows; shift baked into cp.async row base.
#define ASZh 4096
#define BROWB 48            /* B smem row stride bytes (24 fp16) */
#define BSZh (128*BROWB)    /* 6144 */
#define STGh (ASZh + BSZh)  /* 10240 */
#define CSTAGES 6

__global__ __launch_bounds__(256, 2) void conv_gemm_f16(
        const __half* __restrict__ X, const __half* __restrict__ Wt,
        __half* __restrict__ Y) {
    extern __shared__ __align__(128) char dsm[];
    const int tid = threadIdx.x;
    const int cb = blockIdx.x;
    const int bm = cb * 128;           // co
    const int bn = blockIdx.y * 128;   // l
    const __half* Xb = X + (size_t)blockIdx.z * LROWS * TCC;
    __half* Yb = Y + (size_t)blockIdx.z * LROWS * TCC;
    const int lane = tid & 31, wid = tid >> 5;
    const int wm = (wid & 1) * 64, wn = (wid >> 1) * 32;
    const int g = lane >> 2, tg = lane & 3;
    const int aoff = (wid & 1) * 4;
    const uint32_t smem_u = s2u(dsm);

    float acc[4][4][4];
#pragma unroll
    for (int mi = 0; mi < 4; mi++)
#pragma unroll
        for (int ni = 0; ni < 4; ni++)
#pragma unroll
            for (int r = 0; r < 4; r++) acc[mi][ni][r] = 0.f;

    const int NT = RKK / 16;   // 480 = 80 * 6

    const int brow = tid >> 1, bhalf = tid & 1;

    auto load_stage = [&](int slot, int t) {
        const int kseg = t / 96;           // (t*16)/TCC
        const int ci0  = t * 16 - kseg * TCC;
        const uint32_t sa = smem_u + slot * STGh;
        const uint32_t sb = sa + ASZh;
        // A: permuted fp16 weight tile, 4KB straight copy
        cpasync16(sa + tid * 16, Wt + ((size_t)t * 12 + cb) * 2048 + tid * 8);
        // B: 128 rows x 32B from [l][c], shift baked into row base
        const __half* src = Xb + (size_t)(16 + bn + kseg - 2 + brow) * TCC
                              + ci0 + bhalf * 8;
        cpasync16(sb + brow * BROWB + bhalf * 16, src);
    };

    load_stage(0, 0); cpa_commit();
    load_stage(1, 1); cpa_commit();
    load_stage(2, 2); cpa_commit();
    load_stage(3, 3); cpa_commit();
    load_stage(4, 4); cpa_commit();

    for (int tb = 0; tb < NT; tb += CSTAGES) {
#pragma unroll
        for (int s = 0; s < CSTAGES; s++) {
            const int t = tb + s;
            cpa_wait<CSTAGES - 2>();
            __syncthreads();
            if (t + 5 < NT) load_stage((s + 5) % CSTAGES, t + 5);
            cpa_commit();

            const uint4* Af = (const uint4*)(dsm + s * STGh);
            const char* Bs = dsm + s * STGh + ASZh;

            unsigned a[4][4], b[4][2];
#pragma unroll
            for (int mi = 0; mi < 4; mi++) {
                uint4 v = Af[(aoff + mi) * 32 + lane];
                a[mi][0] = v.x; a[mi][1] = v.y; a[mi][2] = v.z; a[mi][3] = v.w;
            }
#pragma unroll
            for (int ni = 0; ni < 4; ni++) {
                int row = wn + ni * 8 + g;
                b[ni][0] = *(const unsigned*)(Bs + row * BROWB + tg * 4);
                b[ni][1] = *(const unsigned*)(Bs + row * BROWB + 16 + tg * 4);
            }
#pragma unroll
            for (int mi = 0; mi < 4; mi++)
#pragma unroll
                for (int ni = 0; ni < 4; ni++)
                    MMA_F16(acc[mi][ni], a[mi], b[ni]);
        }
    }

    // epilogue: store fp16 [l][c] + fused per-channel stats from fp32 accs
#pragma unroll
    for (int mi = 0; mi < 4; mi++) {
        int m0 = bm + wm + mi * 16 + g;
        float s0 = 0.f, q0 = 0.f, s1 = 0.f, q1 = 0.f;
#pragma unroll
        for (int ni = 0; ni < 4; ni++) {
            float v0 = acc[mi][ni][0], v1 = acc[mi][ni][1];
            float v2 = acc[mi][ni][2], v3 = acc[mi][ni][3];
            s0 += v0 + v1; q0 += v0*v0 + v1*v1;
            s1 += v2 + v3; q1 += v2*v2 + v3*v3;
            int l0 = bn + wn + ni * 8 + 2 * tg;
            size_t r0 = ((size_t)(16 + l0)) * TCC;
            size_t r1 = ((size_t)(17 + l0)) * TCC;
            Yb[r0 + m0]     = __float2half(v0);
            Yb[r1 + m0]     = __float2half(v1);
            Yb[r0 + m0 + 8] = __float2half(v2);
            Yb[r1 + m0 + 8] = __float2half(v3);
        }
        s0 += __shfl_xor_sync(0xffffffffu, s0, 1);
        s0 += __shfl_xor_sync(0xffffffffu, s0, 2);
        q0 += __shfl_xor_sync(0xffffffffu, q0, 1);
        q0 += __shfl_xor_sync(0xffffffffu, q0, 2);
        s1 += __shfl_xor_sync(0xffffffffu, s1, 1);
        s1 += __shfl_xor_sync(0xffffffffu, s1, 2);
        q1 += __shfl_xor_sync(0xffffffffu, q1, 1);
        q1 += __shfl_xor_sync(0xffffffffu, q1, 2);
        if (tg == 0) {
            atomicAdd(&g_stats[m0],         s0);
            atomicAdd(&g_stats[TCC + m0],   q0);
            atomicAdd(&g_stats[m0 + 8],     s1);
            atomicAdd(&g_stats[TCC + m0+8], q1);
        }
    }
}

// ---------------- conv BN apply in-place on fp16 [l][c] ----------------------
__global__ void conv_bnH(__half* __restrict__ T, const float* __restrict__ g,
                         const float* __restrict__ beta, const __half* __restrict__ resid) {
    size_t idx = (size_t)blockIdx.x * blockDim.x + threadIdx.x;
    const size_t total = (size_t)Bb * LLEN * (TCC/2);
    if (idx >= total) return;
    int c2  = (int)(idx % (TCC/2));
    int l   = (int)((idx / (TCC/2)) % LLEN);
    int b   = (int)(idx / ((size_t)(TCC/2) * LLEN));
    int c   = c2 * 2;
    size_t a = ((size_t)b * LROWS + 16 + l) * TCC + c;
    const float invM = 1.f / (float)(Bb * LLEN);
    float m0 = g_stats[c] * invM;
    float va = g_stats[TCC + c] * invM - m0*m0;
    float m1 = g_stats[c+1] * invM;
    float vb = g_stats[TCC + c+1] * invM - m1*m1;
    __half2 hv = *(__half2*)(T + a);
    float2 f = __half22float2(hv);
    float o0 = (f.x - m0) * rsqrtf(va + BNEPS) * g[c]   + beta[c];
    float o1 = (f.y - m1) * rsqrtf(vb + BNEPS) * g[c+1] + beta[c+1];
    o0 = o0 > 0.f ? o0 : 0.f;
    o1 = o1 > 0.f ? o1 : 0.f;
    if (resid) {
        float2 r = __half22float2(*(const __half2*)(resid + a));
        o0 += r.x; o1 += r.y;
    }
    *(__half2*)(T + a) = __floats2half2_rn(o0, o1);
}

// ======================= output GEMM (fp16 mma, permuted A) =================
#define STGOh (ASZh + BSZh)

__global__ __launch_bounds__(256, 2) void out_gemm_f16(
        const __half* __restrict__ T2, const float* __restrict__ OB,
        float* __restrict__ OUT) {
    extern __shared__ __align__(128) char dsm[];
    const int tid = threadIdx.x;
    const int cb = blockIdx.x;
    const int bm = cb * 128;           // o
    const int bn = blockIdx.y * 128;   // s
    const int b  = blockIdx.z;
    const __half* T2b = T2 + (size_t)b * LROWS * TCC;
    const int lane = tid & 31, wid = tid >> 5;
    const int wm = (wid & 1) * 64, wn = (wid >> 1) * 32;
    const int g = lane >> 2, tg = lane & 3;
    const int aoff = (wid & 1) * 4;
    const uint32_t smem_u = s2u(dsm);

    float acc[4][4][4];
#pragma unroll
    for (int mi = 0; mi < 4; mi++)
#pragma unroll
        for (int ni = 0; ni < 4; ni++)
#pragma unroll
            for (int r = 0; r < 4; r++) acc[mi][ni][r] = 0.f;

    const int NT = TCC / 16;   // 96
    const int brow = tid >> 1, bhalf = tid & 1;

    auto load_stage = [&](int slot, int t) {
        const uint32_t sa = smem_u + slot * STGOh;
        const uint32_t sb = sa + ASZh;
        cpasync16(sa + tid * 16, g_owRH + ((size_t)t * 2 + cb) * 2048 + tid * 8);
        const __half* src = T2b + (size_t)(16 + bn + brow) * TCC + t * 16 + bhalf * 8;
        cpasync16(sb + brow * BROWB + bhalf * 16, src);
    };
    load_stage(0, 0); cpa_commit();
    load_stage(1, 1); cpa_commit();

    for (int t = 0; t < NT; ++t) {
        cpa_wait<1>();
        __syncthreads();
        if (t + 2 < NT) load_stage((t + 2) % 3, t + 2);
        cpa_commit();
        const int cur = t % 3;
        const uint4* Af = (const uint4*)(dsm + cur * STGOh);
        const char* Bs = dsm + cur * STGOh + ASZh;

        unsigned a[4][4], b[4][2];
#pragma unroll
        for (int mi = 0; mi < 4; mi++) {
            uint4 v = Af[(aoff + mi) * 32 + lane];
            a[mi][0] = v.x; a[mi][1] = v.y; a[mi][2] = v.z; a[mi][3] = v.w;
        }
#pragma unroll
        for (int ni = 0; ni < 4; ni++) {
            int row = wn + ni * 8 + g;
            b[ni][0] = *(const unsigned*)(Bs + row * BROWB + tg * 4);
            b[ni][1] = *(const unsigned*)(Bs + row * BROWB + 16 + tg * 4);
        }
#pragma unroll
        for (int mi = 0; mi < 4; mi++)
#pragma unroll
            for (int ni = 0; ni < 4; ni++)
                MMA_F16(acc[mi][ni], a[mi], b[ni]);
    }

#pragma unroll
    for (int mi = 0; mi < 4; mi++) {
        int o0 = bm + wm + mi * 16 + g;
        float bo0 = OB[o0], bo1 = OB[o0 + 8];
#pragma unroll
        for (int ni = 0; ni < 4; ni++) {
            int sL = bn + wn + ni * 8 + 2 * tg;
            float v0 = acc[mi][ni][0] + bo0; v0 = v0 > 0.f ? v0 : 0.f;
            float v1 = acc[mi][ni][1] + bo0; v1 = v1 > 0.f ? v1 : 0.f;
            float v2 = acc[mi][ni][2] + bo1; v2 = v2 > 0.f ? v2 : 0.f;
            float v3 = acc[mi][ni][3] + bo1; v3 = v3 > 0.f ? v3 : 0.f;
            OUT[((size_t)b * Ss + sL    ) * HHC + o0    ] = v0;
            OUT[((size_t)b * Ss + sL + 1) * HHC + o0    ] = v1;
            OUT[((size_t)b * Ss + sL    ) * HHC + o0 + 8] = v2;
            OUT[((size_t)b * Ss + sL + 1) * HHC + o0 + 8] = v3;
        }
    }
}

// ---------------- launch ----------------------------------------------------
extern "C" void kernel_launch(void* const* d_in, const int* in_sizes, int n_in,
                              void* d_out, int out_size) {
    const float* x     = (const float*)d_in[0];
    const float* adj   = (const float*)d_in[1];
    const float* eimp  = (const float*)d_in[2];
    const float* w1    = (const float*)d_in[3];
    const float* b1    = (const float*)d_in[4];
    const float* rw1   = (const float*)d_in[5];
    const float* rb1   = (const float*)d_in[6];
    const float* rg1   = (const float*)d_in[7];
    const float* rbeta1= (const float*)d_in[8];
    const float* g1    = (const float*)d_in[9];
    const float* beta1 = (const float*)d_in[10];
    const float* w2    = (const float*)d_in[11];
    const float* b2    = (const float*)d_in[12];
    const float* rw2   = (const float*)d_in[13];
    const float* rb2   = (const float*)d_in[14];
    const float* rg2   = (const float*)d_in[15];
    const float* rbeta2= (const float*)d_in[16];
    const float* g2    = (const float*)d_in[17];
    const float* beta2 = (const float*)d_in[18];
    const float* cw1   = (const float*)d_in[19];
    /* cb1 = d_in[20]: cancels exactly through BN mean-subtraction */
    const float* cg1   = (const float*)d_in[21];
    const float* cbeta1= (const float*)d_in[22];
    const float* cw2   = (const float*)d_in[23];
    /* cb2 = d_in[24]: cancels exactly */
    const float* cg2   = (const float*)d_in[25];
    const float* cbeta2= (const float*)d_in[26];
    const float* ow    = (const float*)d_in[27];
    const float* ob    = (const float*)d_in[28];
    float* out = (float*)d_out;

    float *p_xc1, *p_res1, *p_xc2, *p_res2;
    __half *p_htH, *p_t1H, *p_t2H, *p_wt1H, *p_wt2H;
    cudaGetSymbolAddress((void**)&p_xc1,  g_xc1);
    cudaGetSymbolAddress((void**)&p_res1, g_res1);
    cudaGetSymbolAddress((void**)&p_xc2,  g_xc2);
    cudaGetSymbolAddress((void**)&p_res2, g_res2);
    cudaGetSymbolAddress((void**)&p_htH,  g_htH);
    cudaGetSymbolAddress((void**)&p_t1H,  g_t1H);
    cudaGetSymbolAddress((void**)&p_t2H,  g_t2H);
    cudaGetSymbolAddress((void**)&p_wt1H, g_wt1H);
    cudaGetSymbolAddress((void**)&p_wt2H, g_wt2H);

    cudaFuncSetAttribute(conv_gemm_f16,
                         cudaFuncAttributeMaxDynamicSharedMemorySize, CSTAGES * STGh);
    cudaFuncSetAttribute(gcn2_gemm_tf32,
                         cudaFuncAttributeMaxDynamicSharedMemorySize, 3 * STG2);
    cudaFuncSetAttribute(out_gemm_f16,
                         cudaFuncAttributeMaxDynamicSharedMemorySize, 3 * STGOh);

    // -------- GCN stage 1 --------
    gcn1_kernel<<<NBS, 256>>>(x, adj, eimp, w1, b1, rw1, rb1);
    zero_stats_k<<<(4*TCC + 255)/256, 256>>>();
    zero_padsH<<<(Bb*32*(TCC/8) + 255)/256, 256>>>();
    pack_gcn2<<<(H1C*HHC + 255)/256, 256>>>(w2, rw2, b2, rb2);
    pack_owH<<<(TCC/16)*2, 256>>>(ow);
    stats_rows<<<1024, H1C>>>(p_xc1, p_res1, M1R, H1C);
    bn_apply1<<<(M1R*H1C)/256, 256>>>(g1, beta1, rg1, rbeta1);

    // -------- GCN stage 2 (tf32 dual GEMM) --------
    gcn2_gemm_tf32<<<dim3(M1R/128, 4), 256, 3*STG2>>>();
    nodemix2<<<NBS, 256>>>(adj, eimp);
    zero_stats_k<<<(4*TCC + 255)/256, 256>>>();
    stats_rows<<<1024, HHC>>>(p_xc2, p_res2, M1R, HHC);
    bn_apply2_tohalf<<<M1R, 256>>>(g2, beta2, rg2, rbeta2);

    // -------- TCN conv 1 (fp16 mma) --------
    wtrans_convH<<<(RKK/16)*12, 256>>>(cw1, p_wt1H);
    zero_stats_k<<<(4*TCC + 255)/256, 256>>>();
    conv_gemm_f16<<<dim3(TCC/128, LLEN/128, Bb), 256, CSTAGES*STGh>>>(p_htH, p_wt1H, p_t1H);
    conv_bnH<<<(Bb*LLEN*(TCC/2) + 255)/256, 256>>>(p_t1H, cg1, cbeta1, (const __half*)nullptr);

    // -------- TCN conv 2 + residual --------
    wtrans_convH<<<(RKK/16)*12, 256>>>(cw2, p_wt2H);
    zero_stats_k<<<(4*TCC + 255)/256, 256>>>();
    conv_gemm_f16<<<dim3(TCC/128, LLEN/128, Bb), 256, CSTAGES*STGh>>>(p_t1H, p_wt2H, p_t2H);
    conv_bnH<<<(Bb*LLEN*(TCC/2) + 255)/256, 256>>>(p_t2H, cg2, cbeta2, p_htH);

    // -------- output layer (fp16 mma) --------
    out_gemm_f16<<<dim3(HHC/128, LLEN/128, Bb), 256, 3*STGOh>>>(p_t2H, ob, out);

    (void)in_sizes; (void)n_in; (void)out_size;
}